// round 1
// baseline (speedup 1.0000x reference)
#include <cuda_runtime.h>
#include <cuda_bf16.h>

// ---------------- problem constants ----------------
#define Bz   2
#define Nn   2048
#define Tt   256
#define Cc   1024
#define Hh   4096
#define Ss   2304          // N + T
#define HEADS 16
#define Dd   64

// ---------------- scratch (no allocation allowed) ----------------
__device__ float g_m[Bz * 6 * Cc];                 // adaLN modulation vectors
__device__ float g_joint[(long)Bz * Ss * Cc];      // joint ln input / proj out / x2,c2
__device__ float g_qkv[(long)Bz * Ss * 3 * Cc];    // qkv / mlp out
__device__ float g_attn[(long)Bz * Ss * Cc];       // attention output
__device__ float g_hidden[(long)4096 * 4096];      // MLP hidden

// ---------------- activations ----------------
template<int ACT>
__device__ __forceinline__ float act_fn(float x) {
    if (ACT == 1) { // gelu tanh approx
        float x3 = x * x * x;
        return 0.5f * x * (1.f + tanhf(0.7978845608028654f * (x + 0.044715f * x3)));
    }
    if (ACT == 2) { // silu
        return x / (1.f + __expf(-x));
    }
    return x;
}

// ---------------- adaLN: m = silu(mod) @ w_adaln + b ----------------
// grid (24, B), 256 threads. Each thread computes one of 6144 outputs.
__global__ void adaln_kernel(const float* __restrict__ mod,
                             const float* __restrict__ w,
                             const float* __restrict__ bias,
                             float* __restrict__ mout) {
    int b = blockIdx.y;
    int j = blockIdx.x * 256 + threadIdx.x;   // < 6144
    __shared__ float sm[Cc];
    for (int i = threadIdx.x; i < Cc; i += 256) {
        float v = mod[b * Cc + i];
        sm[i] = v / (1.f + __expf(-v));
    }
    __syncthreads();
    float acc = bias[j];
    for (int k = 0; k < Cc; k++) acc += sm[k] * w[(long)k * (6 * Cc) + j];
    mout[b * 6 * Cc + j] = acc;
}

// ---------------- LN + modulate: out = LN(in)*(1+sc)+sh ----------------
// one block per row (C=1024), 256 threads x 4 elements
__global__ void ln_mod_kernel(const float* __restrict__ in, float* __restrict__ out,
                              const float* __restrict__ m, int rowsPerBatch,
                              int shOff, int scOff,
                              long outBatchStride, int outRowOff) {
    int row = blockIdx.x;
    int b = row / rowsPerBatch;
    int r = row - b * rowsPerBatch;
    const float* xi = in + (long)row * Cc;
    float v[4]; float s = 0.f, s2 = 0.f;
#pragma unroll
    for (int i = 0; i < 4; i++) {
        v[i] = xi[threadIdx.x + 256 * i];
        s += v[i]; s2 += v[i] * v[i];
    }
    __shared__ float rs[256], rs2[256];
    rs[threadIdx.x] = s; rs2[threadIdx.x] = s2;
    __syncthreads();
    for (int off = 128; off > 0; off >>= 1) {
        if (threadIdx.x < off) {
            rs[threadIdx.x]  += rs[threadIdx.x + off];
            rs2[threadIdx.x] += rs2[threadIdx.x + off];
        }
        __syncthreads();
    }
    float mu   = rs[0] * (1.f / (float)Cc);
    float var  = rs2[0] * (1.f / (float)Cc) - mu * mu;
    float rstd = rsqrtf(var + 1e-6f);
    const float* mb = m + b * 6 * Cc;
    float* po = out + (long)b * outBatchStride + (long)(outRowOff + r) * Cc;
#pragma unroll
    for (int i = 0; i < 4; i++) {
        int c = threadIdx.x + 256 * i;
        po[c] = (v[i] - mu) * rstd * (1.f + mb[scOff + c]) + mb[shOff + c];
    }
}

// ---------------- residual gate: out = base + add * g ----------------
__global__ void resid_gate_kernel(const float* __restrict__ base,
                                  const float* __restrict__ add,
                                  float* __restrict__ out,
                                  const float* __restrict__ m, int gOff,
                                  int rowsPerBatch, long addBatchStride, int addRowOff) {
    int row = blockIdx.x;
    int b = row / rowsPerBatch;
    int r = row - b * rowsPerBatch;
    const float* pb = base + (long)row * Cc;
    const float* pa = add + (long)b * addBatchStride + (long)(addRowOff + r) * Cc;
    float* po = out + (long)row * Cc;
    const float* g = m + b * 6 * Cc + gOff;
#pragma unroll
    for (int i = 0; i < 4; i++) {
        int c = threadIdx.x + 256 * i;
        po[c] = pb[c] + pa[c] * g[c];
    }
}

// ---------------- tiled SGEMM: C = act(A@B + bias), 128x128x8 ----------------
// A row-major [M,K], B row-major [K,N]. M%128==0, N%128==0, K%8==0.
template<int ACT>
__global__ __launch_bounds__(256)
void gemm_kernel(const float* __restrict__ A, const float* __restrict__ B,
                 const float* __restrict__ bias, float* __restrict__ C,
                 int M, int N, int K) {
    __shared__ float As[8][128];
    __shared__ float Bs[8][128];
    int tid = threadIdx.x;
    int tr = tid >> 4;          // 0..15 -> row group
    int tc = tid & 15;          // 0..15 -> col group
    const float* Ab = A + (long)blockIdx.y * 128 * K;
    const float* Bb = B + blockIdx.x * 128;
    float acc[8][8] = {};
    int aRow = tid >> 1;              // 0..127
    int aCol = (tid & 1) * 4;         // 0 or 4
    int bRow = tid >> 5;              // 0..7
    int bCol = (tid & 31) * 4;        // 0..124

    for (int k0 = 0; k0 < K; k0 += 8) {
        float4 av = *(const float4*)(Ab + (long)aRow * K + k0 + aCol);
        As[aCol + 0][aRow] = av.x;
        As[aCol + 1][aRow] = av.y;
        As[aCol + 2][aRow] = av.z;
        As[aCol + 3][aRow] = av.w;
        *(float4*)(&Bs[bRow][bCol]) = *(const float4*)(Bb + (long)(k0 + bRow) * N + bCol);
        __syncthreads();
#pragma unroll
        for (int kk = 0; kk < 8; kk++) {
            float ar[8], br[8];
#pragma unroll
            for (int i = 0; i < 8; i++) ar[i] = As[kk][tr * 8 + i];
#pragma unroll
            for (int j = 0; j < 8; j++) br[j] = Bs[kk][tc * 8 + j];
#pragma unroll
            for (int i = 0; i < 8; i++)
#pragma unroll
                for (int j = 0; j < 8; j++) acc[i][j] += ar[i] * br[j];
        }
        __syncthreads();
    }
    int row0 = blockIdx.y * 128 + tr * 8;
    int col0 = blockIdx.x * 128 + tc * 8;
#pragma unroll
    for (int i = 0; i < 8; i++) {
        float* pc = C + (long)(row0 + i) * N + col0;
#pragma unroll
        for (int j = 0; j < 8; j++) {
            pc[j] = act_fn<ACT>(acc[i][j] + bias[col0 + j]);
        }
    }
}

// ---------------- flash attention, fp32, BR=BC=64, D=64 ----------------
#define FA_P 65
#define FA_SMEM (int)((3 * 64 * FA_P + 3 * 64) * sizeof(float))
__global__ __launch_bounds__(256)
void flash_kernel(const float* __restrict__ qkv, float* __restrict__ outp) {
    extern __shared__ float smf[];
    float* Qs   = smf;                 // [64][65]
    float* KVs  = Qs + 64 * FA_P;      // [64][65]
    float* Ps   = KVs + 64 * FA_P;     // [64][65]
    float* mrow = Ps + 64 * FA_P;      // [64]
    float* lrow = mrow + 64;           // [64]
    float* crow = lrow + 64;           // [64]

    int bh = blockIdx.y;
    int b = bh >> 4, h = bh & 15;
    int q0 = blockIdx.x * 64;
    int tid = threadIdx.x;

    // load and pre-scale Q
    for (int i = tid; i < 64 * 64; i += 256) {
        int r = i >> 6, d = i & 63;
        Qs[r * FA_P + d] = qkv[(long)(b * Ss + q0 + r) * (3 * Cc) + h * Dd + d] * 0.125f;
    }
    if (tid < 64) { mrow[tid] = -1e30f; lrow[tid] = 0.f; }
    __syncthreads();

    int tq = tid >> 4, tk = tid & 15;
    float Oreg[4][4] = {};  // rows tq+16i, d-cols tk+16j

    for (int j0 = 0; j0 < Ss; j0 += 64) {
        // K tile
        for (int i = tid; i < 64 * 64; i += 256) {
            int r = i >> 6, d = i & 63;
            KVs[r * FA_P + d] = qkv[(long)(b * Ss + j0 + r) * (3 * Cc) + Cc + h * Dd + d];
        }
        __syncthreads();
        // S = Q K^T (pre-scaled)
        float acc[4][4] = {};
        for (int d = 0; d < 64; d++) {
            float qa[4], kb[4];
#pragma unroll
            for (int i = 0; i < 4; i++) qa[i] = Qs[(tq + 16 * i) * FA_P + d];
#pragma unroll
            for (int j = 0; j < 4; j++) kb[j] = KVs[(tk + 16 * j) * FA_P + d];
#pragma unroll
            for (int i = 0; i < 4; i++)
#pragma unroll
                for (int j = 0; j < 4; j++) acc[i][j] += qa[i] * kb[j];
        }
#pragma unroll
        for (int i = 0; i < 4; i++)
#pragma unroll
            for (int j = 0; j < 4; j++)
                Ps[(tq + 16 * i) * FA_P + (tk + 16 * j)] = acc[i][j];
        __syncthreads();   // Ps visible; KVs reads complete
        // online softmax: one thread per row
        if (tid < 64) {
            int r = tid;
            float mold = mrow[r];
            float tm = mold;
            for (int c = 0; c < 64; c++) tm = fmaxf(tm, Ps[r * FA_P + c]);
            float corr = __expf(mold - tm);
            float lsum = 0.f;
            for (int c = 0; c < 64; c++) {
                float p = __expf(Ps[r * FA_P + c] - tm);
                Ps[r * FA_P + c] = p;
                lsum += p;
            }
            mrow[r] = tm;
            lrow[r] = lrow[r] * corr + lsum;
            crow[r] = corr;
        }
        __syncthreads();
        // rescale accumulators
#pragma unroll
        for (int i = 0; i < 4; i++) {
            float cr = crow[tq + 16 * i];
#pragma unroll
            for (int j = 0; j < 4; j++) Oreg[i][j] *= cr;
        }
        // V tile (KVs free now)
        for (int i = tid; i < 64 * 64; i += 256) {
            int r = i >> 6, d = i & 63;
            KVs[r * FA_P + d] = qkv[(long)(b * Ss + j0 + r) * (3 * Cc) + 2 * Cc + h * Dd + d];
        }
        __syncthreads();
        // O += P @ V
        for (int c = 0; c < 64; c++) {
            float vv[4];
#pragma unroll
            for (int j = 0; j < 4; j++) vv[j] = KVs[c * FA_P + (tk + 16 * j)];
#pragma unroll
            for (int i = 0; i < 4; i++) {
                float p = Ps[(tq + 16 * i) * FA_P + c];
#pragma unroll
                for (int j = 0; j < 4; j++) Oreg[i][j] += p * vv[j];
            }
        }
        __syncthreads();   // before next tile overwrites KVs/Ps
    }
    // write out: [B,S,heads*D]
#pragma unroll
    for (int i = 0; i < 4; i++) {
        int r = tq + 16 * i;
        float inv = 1.f / lrow[r];
#pragma unroll
        for (int j = 0; j < 4; j++) {
            int d = tk + 16 * j;
            outp[(long)(b * Ss + q0 + r) * Cc + h * Dd + d] = Oreg[i][j] * inv;
        }
    }
}

// ---------------- launch ----------------
extern "C" void kernel_launch(void* const* d_in, const int* in_sizes, int n_in,
                              void* d_out, int out_size) {
    const float* x       = (const float*)d_in[0];
    const float* mod     = (const float*)d_in[1];
    const float* cond    = (const float*)d_in[2];
    const float* w_adaln = (const float*)d_in[3];
    const float* b_adaln = (const float*)d_in[4];
    const float* w_qkv   = (const float*)d_in[5];
    const float* b_qkv   = (const float*)d_in[6];
    const float* w_proj  = (const float*)d_in[7];
    const float* b_proj  = (const float*)d_in[8];
    const float* w_s1    = (const float*)d_in[9];
    const float* b_s1    = (const float*)d_in[10];
    const float* w_s2    = (const float*)d_in[11];
    const float* b_s2    = (const float*)d_in[12];
    const float* w_d1    = (const float*)d_in[13];
    const float* b_d1    = (const float*)d_in[14];
    const float* w_d2    = (const float*)d_in[15];
    const float* b_d2    = (const float*)d_in[16];

    float* outx = (float*)d_out;                         // [2,2048,1024]
    float* outc = outx + (long)Bz * Nn * Cc;             // [2,256,1024]

    float *gm, *gjoint, *gqkv, *gattn, *ghid;
    cudaGetSymbolAddress((void**)&gm,     g_m);
    cudaGetSymbolAddress((void**)&gjoint, g_joint);
    cudaGetSymbolAddress((void**)&gqkv,   g_qkv);
    cudaGetSymbolAddress((void**)&gattn,  g_attn);
    cudaGetSymbolAddress((void**)&ghid,   g_hidden);

    cudaFuncSetAttribute(flash_kernel, cudaFuncAttributeMaxDynamicSharedMemorySize, FA_SMEM);

    const long SC = (long)Ss * Cc;
    const long NC = (long)Nn * Cc;
    const long TC = (long)Tt * Cc;

    // 1. modulation vectors
    adaln_kernel<<<dim3(24, Bz), 256>>>(mod, w_adaln, b_adaln, gm);

    // 2. LN + msa modulate -> joint [B,S,C]
    ln_mod_kernel<<<Bz * Nn, 256>>>(x,    gjoint, gm, Nn, 0, Cc, SC, 0);
    ln_mod_kernel<<<Bz * Tt, 256>>>(cond, gjoint, gm, Tt, 0, Cc, SC, Nn);

    // 3. qkv = joint @ w_qkv + b  (4608 x 3072 x 1024)
    gemm_kernel<0><<<dim3(3072 / 128, (Bz * Ss) / 128), 256>>>(gjoint, w_qkv, b_qkv, gqkv,
                                                               Bz * Ss, 3 * Cc, Cc);

    // 4. attention
    flash_kernel<<<dim3(Ss / 64, Bz * HEADS), 256, FA_SMEM>>>(gqkv, gattn);

    // 5. proj (4608 x 1024 x 1024) -> gjoint (reuse)
    gemm_kernel<0><<<dim3(Cc / 128, (Bz * Ss) / 128), 256>>>(gattn, w_proj, b_proj, gjoint,
                                                             Bz * Ss, Cc, Cc);

    // 6. attn residual with g_msa (offset 2C)
    resid_gate_kernel<<<Bz * Nn, 256>>>(x,    gjoint, outx, gm, 2 * Cc, Nn, SC, 0);
    resid_gate_kernel<<<Bz * Tt, 256>>>(cond, gjoint, outc, gm, 2 * Cc, Tt, SC, Nn);

    // 7. LN + mlp modulate (sh_mlp=3C, sc_mlp=4C)
    float* gx2 = gjoint;                    // [B*N, C]
    float* gc2 = gjoint + (long)Bz * Nn * Cc; // [B*T, C]
    ln_mod_kernel<<<Bz * Nn, 256>>>(outx, gx2, gm, Nn, 3 * Cc, 4 * Cc, NC, 0);
    ln_mod_kernel<<<Bz * Tt, 256>>>(outc, gc2, gm, Tt, 3 * Cc, 4 * Cc, TC, 0);

    // 8. x MLP: gelu(x2@w_s1+b) @ w_s2 + b
    gemm_kernel<1><<<dim3(Hh / 128, (Bz * Nn) / 128), 256>>>(gx2, w_s1, b_s1, ghid,
                                                             Bz * Nn, Hh, Cc);
    gemm_kernel<0><<<dim3(Cc / 128, (Bz * Nn) / 128), 256>>>(ghid, w_s2, b_s2, gqkv,
                                                             Bz * Nn, Cc, Hh);
    resid_gate_kernel<<<Bz * Nn, 256>>>(outx, gqkv, outx, gm, 5 * Cc, Nn, NC, 0);

    // 9. cond MLP: silu(c2@w_d1+b) @ w_d2 + b
    gemm_kernel<2><<<dim3(Hh / 128, (Bz * Tt) / 128), 256>>>(gc2, w_d1, b_d1, ghid,
                                                             Bz * Tt, Hh, Cc);
    gemm_kernel<0><<<dim3(Cc / 128, (Bz * Tt) / 128), 256>>>(ghid, w_d2, b_d2, gqkv,
                                                             Bz * Tt, Cc, Hh);
    resid_gate_kernel<<<Bz * Tt, 256>>>(outc, gqkv, outc, gm, 5 * Cc, Tt, TC, 0);
}

// round 2
// speedup vs baseline: 1.9178x; 1.9178x over previous
#include <cuda_runtime.h>
#include <cuda_bf16.h>
#include <cstdint>

// ---------------- problem constants ----------------
#define Bz   2
#define Nn   2048
#define Tt   256
#define Cc   1024
#define Hh   4096
#define Ss   2304          // N + T
#define HEADS 16
#define Dd   64

// ---------------- scratch (no allocation allowed) ----------------
__device__ float g_m[Bz * 6 * Cc];                 // adaLN modulation vectors
__device__ float g_joint[(long)Bz * Ss * Cc];      // joint ln input / x2,c2
__device__ float g_qkv[(long)Bz * Ss * 3 * Cc];    // qkv / mlp out
__device__ float g_attn[(long)Bz * Ss * Cc];       // attention output
__device__ float g_hidden[(long)4096 * 4096];      // MLP hidden

// ---------------- activations ----------------
template<int ACT>
__device__ __forceinline__ float act_fn(float x) {
    if (ACT == 1) { // gelu tanh approx
        float x3 = x * x * x;
        return 0.5f * x * (1.f + tanhf(0.7978845608028654f * (x + 0.044715f * x3)));
    }
    if (ACT == 2) { // silu
        return x / (1.f + __expf(-x));
    }
    return x;
}

__device__ __forceinline__ uint32_t f2tf32(float f) {
    uint32_t u;
    asm("cvt.rna.tf32.f32 %0, %1;" : "=r"(u) : "f"(f));
    return u;
}

__device__ __forceinline__ void mma_tf32(float* d,
                                         const uint32_t* a, const uint32_t* b) {
    asm volatile(
        "mma.sync.aligned.m16n8k8.row.col.f32.tf32.tf32.f32 "
        "{%0,%1,%2,%3}, {%4,%5,%6,%7}, {%8,%9}, {%0,%1,%2,%3};\n"
        : "+f"(d[0]), "+f"(d[1]), "+f"(d[2]), "+f"(d[3])
        : "r"(a[0]), "r"(a[1]), "r"(a[2]), "r"(a[3]), "r"(b[0]), "r"(b[1]));
}

// ---------------- adaLN: m = silu(mod) @ w_adaln + b (kept fp32) ----------------
__global__ void adaln_kernel(const float* __restrict__ mod,
                             const float* __restrict__ w,
                             const float* __restrict__ bias,
                             float* __restrict__ mout) {
    int b = blockIdx.y;
    int j = blockIdx.x * 256 + threadIdx.x;   // < 6144
    __shared__ float sm[Cc];
    for (int i = threadIdx.x; i < Cc; i += 256) {
        float v = mod[b * Cc + i];
        sm[i] = v / (1.f + __expf(-v));
    }
    __syncthreads();
    float acc = bias[j];
    for (int k = 0; k < Cc; k++) acc += sm[k] * w[(long)k * (6 * Cc) + j];
    mout[b * 6 * Cc + j] = acc;
}

// ---------------- LN + modulate ----------------
__global__ void ln_mod_kernel(const float* __restrict__ in, float* __restrict__ out,
                              const float* __restrict__ m, int rowsPerBatch,
                              int shOff, int scOff,
                              long outBatchStride, int outRowOff) {
    int row = blockIdx.x;
    int b = row / rowsPerBatch;
    int r = row - b * rowsPerBatch;
    const float* xi = in + (long)row * Cc;
    float v[4]; float s = 0.f, s2 = 0.f;
#pragma unroll
    for (int i = 0; i < 4; i++) {
        v[i] = xi[threadIdx.x + 256 * i];
        s += v[i]; s2 += v[i] * v[i];
    }
    __shared__ float rs[256], rs2[256];
    rs[threadIdx.x] = s; rs2[threadIdx.x] = s2;
    __syncthreads();
    for (int off = 128; off > 0; off >>= 1) {
        if (threadIdx.x < off) {
            rs[threadIdx.x]  += rs[threadIdx.x + off];
            rs2[threadIdx.x] += rs2[threadIdx.x + off];
        }
        __syncthreads();
    }
    float mu   = rs[0] * (1.f / (float)Cc);
    float var  = rs2[0] * (1.f / (float)Cc) - mu * mu;
    float rstd = rsqrtf(var + 1e-6f);
    const float* mb = m + b * 6 * Cc;
    float* po = out + (long)b * outBatchStride + (long)(outRowOff + r) * Cc;
#pragma unroll
    for (int i = 0; i < 4; i++) {
        int c = threadIdx.x + 256 * i;
        po[c] = (v[i] - mu) * rstd * (1.f + mb[scOff + c]) + mb[shOff + c];
    }
}

// ---------------- residual gate ----------------
__global__ void resid_gate_kernel(const float* __restrict__ base,
                                  const float* __restrict__ add,
                                  float* __restrict__ out,
                                  const float* __restrict__ m, int gOff,
                                  int rowsPerBatch, long addBatchStride, int addRowOff) {
    int row = blockIdx.x;
    int b = row / rowsPerBatch;
    int r = row - b * rowsPerBatch;
    const float* pb = base + (long)row * Cc;
    const float* pa = add + (long)b * addBatchStride + (long)(addRowOff + r) * Cc;
    float* po = out + (long)row * Cc;
    const float* g = m + b * 6 * Cc + gOff;
#pragma unroll
    for (int i = 0; i < 4; i++) {
        int c = threadIdx.x + 256 * i;
        po[c] = pb[c] + pa[c] * g[c];
    }
}

// ---------------- TF32 tensor-core GEMM: C = act(A@B + bias) ----------------
// A row-major [M,K], B row-major [K,N]. M%128==0, N%128==0, K%16==0.
// 128x128 tile, k-step 16, double buffered. 8 warps: 2 (M) x 4 (N), 64x32/warp.
template<int ACT>
__global__ __launch_bounds__(256)
void mma_gemm(const float* __restrict__ A, const float* __restrict__ B,
              const float* __restrict__ bias, float* __restrict__ C,
              int M, int N, int K) {
    __shared__ uint32_t As[2][16][136];   // [k][m], stride 136 -> bank = 8k+m (mod32)
    __shared__ uint32_t Bs[2][16][136];   // [k][n]

    int tid  = threadIdx.x;
    int warp = tid >> 5, lane = tid & 31;
    int g    = lane >> 2, tig = lane & 3;
    int warpM = (warp >> 2) * 64;
    int warpN = (warp & 3) * 32;

    const float* Ab = A + (long)blockIdx.y * 128 * K;
    const float* Bb = B + blockIdx.x * 128;

    int aRow  = tid >> 1;          // 0..127
    int aCol  = (tid & 1) * 8;     // 0 or 8
    int bRow  = tid >> 4;          // 0..15
    int bCol4 = (tid & 15);        // float4 col index; this and +16

    float acc[4][4][4];
#pragma unroll
    for (int i = 0; i < 4; i++)
#pragma unroll
        for (int j = 0; j < 4; j++)
#pragma unroll
            for (int q = 0; q < 4; q++) acc[i][j][q] = 0.f;

    float4 ar0, ar1, br0, br1;

    // prologue: stage 0
    ar0 = *(const float4*)(Ab + (long)aRow * K + aCol);
    ar1 = *(const float4*)(Ab + (long)aRow * K + aCol + 4);
    br0 = *(const float4*)(Bb + (long)bRow * N + bCol4 * 4);
    br1 = *(const float4*)(Bb + (long)bRow * N + (bCol4 + 16) * 4);
    {
        As[0][aCol + 0][aRow] = f2tf32(ar0.x);
        As[0][aCol + 1][aRow] = f2tf32(ar0.y);
        As[0][aCol + 2][aRow] = f2tf32(ar0.z);
        As[0][aCol + 3][aRow] = f2tf32(ar0.w);
        As[0][aCol + 4][aRow] = f2tf32(ar1.x);
        As[0][aCol + 5][aRow] = f2tf32(ar1.y);
        As[0][aCol + 6][aRow] = f2tf32(ar1.z);
        As[0][aCol + 7][aRow] = f2tf32(ar1.w);
        uint4 p0 = { f2tf32(br0.x), f2tf32(br0.y), f2tf32(br0.z), f2tf32(br0.w) };
        uint4 p1 = { f2tf32(br1.x), f2tf32(br1.y), f2tf32(br1.z), f2tf32(br1.w) };
        *(uint4*)&Bs[0][bRow][bCol4 * 4]        = p0;
        *(uint4*)&Bs[0][bRow][(bCol4 + 16) * 4] = p1;
    }
    __syncthreads();

    int nstages = K >> 4;
    for (int s = 0; s < nstages; s++) {
        int cur = s & 1;
        bool has_next = (s + 1 < nstages);
        if (has_next) {
            int k0 = (s + 1) << 4;
            ar0 = *(const float4*)(Ab + (long)aRow * K + k0 + aCol);
            ar1 = *(const float4*)(Ab + (long)aRow * K + k0 + aCol + 4);
            br0 = *(const float4*)(Bb + (long)(k0 + bRow) * N + bCol4 * 4);
            br1 = *(const float4*)(Bb + (long)(k0 + bRow) * N + (bCol4 + 16) * 4);
        }
#pragma unroll
        for (int kk = 0; kk < 2; kk++) {
            uint32_t af[4][4], bf[4][2];
#pragma unroll
            for (int mi = 0; mi < 4; mi++) {
                int m = warpM + mi * 16;
                af[mi][0] = As[cur][kk * 8 + tig][m + g];
                af[mi][1] = As[cur][kk * 8 + tig][m + g + 8];
                af[mi][2] = As[cur][kk * 8 + tig + 4][m + g];
                af[mi][3] = As[cur][kk * 8 + tig + 4][m + g + 8];
            }
#pragma unroll
            for (int ni = 0; ni < 4; ni++) {
                int n = warpN + ni * 8;
                bf[ni][0] = Bs[cur][kk * 8 + tig][n + g];
                bf[ni][1] = Bs[cur][kk * 8 + tig + 4][n + g];
            }
#pragma unroll
            for (int mi = 0; mi < 4; mi++)
#pragma unroll
                for (int ni = 0; ni < 4; ni++)
                    mma_tf32(acc[mi][ni], af[mi], bf[ni]);
        }
        if (has_next) {
            int nb = (s + 1) & 1;
            As[nb][aCol + 0][aRow] = f2tf32(ar0.x);
            As[nb][aCol + 1][aRow] = f2tf32(ar0.y);
            As[nb][aCol + 2][aRow] = f2tf32(ar0.z);
            As[nb][aCol + 3][aRow] = f2tf32(ar0.w);
            As[nb][aCol + 4][aRow] = f2tf32(ar1.x);
            As[nb][aCol + 5][aRow] = f2tf32(ar1.y);
            As[nb][aCol + 6][aRow] = f2tf32(ar1.z);
            As[nb][aCol + 7][aRow] = f2tf32(ar1.w);
            uint4 p0 = { f2tf32(br0.x), f2tf32(br0.y), f2tf32(br0.z), f2tf32(br0.w) };
            uint4 p1 = { f2tf32(br1.x), f2tf32(br1.y), f2tf32(br1.z), f2tf32(br1.w) };
            *(uint4*)&Bs[nb][bRow][bCol4 * 4]        = p0;
            *(uint4*)&Bs[nb][bRow][(bCol4 + 16) * 4] = p1;
        }
        __syncthreads();
    }

    // epilogue
    int rowBase = blockIdx.y * 128 + warpM;
    int colBase = blockIdx.x * 128 + warpN;
#pragma unroll
    for (int mi = 0; mi < 4; mi++) {
#pragma unroll
        for (int ni = 0; ni < 4; ni++) {
            int r0 = rowBase + mi * 16 + g;
            int c0 = colBase + ni * 8 + tig * 2;
            float b0 = bias[c0], b1 = bias[c0 + 1];
            float* p0 = C + (long)r0 * N + c0;
            float* p1 = C + (long)(r0 + 8) * N + c0;
            p0[0] = act_fn<ACT>(acc[mi][ni][0] + b0);
            p0[1] = act_fn<ACT>(acc[mi][ni][1] + b1);
            p1[0] = act_fn<ACT>(acc[mi][ni][2] + b0);
            p1[1] = act_fn<ACT>(acc[mi][ni][3] + b1);
        }
    }
}

// ---------------- flash attention, fp32, BR=BC=64, D=64, vectorized ----------------
#define FA_ST 68
#define FA_SMEM (int)((3 * 64 * FA_ST + 3 * 64) * sizeof(float))
__global__ __launch_bounds__(256)
void flash_kernel(const float* __restrict__ qkv, float* __restrict__ outp) {
    extern __shared__ float smf[];
    float* Qs   = smf;                 // [64][68]  Q (pre-scaled)
    float* Ks   = Qs + 64 * FA_ST;     // [64][68]  K tile, then V^T tile
    float* Ps   = Ks + 64 * FA_ST;     // [64][68]  scores / probs
    float* mrow = Ps + 64 * FA_ST;
    float* lrow = mrow + 64;
    float* crow = lrow + 64;

    int bh = blockIdx.y;
    int b = bh >> 4, h = bh & 15;
    int q0 = blockIdx.x * 64;
    int tid = threadIdx.x;

    // load and pre-scale Q (float4)
    for (int idx = tid; idx < 64 * 16; idx += 256) {
        int r = idx >> 4, dq = idx & 15;
        float4 v = *(const float4*)(qkv + (long)(b * Ss + q0 + r) * (3 * Cc) + h * Dd + dq * 4);
        v.x *= 0.125f; v.y *= 0.125f; v.z *= 0.125f; v.w *= 0.125f;
        *(float4*)&Qs[r * FA_ST + dq * 4] = v;
    }
    if (tid < 64) { mrow[tid] = -1e30f; lrow[tid] = 0.f; }
    __syncthreads();

    int tq = tid >> 4, tk = tid & 15;
    float Oreg[4][4] = {};   // rows tq+16i, d-cols tk+16j

    for (int j0 = 0; j0 < Ss; j0 += 64) {
        // K tile (row-major, float4)
        for (int idx = tid; idx < 64 * 16; idx += 256) {
            int r = idx >> 4, dq = idx & 15;
            *(float4*)&Ks[r * FA_ST + dq * 4] =
                *(const float4*)(qkv + (long)(b * Ss + j0 + r) * (3 * Cc) + Cc + h * Dd + dq * 4);
        }
        __syncthreads();

        // S = Q K^T  (vectorized over d)
        float acc[4][4] = {};
#pragma unroll 4
        for (int d4 = 0; d4 < 16; d4++) {
            float4 qa[4], kb[4];
#pragma unroll
            for (int i = 0; i < 4; i++) qa[i] = *(float4*)&Qs[(tq + 16 * i) * FA_ST + d4 * 4];
#pragma unroll
            for (int j = 0; j < 4; j++) kb[j] = *(float4*)&Ks[(tk + 16 * j) * FA_ST + d4 * 4];
#pragma unroll
            for (int i = 0; i < 4; i++)
#pragma unroll
                for (int j = 0; j < 4; j++) {
                    acc[i][j] += qa[i].x * kb[j].x + qa[i].y * kb[j].y
                               + qa[i].z * kb[j].z + qa[i].w * kb[j].w;
                }
        }
#pragma unroll
        for (int i = 0; i < 4; i++)
#pragma unroll
            for (int j = 0; j < 4; j++)
                Ps[(tq + 16 * i) * FA_ST + (tk + 16 * j)] = acc[i][j];
        __syncthreads();

        // online softmax: 4 threads per row
        {
            int r = tid >> 2, q = tid & 3;
            float* pr = Ps + r * FA_ST + q * 16;
            float4 pv[4];
            float tm = -1e30f;
#pragma unroll
            for (int c4 = 0; c4 < 4; c4++) {
                pv[c4] = *(float4*)&pr[c4 * 4];
                tm = fmaxf(tm, fmaxf(fmaxf(pv[c4].x, pv[c4].y), fmaxf(pv[c4].z, pv[c4].w)));
            }
            tm = fmaxf(tm, __shfl_xor_sync(0xffffffff, tm, 1));
            tm = fmaxf(tm, __shfl_xor_sync(0xffffffff, tm, 2));
            float mold = mrow[r];
            tm = fmaxf(tm, mold);
            float lsum = 0.f;
#pragma unroll
            for (int c4 = 0; c4 < 4; c4++) {
                pv[c4].x = __expf(pv[c4].x - tm);
                pv[c4].y = __expf(pv[c4].y - tm);
                pv[c4].z = __expf(pv[c4].z - tm);
                pv[c4].w = __expf(pv[c4].w - tm);
                lsum += pv[c4].x + pv[c4].y + pv[c4].z + pv[c4].w;
                *(float4*)&pr[c4 * 4] = pv[c4];
            }
            lsum += __shfl_xor_sync(0xffffffff, lsum, 1);
            lsum += __shfl_xor_sync(0xffffffff, lsum, 2);
            if (q == 0) {
                float corr = __expf(mold - tm);
                crow[r] = corr;
                mrow[r] = tm;
                lrow[r] = lrow[r] * corr + lsum;
            }
        }
        __syncthreads();

        // rescale O accumulators
#pragma unroll
        for (int i = 0; i < 4; i++) {
            float cr = crow[tq + 16 * i];
#pragma unroll
            for (int j = 0; j < 4; j++) Oreg[i][j] *= cr;
        }

        // V tile, stored TRANSPOSED into Ks: Ks[d][c]
        for (int idx = tid; idx < 64 * 16; idx += 256) {
            int c = idx & 63, dq = idx >> 6;   // dq 0..15
            float4 v = *(const float4*)(qkv + (long)(b * Ss + j0 + c) * (3 * Cc)
                                        + 2 * Cc + h * Dd + dq * 4);
            Ks[(dq * 4 + 0) * FA_ST + c] = v.x;
            Ks[(dq * 4 + 1) * FA_ST + c] = v.y;
            Ks[(dq * 4 + 2) * FA_ST + c] = v.z;
            Ks[(dq * 4 + 3) * FA_ST + c] = v.w;
        }
        __syncthreads();

        // O += P @ V   (vectorized over c via V^T)
#pragma unroll 4
        for (int c4 = 0; c4 < 16; c4++) {
            float4 pa[4], vv[4];
#pragma unroll
            for (int i = 0; i < 4; i++) pa[i] = *(float4*)&Ps[(tq + 16 * i) * FA_ST + c4 * 4];
#pragma unroll
            for (int j = 0; j < 4; j++) vv[j] = *(float4*)&Ks[(tk + 16 * j) * FA_ST + c4 * 4];
#pragma unroll
            for (int i = 0; i < 4; i++)
#pragma unroll
                for (int j = 0; j < 4; j++) {
                    Oreg[i][j] += pa[i].x * vv[j].x + pa[i].y * vv[j].y
                                + pa[i].z * vv[j].z + pa[i].w * vv[j].w;
                }
        }
        __syncthreads();
    }

    // write out: [B,S,heads*D]
#pragma unroll
    for (int i = 0; i < 4; i++) {
        int r = tq + 16 * i;
        float inv = 1.f / lrow[r];
#pragma unroll
        for (int j = 0; j < 4; j++) {
            int d = tk + 16 * j;
            outp[(long)(b * Ss + q0 + r) * Cc + h * Dd + d] = Oreg[i][j] * inv;
        }
    }
}

// ---------------- launch ----------------
extern "C" void kernel_launch(void* const* d_in, const int* in_sizes, int n_in,
                              void* d_out, int out_size) {
    const float* x       = (const float*)d_in[0];
    const float* mod     = (const float*)d_in[1];
    const float* cond    = (const float*)d_in[2];
    const float* w_adaln = (const float*)d_in[3];
    const float* b_adaln = (const float*)d_in[4];
    const float* w_qkv   = (const float*)d_in[5];
    const float* b_qkv   = (const float*)d_in[6];
    const float* w_proj  = (const float*)d_in[7];
    const float* b_proj  = (const float*)d_in[8];
    const float* w_s1    = (const float*)d_in[9];
    const float* b_s1    = (const float*)d_in[10];
    const float* w_s2    = (const float*)d_in[11];
    const float* b_s2    = (const float*)d_in[12];
    const float* w_d1    = (const float*)d_in[13];
    const float* b_d1    = (const float*)d_in[14];
    const float* w_d2    = (const float*)d_in[15];
    const float* b_d2    = (const float*)d_in[16];

    float* outx = (float*)d_out;                         // [2,2048,1024]
    float* outc = outx + (long)Bz * Nn * Cc;             // [2,256,1024]

    float *gm, *gjoint, *gqkv, *gattn, *ghid;
    cudaGetSymbolAddress((void**)&gm,     g_m);
    cudaGetSymbolAddress((void**)&gjoint, g_joint);
    cudaGetSymbolAddress((void**)&gqkv,   g_qkv);
    cudaGetSymbolAddress((void**)&gattn,  g_attn);
    cudaGetSymbolAddress((void**)&ghid,   g_hidden);

    cudaFuncSetAttribute(flash_kernel, cudaFuncAttributeMaxDynamicSharedMemorySize, FA_SMEM);

    const long SC = (long)Ss * Cc;
    const long NC = (long)Nn * Cc;
    const long TC = (long)Tt * Cc;

    // 1. modulation vectors
    adaln_kernel<<<dim3(24, Bz), 256>>>(mod, w_adaln, b_adaln, gm);

    // 2. LN + msa modulate -> joint [B,S,C]
    ln_mod_kernel<<<Bz * Nn, 256>>>(x,    gjoint, gm, Nn, 0, Cc, SC, 0);
    ln_mod_kernel<<<Bz * Tt, 256>>>(cond, gjoint, gm, Tt, 0, Cc, SC, Nn);

    // 3. qkv = joint @ w_qkv + b  (4608 x 3072 x 1024)
    mma_gemm<0><<<dim3(3072 / 128, (Bz * Ss) / 128), 256>>>(gjoint, w_qkv, b_qkv, gqkv,
                                                            Bz * Ss, 3 * Cc, Cc);

    // 4. attention
    flash_kernel<<<dim3(Ss / 64, Bz * HEADS), 256, FA_SMEM>>>(gqkv, gattn);

    // 5. proj (4608 x 1024 x 1024) -> gjoint (reuse)
    mma_gemm<0><<<dim3(Cc / 128, (Bz * Ss) / 128), 256>>>(gattn, w_proj, b_proj, gjoint,
                                                          Bz * Ss, Cc, Cc);

    // 6. attn residual with g_msa (offset 2C)
    resid_gate_kernel<<<Bz * Nn, 256>>>(x,    gjoint, outx, gm, 2 * Cc, Nn, SC, 0);
    resid_gate_kernel<<<Bz * Tt, 256>>>(cond, gjoint, outc, gm, 2 * Cc, Tt, SC, Nn);

    // 7. LN + mlp modulate (sh_mlp=3C, sc_mlp=4C)
    float* gx2 = gjoint;                      // [B*N, C]
    float* gc2 = gjoint + (long)Bz * Nn * Cc; // [B*T, C]
    ln_mod_kernel<<<Bz * Nn, 256>>>(outx, gx2, gm, Nn, 3 * Cc, 4 * Cc, NC, 0);
    ln_mod_kernel<<<Bz * Tt, 256>>>(outc, gc2, gm, Tt, 3 * Cc, 4 * Cc, TC, 0);

    // 8. x MLP: gelu(x2@w_s1+b) @ w_s2 + b
    mma_gemm<1><<<dim3(Hh / 128, (Bz * Nn) / 128), 256>>>(gx2, w_s1, b_s1, ghid,
                                                          Bz * Nn, Hh, Cc);
    mma_gemm<0><<<dim3(Cc / 128, (Bz * Nn) / 128), 256>>>(ghid, w_s2, b_s2, gqkv,
                                                          Bz * Nn, Cc, Hh);
    resid_gate_kernel<<<Bz * Nn, 256>>>(outx, gqkv, outx, gm, 5 * Cc, Nn, NC, 0);

    // 9. cond MLP: silu(c2@w_d1+b) @ w_d2 + b
    mma_gemm<2><<<dim3(Hh / 128, (Bz * Tt) / 128), 256>>>(gc2, w_d1, b_d1, ghid,
                                                          Bz * Tt, Hh, Cc);
    mma_gemm<0><<<dim3(Cc / 128, (Bz * Tt) / 128), 256>>>(ghid, w_d2, b_d2, gqkv,
                                                          Bz * Tt, Cc, Hh);
    resid_gate_kernel<<<Bz * Tt, 256>>>(outc, gqkv, outc, gm, 5 * Cc, Tt, TC, 0);
}

// round 7
// speedup vs baseline: 2.6205x; 1.3664x over previous
#include <cuda_runtime.h>
#include <cuda_bf16.h>
#include <cstdint>

// ---------------- problem constants ----------------
#define Bz   2
#define Nn   2048
#define Tt   256
#define Cc   1024
#define Hh   4096
#define Ss   2304          // N + T
#define HEADS 16
#define Dd   64

// ---------------- scratch (no allocation allowed) ----------------
__device__ float g_m[Bz * 6 * Cc];                 // adaLN modulation vectors
__device__ float g_joint[(long)Bz * Ss * Cc];      // joint ln input / x2,c2
__device__ float g_qkv[(long)Bz * Ss * 3 * Cc];    // qkv / mlp out
__device__ float g_attn[(long)Bz * Ss * Cc];       // attention output
__device__ float g_hidden[(long)4096 * 4096];      // MLP hidden

// ---------------- activations ----------------
template<int ACT>
__device__ __forceinline__ float act_fn(float x) {
    if (ACT == 1) { // gelu tanh approx
        float x3 = x * x * x;
        return 0.5f * x * (1.f + tanhf(0.7978845608028654f * (x + 0.044715f * x3)));
    }
    if (ACT == 2) { // silu
        return x / (1.f + __expf(-x));
    }
    return x;
}

__device__ __forceinline__ uint32_t f2tf32(float f) {
    uint32_t u;
    asm("cvt.rna.tf32.f32 %0, %1;" : "=r"(u) : "f"(f));
    return u;
}

__device__ __forceinline__ void mma_tf32(float* d,
                                         const uint32_t* a, const uint32_t* b) {
    asm volatile(
        "mma.sync.aligned.m16n8k8.row.col.f32.tf32.tf32.f32 "
        "{%0,%1,%2,%3}, {%4,%5,%6,%7}, {%8,%9}, {%0,%1,%2,%3};\n"
        : "+f"(d[0]), "+f"(d[1]), "+f"(d[2]), "+f"(d[3])
        : "r"(a[0]), "r"(a[1]), "r"(a[2]), "r"(a[3]), "r"(b[0]), "r"(b[1]));
}

// ---------------- adaLN: m = silu(mod) @ w_adaln + b ----------------
__global__ void adaln_kernel(const float* __restrict__ mod,
                             const float* __restrict__ w,
                             const float* __restrict__ bias,
                             float* __restrict__ mout) {
    int b = blockIdx.y;
    int j = blockIdx.x * 256 + threadIdx.x;   // < 6144
    __shared__ float sm[Cc];
    for (int i = threadIdx.x; i < Cc; i += 256) {
        float v = mod[b * Cc + i];
        sm[i] = v / (1.f + __expf(-v));
    }
    __syncthreads();
    float acc = bias[j];
    for (int k = 0; k < Cc; k++) acc += sm[k] * w[(long)k * (6 * Cc) + j];
    mout[b * 6 * Cc + j] = acc;
}

// ---------------- LN + modulate ----------------
__global__ void ln_mod_kernel(const float* __restrict__ in, float* __restrict__ out,
                              const float* __restrict__ m, int rowsPerBatch,
                              int shOff, int scOff,
                              long outBatchStride, int outRowOff) {
    int row = blockIdx.x;
    int b = row / rowsPerBatch;
    int r = row - b * rowsPerBatch;
    const float* xi = in + (long)row * Cc;
    float v[4]; float s = 0.f, s2 = 0.f;
#pragma unroll
    for (int i = 0; i < 4; i++) {
        v[i] = xi[threadIdx.x + 256 * i];
        s += v[i]; s2 += v[i] * v[i];
    }
    __shared__ float rs[256], rs2[256];
    rs[threadIdx.x] = s; rs2[threadIdx.x] = s2;
    __syncthreads();
    for (int off = 128; off > 0; off >>= 1) {
        if (threadIdx.x < off) {
            rs[threadIdx.x]  += rs[threadIdx.x + off];
            rs2[threadIdx.x] += rs2[threadIdx.x + off];
        }
        __syncthreads();
    }
    float mu   = rs[0] * (1.f / (float)Cc);
    float var  = rs2[0] * (1.f / (float)Cc) - mu * mu;
    float rstd = rsqrtf(var + 1e-6f);
    const float* mb = m + b * 6 * Cc;
    float* po = out + (long)b * outBatchStride + (long)(outRowOff + r) * Cc;
#pragma unroll
    for (int i = 0; i < 4; i++) {
        int c = threadIdx.x + 256 * i;
        po[c] = (v[i] - mu) * rstd * (1.f + mb[scOff + c]) + mb[shOff + c];
    }
}

// ---------------- residual gate ----------------
__global__ void resid_gate_kernel(const float* __restrict__ base,
                                  const float* __restrict__ add,
                                  float* __restrict__ out,
                                  const float* __restrict__ m, int gOff,
                                  int rowsPerBatch, long addBatchStride, int addRowOff) {
    int row = blockIdx.x;
    int b = row / rowsPerBatch;
    int r = row - b * rowsPerBatch;
    const float* pb = base + (long)row * Cc;
    const float* pa = add + (long)b * addBatchStride + (long)(addRowOff + r) * Cc;
    float* po = out + (long)row * Cc;
    const float* g = m + b * 6 * Cc + gOff;
#pragma unroll
    for (int i = 0; i < 4; i++) {
        int c = threadIdx.x + 256 * i;
        po[c] = pb[c] + pa[c] * g[c];
    }
}

// ---------------- TF32 tensor-core GEMM (validated in R2) ----------------
template<int ACT>
__global__ __launch_bounds__(256)
void mma_gemm(const float* __restrict__ A, const float* __restrict__ B,
              const float* __restrict__ bias, float* __restrict__ C,
              int M, int N, int K) {
    __shared__ uint32_t As[2][16][136];
    __shared__ uint32_t Bs[2][16][136];

    int tid  = threadIdx.x;
    int warp = tid >> 5, lane = tid & 31;
    int g    = lane >> 2, tig = lane & 3;
    int warpM = (warp >> 2) * 64;
    int warpN = (warp & 3) * 32;

    const float* Ab = A + (long)blockIdx.y * 128 * K;
    const float* Bb = B + blockIdx.x * 128;

    int aRow  = tid >> 1;
    int aCol  = (tid & 1) * 8;
    int bRow  = tid >> 4;
    int bCol4 = (tid & 15);

    float acc[4][4][4];
#pragma unroll
    for (int i = 0; i < 4; i++)
#pragma unroll
        for (int j = 0; j < 4; j++)
#pragma unroll
            for (int q = 0; q < 4; q++) acc[i][j][q] = 0.f;

    float4 ar0, ar1, br0, br1;

    ar0 = *(const float4*)(Ab + (long)aRow * K + aCol);
    ar1 = *(const float4*)(Ab + (long)aRow * K + aCol + 4);
    br0 = *(const float4*)(Bb + (long)bRow * N + bCol4 * 4);
    br1 = *(const float4*)(Bb + (long)bRow * N + (bCol4 + 16) * 4);
    {
        As[0][aCol + 0][aRow] = f2tf32(ar0.x);
        As[0][aCol + 1][aRow] = f2tf32(ar0.y);
        As[0][aCol + 2][aRow] = f2tf32(ar0.z);
        As[0][aCol + 3][aRow] = f2tf32(ar0.w);
        As[0][aCol + 4][aRow] = f2tf32(ar1.x);
        As[0][aCol + 5][aRow] = f2tf32(ar1.y);
        As[0][aCol + 6][aRow] = f2tf32(ar1.z);
        As[0][aCol + 7][aRow] = f2tf32(ar1.w);
        uint4 p0 = { f2tf32(br0.x), f2tf32(br0.y), f2tf32(br0.z), f2tf32(br0.w) };
        uint4 p1 = { f2tf32(br1.x), f2tf32(br1.y), f2tf32(br1.z), f2tf32(br1.w) };
        *(uint4*)&Bs[0][bRow][bCol4 * 4]        = p0;
        *(uint4*)&Bs[0][bRow][(bCol4 + 16) * 4] = p1;
    }
    __syncthreads();

    int nstages = K >> 4;
    for (int s = 0; s < nstages; s++) {
        int cur = s & 1;
        bool has_next = (s + 1 < nstages);
        if (has_next) {
            int k0 = (s + 1) << 4;
            ar0 = *(const float4*)(Ab + (long)aRow * K + k0 + aCol);
            ar1 = *(const float4*)(Ab + (long)aRow * K + k0 + aCol + 4);
            br0 = *(const float4*)(Bb + (long)(k0 + bRow) * N + bCol4 * 4);
            br1 = *(const float4*)(Bb + (long)(k0 + bRow) * N + (bCol4 + 16) * 4);
        }
#pragma unroll
        for (int kk = 0; kk < 2; kk++) {
            uint32_t af[4][4], bf[4][2];
#pragma unroll
            for (int mi = 0; mi < 4; mi++) {
                int m = warpM + mi * 16;
                af[mi][0] = As[cur][kk * 8 + tig][m + g];
                af[mi][1] = As[cur][kk * 8 + tig][m + g + 8];
                af[mi][2] = As[cur][kk * 8 + tig + 4][m + g];
                af[mi][3] = As[cur][kk * 8 + tig + 4][m + g + 8];
            }
#pragma unroll
            for (int ni = 0; ni < 4; ni++) {
                int n = warpN + ni * 8;
                bf[ni][0] = Bs[cur][kk * 8 + tig][n + g];
                bf[ni][1] = Bs[cur][kk * 8 + tig + 4][n + g];
            }
#pragma unroll
            for (int mi = 0; mi < 4; mi++)
#pragma unroll
                for (int ni = 0; ni < 4; ni++)
                    mma_tf32(acc[mi][ni], af[mi], bf[ni]);
        }
        if (has_next) {
            int nb = (s + 1) & 1;
            As[nb][aCol + 0][aRow] = f2tf32(ar0.x);
            As[nb][aCol + 1][aRow] = f2tf32(ar0.y);
            As[nb][aCol + 2][aRow] = f2tf32(ar0.z);
            As[nb][aCol + 3][aRow] = f2tf32(ar0.w);
            As[nb][aCol + 4][aRow] = f2tf32(ar1.x);
            As[nb][aCol + 5][aRow] = f2tf32(ar1.y);
            As[nb][aCol + 6][aRow] = f2tf32(ar1.z);
            As[nb][aCol + 7][aRow] = f2tf32(ar1.w);
            uint4 p0 = { f2tf32(br0.x), f2tf32(br0.y), f2tf32(br0.z), f2tf32(br0.w) };
            uint4 p1 = { f2tf32(br1.x), f2tf32(br1.y), f2tf32(br1.z), f2tf32(br1.w) };
            *(uint4*)&Bs[nb][bRow][bCol4 * 4]        = p0;
            *(uint4*)&Bs[nb][bRow][(bCol4 + 16) * 4] = p1;
        }
        __syncthreads();
    }

    int rowBase = blockIdx.y * 128 + warpM;
    int colBase = blockIdx.x * 128 + warpN;
#pragma unroll
    for (int mi = 0; mi < 4; mi++) {
#pragma unroll
        for (int ni = 0; ni < 4; ni++) {
            int r0 = rowBase + mi * 16 + g;
            int c0 = colBase + ni * 8 + tig * 2;
            float b0 = bias[c0], b1 = bias[c0 + 1];
            float* p0 = C + (long)r0 * N + c0;
            float* p1 = C + (long)(r0 + 8) * N + c0;
            p0[0] = act_fn<ACT>(acc[mi][ni][0] + b0);
            p0[1] = act_fn<ACT>(acc[mi][ni][1] + b1);
            p1[0] = act_fn<ACT>(acc[mi][ni][2] + b0);
            p1[1] = act_fn<ACT>(acc[mi][ni][3] + b1);
        }
    }
}

// ---------------- TF32 tensor-core flash attention ----------------
// BR=BC=64, D=64. 8 warps: 2 (M, 32 rows) x 4 (N, 16 cols).
// Qt[d][r] / Kt[d][j] / Vs[c][d] in tf32 (stride 72); Pt[c][r] scores^T (stride 73).
#define QK_ST 72
#define P_ST  73
#define FA_SMEM (int)((2 * 64 * QK_ST + 64 * P_ST + 3 * 64) * sizeof(float))
__global__ __launch_bounds__(256)
void flash_tc_kernel(const float* __restrict__ qkv, float* __restrict__ outp) {
    extern __shared__ float smf[];
    uint32_t* Qt  = (uint32_t*)smf;            // [64][QK_ST]
    uint32_t* KVt = Qt + 64 * QK_ST;           // K^T tile, then V tile
    uint32_t* Pt  = KVt + 64 * QK_ST;          // [64][P_ST]
    float* mrow = (float*)(Pt + 64 * P_ST);
    float* lrow = mrow + 64;
    float* crow = lrow + 64;

    int bh = blockIdx.y;
    int b = bh >> 4, h = bh & 15;
    int q0 = blockIdx.x * 64;
    int tid = threadIdx.x;
    int lane = tid & 31, warp = tid >> 5;
    int g = lane >> 2, tig = lane & 3;
    int warpM = (warp >> 2) * 32;
    int warpN = (warp & 3) * 16;

    // load Q transposed + pre-scale (lanes span r: conflict-free)
    for (int idx = tid; idx < 1024; idx += 256) {
        int r = idx & 63, dq = idx >> 6;   // dq 0..15
        float4 v = *(const float4*)(qkv + (long)(b * Ss + q0 + r) * (3 * Cc) + h * Dd + dq * 4);
        Qt[(dq * 4 + 0) * QK_ST + r] = f2tf32(v.x * 0.125f);
        Qt[(dq * 4 + 1) * QK_ST + r] = f2tf32(v.y * 0.125f);
        Qt[(dq * 4 + 2) * QK_ST + r] = f2tf32(v.z * 0.125f);
        Qt[(dq * 4 + 3) * QK_ST + r] = f2tf32(v.w * 0.125f);
    }
    if (tid < 64) { mrow[tid] = -1e30f; lrow[tid] = 0.f; }
    __syncthreads();

    float Oc[2][2][4] = {};   // [mi][ni][frag]

    for (int j0 = 0; j0 < Ss; j0 += 64) {
        // ---- K^T tile ----
        for (int idx = tid; idx < 1024; idx += 256) {
            int r = idx & 63, dq = idx >> 6;
            float4 v = *(const float4*)(qkv + (long)(b * Ss + j0 + r) * (3 * Cc) + Cc + h * Dd + dq * 4);
            KVt[(dq * 4 + 0) * QK_ST + r] = f2tf32(v.x);
            KVt[(dq * 4 + 1) * QK_ST + r] = f2tf32(v.y);
            KVt[(dq * 4 + 2) * QK_ST + r] = f2tf32(v.z);
            KVt[(dq * 4 + 3) * QK_ST + r] = f2tf32(v.w);
        }
        __syncthreads();

        // ---- S = Q K^T on tensor cores ----
        float Sc[2][2][4];
#pragma unroll
        for (int mi = 0; mi < 2; mi++)
#pragma unroll
            for (int ni = 0; ni < 2; ni++)
#pragma unroll
                for (int q = 0; q < 4; q++) Sc[mi][ni][q] = 0.f;
#pragma unroll
        for (int ks = 0; ks < 8; ks++) {
            uint32_t af[2][4], bf[2][2];
#pragma unroll
            for (int mi = 0; mi < 2; mi++) {
                int m = warpM + mi * 16;
                af[mi][0] = Qt[(ks * 8 + tig) * QK_ST + m + g];
                af[mi][1] = Qt[(ks * 8 + tig) * QK_ST + m + g + 8];
                af[mi][2] = Qt[(ks * 8 + tig + 4) * QK_ST + m + g];
                af[mi][3] = Qt[(ks * 8 + tig + 4) * QK_ST + m + g + 8];
            }
#pragma unroll
            for (int ni = 0; ni < 2; ni++) {
                int n = warpN + ni * 8;
                bf[ni][0] = KVt[(ks * 8 + tig) * QK_ST + n + g];
                bf[ni][1] = KVt[(ks * 8 + tig + 4) * QK_ST + n + g];
            }
#pragma unroll
            for (int mi = 0; mi < 2; mi++)
#pragma unroll
                for (int ni = 0; ni < 2; ni++)
                    mma_tf32(Sc[mi][ni], af[mi], bf[ni]);
        }
        // store S^T into Pt (as raw float bits)
#pragma unroll
        for (int mi = 0; mi < 2; mi++) {
            int m0 = warpM + mi * 16 + g;
#pragma unroll
            for (int ni = 0; ni < 2; ni++) {
                int n0 = warpN + ni * 8 + tig * 2;
                Pt[n0 * P_ST + m0]           = __float_as_uint(Sc[mi][ni][0]);
                Pt[(n0 + 1) * P_ST + m0]     = __float_as_uint(Sc[mi][ni][1]);
                Pt[n0 * P_ST + m0 + 8]       = __float_as_uint(Sc[mi][ni][2]);
                Pt[(n0 + 1) * P_ST + m0 + 8] = __float_as_uint(Sc[mi][ni][3]);
            }
        }
        __syncthreads();

        // ---- online softmax (4 threads per row) on Pt[c][r] ----
        {
            int r = tid >> 2, q = tid & 3;
            float pv[16];
            float tm = -1e30f;
#pragma unroll
            for (int i = 0; i < 16; i++) {
                pv[i] = __uint_as_float(Pt[(q * 16 + i) * P_ST + r]);
                tm = fmaxf(tm, pv[i]);
            }
            tm = fmaxf(tm, __shfl_xor_sync(0xffffffff, tm, 1));
            tm = fmaxf(tm, __shfl_xor_sync(0xffffffff, tm, 2));
            float mold = mrow[r];
            tm = fmaxf(tm, mold);
            float ls = 0.f;
#pragma unroll
            for (int i = 0; i < 16; i++) {
                float p = __expf(pv[i] - tm);
                ls += p;
                Pt[(q * 16 + i) * P_ST + r] = f2tf32(p);
            }
            ls += __shfl_xor_sync(0xffffffff, ls, 1);
            ls += __shfl_xor_sync(0xffffffff, ls, 2);
            if (q == 0) {
                float corr = __expf(mold - tm);
                crow[r] = corr;
                mrow[r] = tm;
                lrow[r] = lrow[r] * corr + ls;
            }
        }

        // ---- V tile (natural [c][d], tf32) ----
        for (int idx = tid; idx < 1024; idx += 256) {
            int c = idx >> 4, dq = idx & 15;
            float4 v = *(const float4*)(qkv + (long)(b * Ss + j0 + c) * (3 * Cc)
                                        + 2 * Cc + h * Dd + dq * 4);
            uint4 p = { f2tf32(v.x), f2tf32(v.y), f2tf32(v.z), f2tf32(v.w) };
            *(uint4*)&KVt[c * QK_ST + dq * 4] = p;
        }
        __syncthreads();

        // ---- rescale O accumulators ----
#pragma unroll
        for (int mi = 0; mi < 2; mi++) {
            int m0 = warpM + mi * 16 + g;
            float cl = crow[m0], ch = crow[m0 + 8];
#pragma unroll
            for (int ni = 0; ni < 2; ni++) {
                Oc[mi][ni][0] *= cl; Oc[mi][ni][1] *= cl;
                Oc[mi][ni][2] *= ch; Oc[mi][ni][3] *= ch;
            }
        }

        // ---- O += P @ V on tensor cores (k = c) ----
#pragma unroll
        for (int ks = 0; ks < 8; ks++) {
            uint32_t af[2][4], bf[2][2];
#pragma unroll
            for (int mi = 0; mi < 2; mi++) {
                int m = warpM + mi * 16;
                af[mi][0] = Pt[(ks * 8 + tig) * P_ST + m + g];
                af[mi][1] = Pt[(ks * 8 + tig) * P_ST + m + g + 8];
                af[mi][2] = Pt[(ks * 8 + tig + 4) * P_ST + m + g];
                af[mi][3] = Pt[(ks * 8 + tig + 4) * P_ST + m + g + 8];
            }
#pragma unroll
            for (int ni = 0; ni < 2; ni++) {
                int n = warpN + ni * 8;
                bf[ni][0] = KVt[(ks * 8 + tig) * QK_ST + n + g];
                bf[ni][1] = KVt[(ks * 8 + tig + 4) * QK_ST + n + g];
            }
#pragma unroll
            for (int mi = 0; mi < 2; mi++)
#pragma unroll
                for (int ni = 0; ni < 2; ni++)
                    mma_tf32(Oc[mi][ni], af[mi], bf[ni]);
        }
        __syncthreads();
    }

    // ---- epilogue: normalize and write ----
#pragma unroll
    for (int mi = 0; mi < 2; mi++) {
        int m0 = warpM + mi * 16 + g;
        float inv0 = 1.f / lrow[m0];
        float inv1 = 1.f / lrow[m0 + 8];
#pragma unroll
        for (int ni = 0; ni < 2; ni++) {
            int n0 = warpN + ni * 8 + tig * 2;
            float2 w0 = { Oc[mi][ni][0] * inv0, Oc[mi][ni][1] * inv0 };
            float2 w1 = { Oc[mi][ni][2] * inv1, Oc[mi][ni][3] * inv1 };
            *(float2*)(outp + (long)(b * Ss + q0 + m0) * Cc + h * Dd + n0)     = w0;
            *(float2*)(outp + (long)(b * Ss + q0 + m0 + 8) * Cc + h * Dd + n0) = w1;
        }
    }
}

// ---------------- launch ----------------
extern "C" void kernel_launch(void* const* d_in, const int* in_sizes, int n_in,
                              void* d_out, int out_size) {
    const float* x       = (const float*)d_in[0];
    const float* mod     = (const float*)d_in[1];
    const float* cond    = (const float*)d_in[2];
    const float* w_adaln = (const float*)d_in[3];
    const float* b_adaln = (const float*)d_in[4];
    const float* w_qkv   = (const float*)d_in[5];
    const float* b_qkv   = (const float*)d_in[6];
    const float* w_proj  = (const float*)d_in[7];
    const float* b_proj  = (const float*)d_in[8];
    const float* w_s1    = (const float*)d_in[9];
    const float* b_s1    = (const float*)d_in[10];
    const float* w_s2    = (const float*)d_in[11];
    const float* b_s2    = (const float*)d_in[12];
    const float* w_d1    = (const float*)d_in[13];
    const float* b_d1    = (const float*)d_in[14];
    const float* w_d2    = (const float*)d_in[15];
    const float* b_d2    = (const float*)d_in[16];

    float* outx = (float*)d_out;                         // [2,2048,1024]
    float* outc = outx + (long)Bz * Nn * Cc;             // [2,256,1024]

    float *gm, *gjoint, *gqkv, *gattn, *ghid;
    cudaGetSymbolAddress((void**)&gm,     g_m);
    cudaGetSymbolAddress((void**)&gjoint, g_joint);
    cudaGetSymbolAddress((void**)&gqkv,   g_qkv);
    cudaGetSymbolAddress((void**)&gattn,  g_attn);
    cudaGetSymbolAddress((void**)&ghid,   g_hidden);

    cudaFuncSetAttribute(flash_tc_kernel, cudaFuncAttributeMaxDynamicSharedMemorySize, FA_SMEM);

    const long SC = (long)Ss * Cc;
    const long NC = (long)Nn * Cc;
    const long TC = (long)Tt * Cc;

    // 1. modulation vectors
    adaln_kernel<<<dim3(24, Bz), 256>>>(mod, w_adaln, b_adaln, gm);

    // 2. LN + msa modulate -> joint [B,S,C]
    ln_mod_kernel<<<Bz * Nn, 256>>>(x,    gjoint, gm, Nn, 0, Cc, SC, 0);
    ln_mod_kernel<<<Bz * Tt, 256>>>(cond, gjoint, gm, Tt, 0, Cc, SC, Nn);

    // 3. qkv = joint @ w_qkv + b  (4608 x 3072 x 1024)
    mma_gemm<0><<<dim3(3072 / 128, (Bz * Ss) / 128), 256>>>(gjoint, w_qkv, b_qkv, gqkv,
                                                            Bz * Ss, 3 * Cc, Cc);

    // 4. attention (tensor-core flash)
    flash_tc_kernel<<<dim3(Ss / 64, Bz * HEADS), 256, FA_SMEM>>>(gqkv, gattn);

    // 5. proj (4608 x 1024 x 1024) -> gjoint (reuse)
    mma_gemm<0><<<dim3(Cc / 128, (Bz * Ss) / 128), 256>>>(gattn, w_proj, b_proj, gjoint,
                                                          Bz * Ss, Cc, Cc);

    // 6. attn residual with g_msa (offset 2C)
    resid_gate_kernel<<<Bz * Nn, 256>>>(x,    gjoint, outx, gm, 2 * Cc, Nn, SC, 0);
    resid_gate_kernel<<<Bz * Tt, 256>>>(cond, gjoint, outc, gm, 2 * Cc, Tt, SC, Nn);

    // 7. LN + mlp modulate (sh_mlp=3C, sc_mlp=4C)
    float* gx2 = gjoint;                      // [B*N, C]
    float* gc2 = gjoint + (long)Bz * Nn * Cc; // [B*T, C]
    ln_mod_kernel<<<Bz * Nn, 256>>>(outx, gx2, gm, Nn, 3 * Cc, 4 * Cc, NC, 0);
    ln_mod_kernel<<<Bz * Tt, 256>>>(outc, gc2, gm, Tt, 3 * Cc, 4 * Cc, TC, 0);

    // 8. x MLP: gelu(x2@w_s1+b) @ w_s2 + b
    mma_gemm<1><<<dim3(Hh / 128, (Bz * Nn) / 128), 256>>>(gx2, w_s1, b_s1, ghid,
                                                          Bz * Nn, Hh, Cc);
    mma_gemm<0><<<dim3(Cc / 128, (Bz * Nn) / 128), 256>>>(ghid, w_s2, b_s2, gqkv,
                                                          Bz * Nn, Cc, Hh);
    resid_gate_kernel<<<Bz * Nn, 256>>>(outx, gqkv, outx, gm, 5 * Cc, Nn, NC, 0);

    // 9. cond MLP: silu(c2@w_d1+b) @ w_d2 + b
    mma_gemm<2><<<dim3(Hh / 128, (Bz * Tt) / 128), 256>>>(gc2, w_d1, b_d1, ghid,
                                                          Bz * Tt, Hh, Cc);
    mma_gemm<0><<<dim3(Cc / 128, (Bz * Tt) / 128), 256>>>(ghid, w_d2, b_d2, gqkv,
                                                          Bz * Tt, Cc, Hh);
    resid_gate_kernel<<<Bz * Tt, 256>>>(outc, gqkv, outc, gm, 5 * Cc, Tt, TC, 0);
}

// round 8
// speedup vs baseline: 2.8907x; 1.1031x over previous
#include <cuda_runtime.h>
#include <cuda_bf16.h>
#include <cstdint>

// ---------------- problem constants ----------------
#define Bz   2
#define Nn   2048
#define Tt   256
#define Cc   1024
#define Hh   4096
#define Ss   2304          // N + T
#define HEADS 16
#define Dd   64

// ---------------- scratch (no allocation allowed) ----------------
__device__ float g_m[Bz * 6 * Cc];                 // adaLN modulation vectors
__device__ float g_joint[(long)Bz * Ss * Cc];      // joint ln input / x2,c2
__device__ float g_qkv[(long)Bz * Ss * 3 * Cc];    // qkv / mlp out
__device__ float g_attn[(long)Bz * Ss * Cc];      // attention output
__device__ float g_hidden[(long)4096 * 4096];      // MLP hidden

// ---------------- activations ----------------
template<int ACT>
__device__ __forceinline__ float act_fn(float x) {
    if (ACT == 1) { // gelu tanh approx
        float x3 = x * x * x;
        return 0.5f * x * (1.f + tanhf(0.7978845608028654f * (x + 0.044715f * x3)));
    }
    if (ACT == 2) { // silu
        return x / (1.f + __expf(-x));
    }
    return x;
}

__device__ __forceinline__ void mma_tf32(float* d,
                                         const uint32_t* a, const uint32_t* b) {
    asm volatile(
        "mma.sync.aligned.m16n8k8.row.col.f32.tf32.tf32.f32 "
        "{%0,%1,%2,%3}, {%4,%5,%6,%7}, {%8,%9}, {%0,%1,%2,%3};\n"
        : "+f"(d[0]), "+f"(d[1]), "+f"(d[2]), "+f"(d[3])
        : "r"(a[0]), "r"(a[1]), "r"(a[2]), "r"(a[3]), "r"(b[0]), "r"(b[1]));
}

__device__ __forceinline__ void cp_async16(uint32_t smem_dst, const void* gsrc) {
    asm volatile("cp.async.ca.shared.global [%0], [%1], 16;\n"
                 :: "r"(smem_dst), "l"(gsrc));
}

// ---------------- adaLN: m = silu(mod) @ w_adaln + b ----------------
__global__ void adaln_kernel(const float* __restrict__ mod,
                             const float* __restrict__ w,
                             const float* __restrict__ bias,
                             float* __restrict__ mout) {
    int b = blockIdx.y;
    int j = blockIdx.x * 256 + threadIdx.x;   // < 6144
    __shared__ float sm[Cc];
    for (int i = threadIdx.x; i < Cc; i += 256) {
        float v = mod[b * Cc + i];
        sm[i] = v / (1.f + __expf(-v));
    }
    __syncthreads();
    float acc = bias[j];
    for (int k = 0; k < Cc; k++) acc += sm[k] * w[(long)k * (6 * Cc) + j];
    mout[b * 6 * Cc + j] = acc;
}

// ---------------- LN + modulate ----------------
__global__ void ln_mod_kernel(const float* __restrict__ in, float* __restrict__ out,
                              const float* __restrict__ m, int rowsPerBatch,
                              int shOff, int scOff,
                              long outBatchStride, int outRowOff) {
    int row = blockIdx.x;
    int b = row / rowsPerBatch;
    int r = row - b * rowsPerBatch;
    const float* xi = in + (long)row * Cc;
    float v[4]; float s = 0.f, s2 = 0.f;
#pragma unroll
    for (int i = 0; i < 4; i++) {
        v[i] = xi[threadIdx.x + 256 * i];
        s += v[i]; s2 += v[i] * v[i];
    }
    __shared__ float rs[256], rs2[256];
    rs[threadIdx.x] = s; rs2[threadIdx.x] = s2;
    __syncthreads();
    for (int off = 128; off > 0; off >>= 1) {
        if (threadIdx.x < off) {
            rs[threadIdx.x]  += rs[threadIdx.x + off];
            rs2[threadIdx.x] += rs2[threadIdx.x + off];
        }
        __syncthreads();
    }
    float mu   = rs[0] * (1.f / (float)Cc);
    float var  = rs2[0] * (1.f / (float)Cc) - mu * mu;
    float rstd = rsqrtf(var + 1e-6f);
    const float* mb = m + b * 6 * Cc;
    float* po = out + (long)b * outBatchStride + (long)(outRowOff + r) * Cc;
#pragma unroll
    for (int i = 0; i < 4; i++) {
        int c = threadIdx.x + 256 * i;
        po[c] = (v[i] - mu) * rstd * (1.f + mb[scOff + c]) + mb[shOff + c];
    }
}

// ---------------- residual gate ----------------
__global__ void resid_gate_kernel(const float* __restrict__ base,
                                  const float* __restrict__ add,
                                  float* __restrict__ out,
                                  const float* __restrict__ m, int gOff,
                                  int rowsPerBatch, long addBatchStride, int addRowOff) {
    int row = blockIdx.x;
    int b = row / rowsPerBatch;
    int r = row - b * rowsPerBatch;
    const float* pb = base + (long)row * Cc;
    const float* pa = add + (long)b * addBatchStride + (long)(addRowOff + r) * Cc;
    float* po = out + (long)row * Cc;
    const float* g = m + b * 6 * Cc + gOff;
#pragma unroll
    for (int i = 0; i < 4; i++) {
        int c = threadIdx.x + 256 * i;
        po[c] = pb[c] + pa[c] * g[c];
    }
}

// ---------------- TF32 GEMM, cp.async 3-stage pipeline ----------------
// A row-major [M,K] -> smem natural [m][k] stride 20 (banks 20g+tig all-distinct)
// B row-major [K,N] -> smem natural [k][n] stride 136 (banks 8tig+g all-distinct)
// 128x128 tile, k-step 16. 8 warps 2Mx4N, 64x32 per warp. No cvt: raw fp32 bits as tf32.
#define GA_ST 20
#define GB_ST 136
#define GA_STG (128 * GA_ST)
#define GB_STG (16 * GB_ST)
#define GEMM_SMEM (int)((3 * GA_STG + 3 * GB_STG) * sizeof(uint32_t))

template<int ACT>
__global__ __launch_bounds__(256, 2)
void mma_gemm(const float* __restrict__ A, const float* __restrict__ B,
              const float* __restrict__ bias, float* __restrict__ C,
              int M, int N, int K) {
    extern __shared__ uint32_t smg[];
    uint32_t* As = smg;                 // [3][128][GA_ST]
    uint32_t* Bs = smg + 3 * GA_STG;    // [3][16][GB_ST]

    int tid  = threadIdx.x;
    int warp = tid >> 5, lane = tid & 31;
    int g    = lane >> 2, tig = lane & 3;
    int warpM = (warp >> 2) * 64;
    int warpN = (warp & 3) * 32;

    const float* Ab = A + (long)blockIdx.y * 128 * K;
    const float* Bb = B + blockIdx.x * 128;

    // cp.async chunk assignment: 512 16B-chunks each for A and B per stage
    int aRow  = tid >> 1;              // 0..127
    int aCol  = (tid & 1) * 8;         // 0 or 8 (two 16B chunks -> 8 floats)
    int bRow  = tid >> 4;              // 0..15
    int bCol  = (tid & 15) * 8;        // two 16B chunks -> 8 floats

    float acc[4][4][4];
#pragma unroll
    for (int i = 0; i < 4; i++)
#pragma unroll
        for (int j = 0; j < 4; j++)
#pragma unroll
            for (int q = 0; q < 4; q++) acc[i][j][q] = 0.f;

    int nstages = K >> 4;

#define GEMM_ISSUE(s) do {                                                     \
        int buf_ = (s) % 3;                                                    \
        int k0_  = (s) << 4;                                                   \
        uint32_t* Ad = As + buf_ * GA_STG;                                     \
        uint32_t* Bd = Bs + buf_ * GB_STG;                                     \
        uint32_t da = (uint32_t)__cvta_generic_to_shared(Ad + aRow * GA_ST + aCol); \
        const float* sa = Ab + (long)aRow * K + k0_ + aCol;                    \
        cp_async16(da, sa);                                                    \
        cp_async16(da + 16, sa + 4);                                           \
        uint32_t db = (uint32_t)__cvta_generic_to_shared(Bd + bRow * GB_ST + bCol); \
        const float* sb = Bb + (long)(k0_ + bRow) * N + bCol;                  \
        cp_async16(db, sb);                                                    \
        cp_async16(db + 16, sb + 4);                                           \
        asm volatile("cp.async.commit_group;\n");                              \
    } while (0)

    GEMM_ISSUE(0);
    GEMM_ISSUE(1);

    for (int s = 0; s < nstages; s++) {
        if (s + 1 < nstages) asm volatile("cp.async.wait_group 1;\n");
        else                 asm volatile("cp.async.wait_group 0;\n");
        __syncthreads();
        if (s + 2 < nstages) GEMM_ISSUE(s + 2);

        uint32_t* Ac = As + (s % 3) * GA_STG;
        uint32_t* Bc = Bs + (s % 3) * GB_STG;
#pragma unroll
        for (int kk = 0; kk < 2; kk++) {
            uint32_t af[4][4], bf[4][2];
#pragma unroll
            for (int mi = 0; mi < 4; mi++) {
                int m = warpM + mi * 16 + g;
                af[mi][0] = Ac[m * GA_ST + kk * 8 + tig];
                af[mi][1] = Ac[(m + 8) * GA_ST + kk * 8 + tig];
                af[mi][2] = Ac[m * GA_ST + kk * 8 + tig + 4];
                af[mi][3] = Ac[(m + 8) * GA_ST + kk * 8 + tig + 4];
            }
#pragma unroll
            for (int ni = 0; ni < 4; ni++) {
                int n = warpN + ni * 8 + g;
                bf[ni][0] = Bc[(kk * 8 + tig) * GB_ST + n];
                bf[ni][1] = Bc[(kk * 8 + tig + 4) * GB_ST + n];
            }
#pragma unroll
            for (int mi = 0; mi < 4; mi++)
#pragma unroll
                for (int ni = 0; ni < 4; ni++)
                    mma_tf32(acc[mi][ni], af[mi], bf[ni]);
        }
    }
#undef GEMM_ISSUE

    int rowBase = blockIdx.y * 128 + warpM;
    int colBase = blockIdx.x * 128 + warpN;
#pragma unroll
    for (int mi = 0; mi < 4; mi++) {
#pragma unroll
        for (int ni = 0; ni < 4; ni++) {
            int r0 = rowBase + mi * 16 + g;
            int c0 = colBase + ni * 8 + tig * 2;
            float b0 = bias[c0], b1 = bias[c0 + 1];
            float* p0 = C + (long)r0 * N + c0;
            float* p1 = C + (long)(r0 + 8) * N + c0;
            p0[0] = act_fn<ACT>(acc[mi][ni][0] + b0);
            p0[1] = act_fn<ACT>(acc[mi][ni][1] + b1);
            p1[0] = act_fn<ACT>(acc[mi][ni][2] + b0);
            p1[1] = act_fn<ACT>(acc[mi][ni][3] + b1);
        }
    }
}

// ---------------- TF32 tensor-core flash attention, BR=128, BC=64 ----------------
// 8 warps: 4 (M, 32 rows) x 2 (N, 32 cols).
// Qt[d][r] stride 136; KVt: K as [d][j], V as [c][d], stride 72; Pt[c][r] stride 136.
#define FQ_ST 136
#define FK_ST 72
#define FA_SMEM (int)((64 * FQ_ST + 64 * FK_ST + 64 * FQ_ST + 3 * 128) * sizeof(uint32_t))
__global__ __launch_bounds__(256, 2)
void flash_tc_kernel(const float* __restrict__ qkv, float* __restrict__ outp) {
    extern __shared__ uint32_t smu[];
    uint32_t* Qt  = smu;                       // [64][FQ_ST] Q^T (pre-scaled)
    uint32_t* KVt = Qt + 64 * FQ_ST;           // [64][FK_ST] K^T tile, then V tile
    uint32_t* Pt  = KVt + 64 * FK_ST;          // [64][FQ_ST] scores^T / probs^T
    float* mrow = (float*)(Pt + 64 * FQ_ST);   // [128]
    float* lrow = mrow + 128;
    float* crow = lrow + 128;

    int bh = blockIdx.y;
    int b = bh >> 4, h = bh & 15;
    int q0 = blockIdx.x * 128;
    int tid = threadIdx.x;
    int lane = tid & 31, warp = tid >> 5;
    int g = lane >> 2, tig = lane & 3;
    int warpM = (warp >> 1) * 32;   // 0,32,64,96
    int warpN = (warp & 1) * 32;    // 0,32

    // load Q transposed + pre-scale, raw bits (lanes span r: conflict-free)
    for (int idx = tid; idx < 2048; idx += 256) {
        int r = idx & 127, dq = idx >> 7;   // dq 0..15
        float4 v = *(const float4*)(qkv + (long)(b * Ss + q0 + r) * (3 * Cc) + h * Dd + dq * 4);
        Qt[(dq * 4 + 0) * FQ_ST + r] = __float_as_uint(v.x * 0.125f);
        Qt[(dq * 4 + 1) * FQ_ST + r] = __float_as_uint(v.y * 0.125f);
        Qt[(dq * 4 + 2) * FQ_ST + r] = __float_as_uint(v.z * 0.125f);
        Qt[(dq * 4 + 3) * FQ_ST + r] = __float_as_uint(v.w * 0.125f);
    }
    if (tid < 128) { mrow[tid] = -1e30f; lrow[tid] = 0.f; }
    __syncthreads();

    float Oc[2][4][4] = {};   // [mi][ni][frag]

    for (int j0 = 0; j0 < Ss; j0 += 64) {
        // ---- K^T tile ----
        for (int idx = tid; idx < 1024; idx += 256) {
            int r = idx & 63, dq = idx >> 6;
            float4 v = *(const float4*)(qkv + (long)(b * Ss + j0 + r) * (3 * Cc) + Cc + h * Dd + dq * 4);
            KVt[(dq * 4 + 0) * FK_ST + r] = __float_as_uint(v.x);
            KVt[(dq * 4 + 1) * FK_ST + r] = __float_as_uint(v.y);
            KVt[(dq * 4 + 2) * FK_ST + r] = __float_as_uint(v.z);
            KVt[(dq * 4 + 3) * FK_ST + r] = __float_as_uint(v.w);
        }
        __syncthreads();

        // ---- S = Q K^T on tensor cores ----
        float Sc[2][4][4];
#pragma unroll
        for (int mi = 0; mi < 2; mi++)
#pragma unroll
            for (int ni = 0; ni < 4; ni++)
#pragma unroll
                for (int q = 0; q < 4; q++) Sc[mi][ni][q] = 0.f;
#pragma unroll
        for (int ks = 0; ks < 8; ks++) {
            uint32_t af[2][4], bf[4][2];
#pragma unroll
            for (int mi = 0; mi < 2; mi++) {
                int m = warpM + mi * 16 + g;
                af[mi][0] = Qt[(ks * 8 + tig) * FQ_ST + m];
                af[mi][1] = Qt[(ks * 8 + tig) * FQ_ST + m + 8];
                af[mi][2] = Qt[(ks * 8 + tig + 4) * FQ_ST + m];
                af[mi][3] = Qt[(ks * 8 + tig + 4) * FQ_ST + m + 8];
            }
#pragma unroll
            for (int ni = 0; ni < 4; ni++) {
                int n = warpN + ni * 8 + g;
                bf[ni][0] = KVt[(ks * 8 + tig) * FK_ST + n];
                bf[ni][1] = KVt[(ks * 8 + tig + 4) * FK_ST + n];
            }
#pragma unroll
            for (int mi = 0; mi < 2; mi++)
#pragma unroll
                for (int ni = 0; ni < 4; ni++)
                    mma_tf32(Sc[mi][ni], af[mi], bf[ni]);
        }
        // store S^T into Pt (raw float bits)
#pragma unroll
        for (int mi = 0; mi < 2; mi++) {
            int m0 = warpM + mi * 16 + g;
#pragma unroll
            for (int ni = 0; ni < 4; ni++) {
                int n0 = warpN + ni * 8 + tig * 2;
                Pt[n0 * FQ_ST + m0]           = __float_as_uint(Sc[mi][ni][0]);
                Pt[(n0 + 1) * FQ_ST + m0]     = __float_as_uint(Sc[mi][ni][1]);
                Pt[n0 * FQ_ST + m0 + 8]       = __float_as_uint(Sc[mi][ni][2]);
                Pt[(n0 + 1) * FQ_ST + m0 + 8] = __float_as_uint(Sc[mi][ni][3]);
            }
        }
        __syncthreads();

        // ---- online softmax (2 threads per row, 32 cols each) on Pt[c][r] ----
        {
            int r = tid >> 1, q = tid & 1;
            float pv[32];
            float tm = -1e30f;
#pragma unroll
            for (int i = 0; i < 32; i++) {
                pv[i] = __uint_as_float(Pt[(q * 32 + i) * FQ_ST + r]);
                tm = fmaxf(tm, pv[i]);
            }
            tm = fmaxf(tm, __shfl_xor_sync(0xffffffff, tm, 1));
            float mold = mrow[r];
            tm = fmaxf(tm, mold);
            float ls = 0.f;
#pragma unroll
            for (int i = 0; i < 32; i++) {
                float p = __expf(pv[i] - tm);
                ls += p;
                Pt[(q * 32 + i) * FQ_ST + r] = __float_as_uint(p);
            }
            ls += __shfl_xor_sync(0xffffffff, ls, 1);
            if (q == 0) {
                float corr = __expf(mold - tm);
                crow[r] = corr;
                mrow[r] = tm;
                lrow[r] = lrow[r] * corr + ls;
            }
        }

        // ---- V tile (natural [c][d], raw bits) ----
        for (int idx = tid; idx < 1024; idx += 256) {
            int c = idx >> 4, dq = idx & 15;
            float4 v = *(const float4*)(qkv + (long)(b * Ss + j0 + c) * (3 * Cc)
                                        + 2 * Cc + h * Dd + dq * 4);
            uint4 p = { __float_as_uint(v.x), __float_as_uint(v.y),
                        __float_as_uint(v.z), __float_as_uint(v.w) };
            *(uint4*)&KVt[c * FK_ST + dq * 4] = p;
        }
        __syncthreads();

        // ---- rescale O accumulators ----
#pragma unroll
        for (int mi = 0; mi < 2; mi++) {
            int m0 = warpM + mi * 16 + g;
            float cl = crow[m0], ch = crow[m0 + 8];
#pragma unroll
            for (int ni = 0; ni < 4; ni++) {
                Oc[mi][ni][0] *= cl; Oc[mi][ni][1] *= cl;
                Oc[mi][ni][2] *= ch; Oc[mi][ni][3] *= ch;
            }
        }

        // ---- O += P @ V on tensor cores (k = c) ----
#pragma unroll
        for (int ks = 0; ks < 8; ks++) {
            uint32_t af[2][4], bf[4][2];
#pragma unroll
            for (int mi = 0; mi < 2; mi++) {
                int m = warpM + mi * 16 + g;
                af[mi][0] = Pt[(ks * 8 + tig) * FQ_ST + m];
                af[mi][1] = Pt[(ks * 8 + tig) * FQ_ST + m + 8];
                af[mi][2] = Pt[(ks * 8 + tig + 4) * FQ_ST + m];
                af[mi][3] = Pt[(ks * 8 + tig + 4) * FQ_ST + m + 8];
            }
#pragma unroll
            for (int ni = 0; ni < 4; ni++) {
                int n = warpN + ni * 8 + g;
                bf[ni][0] = KVt[(ks * 8 + tig) * FK_ST + n];
                bf[ni][1] = KVt[(ks * 8 + tig + 4) * FK_ST + n];
            }
#pragma unroll
            for (int mi = 0; mi < 2; mi++)
#pragma unroll
                for (int ni = 0; ni < 4; ni++)
                    mma_tf32(Oc[mi][ni], af[mi], bf[ni]);
        }
        __syncthreads();
    }

    // ---- epilogue: normalize and write ----
#pragma unroll
    for (int mi = 0; mi < 2; mi++) {
        int m0 = warpM + mi * 16 + g;
        float inv0 = 1.f / lrow[m0];
        float inv1 = 1.f / lrow[m0 + 8];
#pragma unroll
        for (int ni = 0; ni < 4; ni++) {
            int n0 = warpN + ni * 8 + tig * 2;
            float2 w0 = { Oc[mi][ni][0] * inv0, Oc[mi][ni][1] * inv0 };
            float2 w1 = { Oc[mi][ni][2] * inv1, Oc[mi][ni][3] * inv1 };
            *(float2*)(outp + (long)(b * Ss + q0 + m0) * Cc + h * Dd + n0)     = w0;
            *(float2*)(outp + (long)(b * Ss + q0 + m0 + 8) * Cc + h * Dd + n0) = w1;
        }
    }
}

// ---------------- launch ----------------
extern "C" void kernel_launch(void* const* d_in, const int* in_sizes, int n_in,
                              void* d_out, int out_size) {
    const float* x       = (const float*)d_in[0];
    const float* mod     = (const float*)d_in[1];
    const float* cond    = (const float*)d_in[2];
    const float* w_adaln = (const float*)d_in[3];
    const float* b_adaln = (const float*)d_in[4];
    const float* w_qkv   = (const float*)d_in[5];
    const float* b_qkv   = (const float*)d_in[6];
    const float* w_proj  = (const float*)d_in[7];
    const float* b_proj  = (const float*)d_in[8];
    const float* w_s1    = (const float*)d_in[9];
    const float* b_s1    = (const float*)d_in[10];
    const float* w_s2    = (const float*)d_in[11];
    const float* b_s2    = (const float*)d_in[12];
    const float* w_d1    = (const float*)d_in[13];
    const float* b_d1    = (const float*)d_in[14];
    const float* w_d2    = (const float*)d_in[15];
    const float* b_d2    = (const float*)d_in[16];

    float* outx = (float*)d_out;                         // [2,2048,1024]
    float* outc = outx + (long)Bz * Nn * Cc;             // [2,256,1024]

    float *gm, *gjoint, *gqkv, *gattn, *ghid;
    cudaGetSymbolAddress((void**)&gm,     g_m);
    cudaGetSymbolAddress((void**)&gjoint, g_joint);
    cudaGetSymbolAddress((void**)&gqkv,   g_qkv);
    cudaGetSymbolAddress((void**)&gattn,  g_attn);
    cudaGetSymbolAddress((void**)&ghid,   g_hidden);

    cudaFuncSetAttribute(flash_tc_kernel, cudaFuncAttributeMaxDynamicSharedMemorySize, FA_SMEM);
    cudaFuncSetAttribute(mma_gemm<0>, cudaFuncAttributeMaxDynamicSharedMemorySize, GEMM_SMEM);
    cudaFuncSetAttribute(mma_gemm<1>, cudaFuncAttributeMaxDynamicSharedMemorySize, GEMM_SMEM);
    cudaFuncSetAttribute(mma_gemm<2>, cudaFuncAttributeMaxDynamicSharedMemorySize, GEMM_SMEM);

    const long SC = (long)Ss * Cc;
    const long NC = (long)Nn * Cc;
    const long TC = (long)Tt * Cc;

    // 1. modulation vectors
    adaln_kernel<<<dim3(24, Bz), 256>>>(mod, w_adaln, b_adaln, gm);

    // 2. LN + msa modulate -> joint [B,S,C]
    ln_mod_kernel<<<Bz * Nn, 256>>>(x,    gjoint, gm, Nn, 0, Cc, SC, 0);
    ln_mod_kernel<<<Bz * Tt, 256>>>(cond, gjoint, gm, Tt, 0, Cc, SC, Nn);

    // 3. qkv = joint @ w_qkv + b  (4608 x 3072 x 1024)
    mma_gemm<0><<<dim3(3072 / 128, (Bz * Ss) / 128), 256, GEMM_SMEM>>>(
        gjoint, w_qkv, b_qkv, gqkv, Bz * Ss, 3 * Cc, Cc);

    // 4. attention (tensor-core flash, BR=128)
    flash_tc_kernel<<<dim3(Ss / 128, Bz * HEADS), 256, FA_SMEM>>>(gqkv, gattn);

    // 5. proj (4608 x 1024 x 1024) -> gjoint (reuse)
    mma_gemm<0><<<dim3(Cc / 128, (Bz * Ss) / 128), 256, GEMM_SMEM>>>(
        gattn, w_proj, b_proj, gjoint, Bz * Ss, Cc, Cc);

    // 6. attn residual with g_msa (offset 2C)
    resid_gate_kernel<<<Bz * Nn, 256>>>(x,    gjoint, outx, gm, 2 * Cc, Nn, SC, 0);
    resid_gate_kernel<<<Bz * Tt, 256>>>(cond, gjoint, outc, gm, 2 * Cc, Tt, SC, Nn);

    // 7. LN + mlp modulate (sh_mlp=3C, sc_mlp=4C)
    float* gx2 = gjoint;                      // [B*N, C]
    float* gc2 = gjoint + (long)Bz * Nn * Cc; // [B*T, C]
    ln_mod_kernel<<<Bz * Nn, 256>>>(outx, gx2, gm, Nn, 3 * Cc, 4 * Cc, NC, 0);
    ln_mod_kernel<<<Bz * Tt, 256>>>(outc, gc2, gm, Tt, 3 * Cc, 4 * Cc, TC, 0);

    // 8. x MLP: gelu(x2@w_s1+b) @ w_s2 + b
    mma_gemm<1><<<dim3(Hh / 128, (Bz * Nn) / 128), 256, GEMM_SMEM>>>(
        gx2, w_s1, b_s1, ghid, Bz * Nn, Hh, Cc);
    mma_gemm<0><<<dim3(Cc / 128, (Bz * Nn) / 128), 256, GEMM_SMEM>>>(
        ghid, w_s2, b_s2, gqkv, Bz * Nn, Cc, Hh);
    resid_gate_kernel<<<Bz * Nn, 256>>>(outx, gqkv, outx, gm, 5 * Cc, Nn, NC, 0);

    // 9. cond MLP: silu(c2@w_d1+b) @ w_d2 + b
    mma_gemm<2><<<dim3(Hh / 128, (Bz * Tt) / 128), 256, GEMM_SMEM>>>(
        gc2, w_d1, b_d1, ghid, Bz * Tt, Hh, Cc);
    mma_gemm<0><<<dim3(Cc / 128, (Bz * Tt) / 128), 256, GEMM_SMEM>>>(
        ghid, w_d2, b_d2, gqkv, Bz * Tt, Cc, Hh);
    resid_gate_kernel<<<Bz * Tt, 256>>>(outc, gqkv, outc, gm, 5 * Cc, Tt, TC, 0);
}

// round 10
// speedup vs baseline: 4.4286x; 1.5321x over previous
#include <cuda_runtime.h>
#include <cuda_fp16.h>
#include <cstdint>

// ---------------- problem constants ----------------
#define Bz   2
#define Nn   2048
#define Tt   256
#define Cc   1024
#define Hh   4096
#define Ss   2304          // N + T
#define HEADS 16
#define Dd   64

// ---------------- scratch (no allocation allowed) ----------------
__device__ float  g_m[Bz * 6 * Cc];                  // adaLN modulation vectors
__device__ float  g_joint[(long)Bz * Ss * Cc];       // proj out (fp32)
__device__ float  g_qkv[(long)Bz * Ss * 3 * Cc];     // qkv (fp32) / mlp out (fp32)
__device__ __half g_wTh[20971520];                   // transposed fp16 weights [N][K]
__device__ __half g_jh[(long)Bz * Ss * Cc];          // fp16: joint / x2,c2
__device__ __half g_ah[(long)Bz * Ss * Cc];          // fp16: attention out
__device__ __half g_hid16[(long)Bz * Nn * Hh];       // fp16: MLP hidden

// offsets into g_wTh (halves)
#define WT_QKV  0L
#define WT_PROJ 3145728L
#define WT_S1   4194304L
#define WT_S2   8388608L
#define WT_D1   12582912L
#define WT_D2   16777216L

// ---------------- activations ----------------
template<int ACT>
__device__ __forceinline__ float act_fn(float x) {
    if (ACT == 1) { // gelu tanh approx
        float x3 = x * x * x;
        return 0.5f * x * (1.f + tanhf(0.7978845608028654f * (x + 0.044715f * x3)));
    }
    if (ACT == 2) { // silu
        return x / (1.f + __expf(-x));
    }
    return x;
}

__device__ __forceinline__ void mma_tf32(float* d,
                                         const uint32_t* a, const uint32_t* b) {
    asm volatile(
        "mma.sync.aligned.m16n8k8.row.col.f32.tf32.tf32.f32 "
        "{%0,%1,%2,%3}, {%4,%5,%6,%7}, {%8,%9}, {%0,%1,%2,%3};\n"
        : "+f"(d[0]), "+f"(d[1]), "+f"(d[2]), "+f"(d[3])
        : "r"(a[0]), "r"(a[1]), "r"(a[2]), "r"(a[3]), "r"(b[0]), "r"(b[1]));
}

__device__ __forceinline__ void mma_f16(float* d,
                                        const uint32_t* a, const uint32_t* b) {
    asm volatile(
        "mma.sync.aligned.m16n8k16.row.col.f32.f16.f16.f32 "
        "{%0,%1,%2,%3}, {%4,%5,%6,%7}, {%8,%9}, {%0,%1,%2,%3};\n"
        : "+f"(d[0]), "+f"(d[1]), "+f"(d[2]), "+f"(d[3])
        : "r"(a[0]), "r"(a[1]), "r"(a[2]), "r"(a[3]), "r"(b[0]), "r"(b[1]));
}

__device__ __forceinline__ void cp_async16(uint32_t smem_dst, const void* gsrc) {
    asm volatile("cp.async.ca.shared.global [%0], [%1], 16;\n"
                 :: "r"(smem_dst), "l"(gsrc));
}

// ---------------- weight transpose + cvt: out[N][K] = (half)in[K][N] ----------------
__global__ void transpose_cvt_kernel(const float* __restrict__ in, __half* __restrict__ out,
                                     int K, int N) {
    __shared__ float t[32][33];
    int n0 = blockIdx.x * 32, k0 = blockIdx.y * 32;
    int tx = threadIdx.x, ty = threadIdx.y;  // (32, 8)
#pragma unroll
    for (int i = 0; i < 32; i += 8)
        t[ty + i][tx] = in[(long)(k0 + ty + i) * N + n0 + tx];
    __syncthreads();
#pragma unroll
    for (int i = 0; i < 32; i += 8)
        out[(long)(n0 + ty + i) * K + k0 + tx] = __float2half(t[tx][ty + i]);
}

// ---------------- adaLN: m = silu(mod) @ w_adaln + b ----------------
__global__ void adaln_kernel(const float* __restrict__ mod,
                             const float* __restrict__ w,
                             const float* __restrict__ bias,
                             float* __restrict__ mout) {
    int b = blockIdx.y;
    int j = blockIdx.x * 256 + threadIdx.x;   // < 6144
    __shared__ float sm[Cc];
    for (int i = threadIdx.x; i < Cc; i += 256) {
        float v = mod[b * Cc + i];
        sm[i] = v / (1.f + __expf(-v));
    }
    __syncthreads();
    float acc = bias[j];
    for (int k = 0; k < Cc; k++) acc += sm[k] * w[(long)k * (6 * Cc) + j];
    mout[b * 6 * Cc + j] = acc;
}

// ---------------- LN + modulate -> fp16 out ----------------
__global__ void ln_mod_h_kernel(const float* __restrict__ in, __half* __restrict__ out,
                                const float* __restrict__ m, int rowsPerBatch,
                                int shOff, int scOff,
                                long outBatchStride, int outRowOff) {
    int row = blockIdx.x;
    int b = row / rowsPerBatch;
    int r = row - b * rowsPerBatch;
    const float* xi = in + (long)row * Cc;
    float v[4]; float s = 0.f, s2 = 0.f;
#pragma unroll
    for (int i = 0; i < 4; i++) {
        v[i] = xi[threadIdx.x + 256 * i];
        s += v[i]; s2 += v[i] * v[i];
    }
    __shared__ float rs[256], rs2[256];
    rs[threadIdx.x] = s; rs2[threadIdx.x] = s2;
    __syncthreads();
    for (int off = 128; off > 0; off >>= 1) {
        if (threadIdx.x < off) {
            rs[threadIdx.x]  += rs[threadIdx.x + off];
            rs2[threadIdx.x] += rs2[threadIdx.x + off];
        }
        __syncthreads();
    }
    float mu   = rs[0] * (1.f / (float)Cc);
    float var  = rs2[0] * (1.f / (float)Cc) - mu * mu;
    float rstd = rsqrtf(var + 1e-6f);
    const float* mb = m + b * 6 * Cc;
    __half* po = out + (long)b * outBatchStride + (long)(outRowOff + r) * Cc;
#pragma unroll
    for (int i = 0; i < 4; i++) {
        int c = threadIdx.x + 256 * i;
        po[c] = __float2half((v[i] - mu) * rstd * (1.f + mb[scOff + c]) + mb[shOff + c]);
    }
}

// ---------------- residual gate (fp32) ----------------
__global__ void resid_gate_kernel(const float* __restrict__ base,
                                  const float* __restrict__ add,
                                  float* __restrict__ out,
                                  const float* __restrict__ m, int gOff,
                                  int rowsPerBatch, long addBatchStride, int addRowOff) {
    int row = blockIdx.x;
    int b = row / rowsPerBatch;
    int r = row - b * rowsPerBatch;
    const float* pb = base + (long)row * Cc;
    const float* pa = add + (long)b * addBatchStride + (long)(addRowOff + r) * Cc;
    float* po = out + (long)row * Cc;
    const float* g = m + b * 6 * Cc + gOff;
#pragma unroll
    for (int i = 0; i < 4; i++) {
        int c = threadIdx.x + 256 * i;
        po[c] = pb[c] + pa[c] * g[c];
    }
}

// ---------------- FP16 tensor-core GEMM: C = act(A @ BT^T + bias) ----------------
// A [M,K] fp16 K-major; BT [N,K] fp16 K-major. 128x128 tile, BK=32 halves.
// smem rows stride 40 halves (20 words): frag words 20g+tig all-distinct (no conflicts).
// 3-stage cp.async. 8 warps 2Mx4N (64x32/warp). m16n8k16 fp16->fp32.
#define GH_ST 20                       // words per smem row
#define GH_STG (128 * GH_ST)           // words per tile buffer
#define GEMMH_SMEM (6 * GH_STG * 4)    // bytes (61440)

template<int ACT, int HOUT>
__global__ __launch_bounds__(256, 2)
void gemm_h(const __half* __restrict__ A, const __half* __restrict__ BT,
            const float* __restrict__ bias, void* __restrict__ Cv,
            int M, int N, int K) {
    extern __shared__ uint32_t smg[];
    uint32_t* As = smg;                 // [3][128][20]
    uint32_t* Bs = smg + 3 * GH_STG;    // [3][128][20]

    int tid  = threadIdx.x;
    int warp = tid >> 5, lane = tid & 31;
    int g    = lane >> 2, tig = lane & 3;
    int warpM = (warp >> 2) * 64;
    int warpN = (warp & 3) * 32;

    const __half* Ab = A  + (long)blockIdx.y * 128 * K;
    const __half* Bb = BT + (long)blockIdx.x * 128 * K;

    float acc[4][4][4];
#pragma unroll
    for (int i = 0; i < 4; i++)
#pragma unroll
        for (int j = 0; j < 4; j++)
#pragma unroll
            for (int q = 0; q < 4; q++) acc[i][j][q] = 0.f;

    int nstages = K >> 5;

#define GH_FILL(s) do {                                                        \
        int buf_ = (s) % 3;                                                    \
        int k0_  = (s) << 5;                                                   \
        uint32_t* Ad = As + buf_ * GH_STG;                                     \
        uint32_t* Bd = Bs + buf_ * GH_STG;                                     \
        _Pragma("unroll")                                                      \
        for (int i_ = 0; i_ < 2; i_++) {                                       \
            int c_ = tid + i_ * 256;           /* 0..511 */                    \
            int r_ = c_ >> 2, kc_ = c_ & 3;                                    \
            uint32_t da_ = (uint32_t)__cvta_generic_to_shared(Ad + r_ * GH_ST + kc_ * 4); \
            cp_async16(da_, Ab + (long)r_ * K + k0_ + kc_ * 8);                \
            uint32_t db_ = (uint32_t)__cvta_generic_to_shared(Bd + r_ * GH_ST + kc_ * 4); \
            cp_async16(db_, Bb + (long)r_ * K + k0_ + kc_ * 8);                \
        }                                                                      \
        asm volatile("cp.async.commit_group;\n");                              \
    } while (0)

    GH_FILL(0);
    GH_FILL(1);

    for (int s = 0; s < nstages; s++) {
        if (s + 1 < nstages) asm volatile("cp.async.wait_group 1;\n");
        else                 asm volatile("cp.async.wait_group 0;\n");
        __syncthreads();
        if (s + 2 < nstages) GH_FILL(s + 2);

        uint32_t* Ac = As + (s % 3) * GH_STG;
        uint32_t* Bc = Bs + (s % 3) * GH_STG;
#pragma unroll
        for (int kk = 0; kk < 2; kk++) {     // two k16 chunks per BK=32
            uint32_t af[4][4], bf[4][2];
#pragma unroll
            for (int mi = 0; mi < 4; mi++) {
                int m = warpM + mi * 16 + g;
                af[mi][0] = Ac[m * GH_ST + kk * 8 + tig];
                af[mi][1] = Ac[(m + 8) * GH_ST + kk * 8 + tig];
                af[mi][2] = Ac[m * GH_ST + kk * 8 + 4 + tig];
                af[mi][3] = Ac[(m + 8) * GH_ST + kk * 8 + 4 + tig];
            }
#pragma unroll
            for (int ni = 0; ni < 4; ni++) {
                int n = warpN + ni * 8 + g;
                bf[ni][0] = Bc[n * GH_ST + kk * 8 + tig];
                bf[ni][1] = Bc[n * GH_ST + kk * 8 + 4 + tig];
            }
#pragma unroll
            for (int mi = 0; mi < 4; mi++)
#pragma unroll
                for (int ni = 0; ni < 4; ni++)
                    mma_f16(acc[mi][ni], af[mi], bf[ni]);
        }
    }
#undef GH_FILL

    int rowBase = blockIdx.y * 128 + warpM;
    int colBase = blockIdx.x * 128 + warpN;
#pragma unroll
    for (int mi = 0; mi < 4; mi++) {
#pragma unroll
        for (int ni = 0; ni < 4; ni++) {
            int r0 = rowBase + mi * 16 + g;
            int c0 = colBase + ni * 8 + tig * 2;
            float b0 = bias[c0], b1 = bias[c0 + 1];
            float v00 = act_fn<ACT>(acc[mi][ni][0] + b0);
            float v01 = act_fn<ACT>(acc[mi][ni][1] + b1);
            float v10 = act_fn<ACT>(acc[mi][ni][2] + b0);
            float v11 = act_fn<ACT>(acc[mi][ni][3] + b1);
            if (HOUT) {
                __half* C = (__half*)Cv;
                *(__half2*)(C + (long)r0 * N + c0)       = __floats2half2_rn(v00, v01);
                *(__half2*)(C + (long)(r0 + 8) * N + c0) = __floats2half2_rn(v10, v11);
            } else {
                float* C = (float*)Cv;
                float2 w0 = { v00, v01 }, w1 = { v10, v11 };
                *(float2*)(C + (long)r0 * N + c0)       = w0;
                *(float2*)(C + (long)(r0 + 8) * N + c0) = w1;
            }
        }
    }
}

// ---------------- TF32 tensor-core flash attention, BR=128, BC=64 ----------------
// (validated R8; epilogue now writes fp16 for the proj GEMM input)
#define FQ_ST 136
#define FK_ST 72
#define FA_SMEM (int)((64 * FQ_ST + 64 * FK_ST + 64 * FQ_ST + 3 * 128) * sizeof(uint32_t))
__global__ __launch_bounds__(256, 2)
void flash_tc_kernel(const float* __restrict__ qkv, __half* __restrict__ outp) {
    extern __shared__ uint32_t smu[];
    uint32_t* Qt  = smu;                       // [64][FQ_ST] Q^T (pre-scaled)
    uint32_t* KVt = Qt + 64 * FQ_ST;           // [64][FK_ST] K^T tile, then V tile
    uint32_t* Pt  = KVt + 64 * FK_ST;          // [64][FQ_ST] scores^T / probs^T
    float* mrow = (float*)(Pt + 64 * FQ_ST);   // [128]
    float* lrow = mrow + 128;
    float* crow = lrow + 128;

    int bh = blockIdx.y;
    int b = bh >> 4, h = bh & 15;
    int q0 = blockIdx.x * 128;
    int tid = threadIdx.x;
    int lane = tid & 31, warp = tid >> 5;
    int g = lane >> 2, tig = lane & 3;
    int warpM = (warp >> 1) * 32;   // 0,32,64,96
    int warpN = (warp & 1) * 32;    // 0,32

    for (int idx = tid; idx < 2048; idx += 256) {
        int r = idx & 127, dq = idx >> 7;   // dq 0..15
        float4 v = *(const float4*)(qkv + (long)(b * Ss + q0 + r) * (3 * Cc) + h * Dd + dq * 4);
        Qt[(dq * 4 + 0) * FQ_ST + r] = __float_as_uint(v.x * 0.125f);
        Qt[(dq * 4 + 1) * FQ_ST + r] = __float_as_uint(v.y * 0.125f);
        Qt[(dq * 4 + 2) * FQ_ST + r] = __float_as_uint(v.z * 0.125f);
        Qt[(dq * 4 + 3) * FQ_ST + r] = __float_as_uint(v.w * 0.125f);
    }
    if (tid < 128) { mrow[tid] = -1e30f; lrow[tid] = 0.f; }
    __syncthreads();

    float Oc[2][4][4] = {};   // [mi][ni][frag]

    for (int j0 = 0; j0 < Ss; j0 += 64) {
        // ---- K^T tile ----
        for (int idx = tid; idx < 1024; idx += 256) {
            int r = idx & 63, dq = idx >> 6;
            float4 v = *(const float4*)(qkv + (long)(b * Ss + j0 + r) * (3 * Cc) + Cc + h * Dd + dq * 4);
            KVt[(dq * 4 + 0) * FK_ST + r] = __float_as_uint(v.x);
            KVt[(dq * 4 + 1) * FK_ST + r] = __float_as_uint(v.y);
            KVt[(dq * 4 + 2) * FK_ST + r] = __float_as_uint(v.z);
            KVt[(dq * 4 + 3) * FK_ST + r] = __float_as_uint(v.w);
        }
        __syncthreads();

        // ---- S = Q K^T ----
        float Sc[2][4][4];
#pragma unroll
        for (int mi = 0; mi < 2; mi++)
#pragma unroll
            for (int ni = 0; ni < 4; ni++)
#pragma unroll
                for (int q = 0; q < 4; q++) Sc[mi][ni][q] = 0.f;
#pragma unroll
        for (int ks = 0; ks < 8; ks++) {
            uint32_t af[2][4], bf[4][2];
#pragma unroll
            for (int mi = 0; mi < 2; mi++) {
                int m = warpM + mi * 16 + g;
                af[mi][0] = Qt[(ks * 8 + tig) * FQ_ST + m];
                af[mi][1] = Qt[(ks * 8 + tig) * FQ_ST + m + 8];
                af[mi][2] = Qt[(ks * 8 + tig + 4) * FQ_ST + m];
                af[mi][3] = Qt[(ks * 8 + tig + 4) * FQ_ST + m + 8];
            }
#pragma unroll
            for (int ni = 0; ni < 4; ni++) {
                int n = warpN + ni * 8 + g;
                bf[ni][0] = KVt[(ks * 8 + tig) * FK_ST + n];
                bf[ni][1] = KVt[(ks * 8 + tig + 4) * FK_ST + n];
            }
#pragma unroll
            for (int mi = 0; mi < 2; mi++)
#pragma unroll
                for (int ni = 0; ni < 4; ni++)
                    mma_tf32(Sc[mi][ni], af[mi], bf[ni]);
        }
#pragma unroll
        for (int mi = 0; mi < 2; mi++) {
            int m0 = warpM + mi * 16 + g;
#pragma unroll
            for (int ni = 0; ni < 4; ni++) {
                int n0 = warpN + ni * 8 + tig * 2;
                Pt[n0 * FQ_ST + m0]           = __float_as_uint(Sc[mi][ni][0]);
                Pt[(n0 + 1) * FQ_ST + m0]     = __float_as_uint(Sc[mi][ni][1]);
                Pt[n0 * FQ_ST + m0 + 8]       = __float_as_uint(Sc[mi][ni][2]);
                Pt[(n0 + 1) * FQ_ST + m0 + 8] = __float_as_uint(Sc[mi][ni][3]);
            }
        }
        __syncthreads();

        // ---- online softmax (2 threads per row) ----
        {
            int r = tid >> 1, q = tid & 1;
            float pv[32];
            float tm = -1e30f;
#pragma unroll
            for (int i = 0; i < 32; i++) {
                pv[i] = __uint_as_float(Pt[(q * 32 + i) * FQ_ST + r]);
                tm = fmaxf(tm, pv[i]);
            }
            tm = fmaxf(tm, __shfl_xor_sync(0xffffffff, tm, 1));
            float mold = mrow[r];
            tm = fmaxf(tm, mold);
            float ls = 0.f;
#pragma unroll
            for (int i = 0; i < 32; i++) {
                float p = __expf(pv[i] - tm);
                ls += p;
                Pt[(q * 32 + i) * FQ_ST + r] = __float_as_uint(p);
            }
            ls += __shfl_xor_sync(0xffffffff, ls, 1);
            if (q == 0) {
                float corr = __expf(mold - tm);
                crow[r] = corr;
                mrow[r] = tm;
                lrow[r] = lrow[r] * corr + ls;
            }
        }

        // ---- V tile ----
        for (int idx = tid; idx < 1024; idx += 256) {
            int c = idx >> 4, dq = idx & 15;
            float4 v = *(const float4*)(qkv + (long)(b * Ss + j0 + c) * (3 * Cc)
                                        + 2 * Cc + h * Dd + dq * 4);
            uint4 p = { __float_as_uint(v.x), __float_as_uint(v.y),
                        __float_as_uint(v.z), __float_as_uint(v.w) };
            *(uint4*)&KVt[c * FK_ST + dq * 4] = p;
        }
        __syncthreads();

        // ---- rescale O ----
#pragma unroll
        for (int mi = 0; mi < 2; mi++) {
            int m0 = warpM + mi * 16 + g;
            float cl = crow[m0], ch = crow[m0 + 8];
#pragma unroll
            for (int ni = 0; ni < 4; ni++) {
                Oc[mi][ni][0] *= cl; Oc[mi][ni][1] *= cl;
                Oc[mi][ni][2] *= ch; Oc[mi][ni][3] *= ch;
            }
        }

        // ---- O += P @ V ----
#pragma unroll
        for (int ks = 0; ks < 8; ks++) {
            uint32_t af[2][4], bf[4][2];
#pragma unroll
            for (int mi = 0; mi < 2; mi++) {
                int m = warpM + mi * 16 + g;
                af[mi][0] = Pt[(ks * 8 + tig) * FQ_ST + m];
                af[mi][1] = Pt[(ks * 8 + tig) * FQ_ST + m + 8];
                af[mi][2] = Pt[(ks * 8 + tig + 4) * FQ_ST + m];
                af[mi][3] = Pt[(ks * 8 + tig + 4) * FQ_ST + m + 8];
            }
#pragma unroll
            for (int ni = 0; ni < 4; ni++) {
                int n = warpN + ni * 8 + g;
                bf[ni][0] = KVt[(ks * 8 + tig) * FK_ST + n];
                bf[ni][1] = KVt[(ks * 8 + tig + 4) * FK_ST + n];
            }
#pragma unroll
            for (int mi = 0; mi < 2; mi++)
#pragma unroll
                for (int ni = 0; ni < 4; ni++)
                    mma_tf32(Oc[mi][ni], af[mi], bf[ni]);
        }
        __syncthreads();
    }

    // ---- epilogue: normalize, write fp16 ----
#pragma unroll
    for (int mi = 0; mi < 2; mi++) {
        int m0 = warpM + mi * 16 + g;
        float inv0 = 1.f / lrow[m0];
        float inv1 = 1.f / lrow[m0 + 8];
#pragma unroll
        for (int ni = 0; ni < 4; ni++) {
            int n0 = warpN + ni * 8 + tig * 2;
            *(__half2*)(outp + (long)(b * Ss + q0 + m0) * Cc + h * Dd + n0) =
                __floats2half2_rn(Oc[mi][ni][0] * inv0, Oc[mi][ni][1] * inv0);
            *(__half2*)(outp + (long)(b * Ss + q0 + m0 + 8) * Cc + h * Dd + n0) =
                __floats2half2_rn(Oc[mi][ni][2] * inv1, Oc[mi][ni][3] * inv1);
        }
    }
}

// ---------------- launch ----------------
extern "C" void kernel_launch(void* const* d_in, const int* in_sizes, int n_in,
                              void* d_out, int out_size) {
    const float* x       = (const float*)d_in[0];
    const float* mod     = (const float*)d_in[1];
    const float* cond    = (const float*)d_in[2];
    const float* w_adaln = (const float*)d_in[3];
    const float* b_adaln = (const float*)d_in[4];
    const float* w_qkv   = (const float*)d_in[5];
    const float* b_qkv   = (const float*)d_in[6];
    const float* w_proj  = (const float*)d_in[7];
    const float* b_proj  = (const float*)d_in[8];
    const float* w_s1    = (const float*)d_in[9];
    const float* b_s1    = (const float*)d_in[10];
    const float* w_s2    = (const float*)d_in[11];
    const float* b_s2    = (const float*)d_in[12];
    const float* w_d1    = (const float*)d_in[13];
    const float* b_d1    = (const float*)d_in[14];
    const float* w_d2    = (const float*)d_in[15];
    const float* b_d2    = (const float*)d_in[16];

    float* outx = (float*)d_out;                         // [2,2048,1024]
    float* outc = outx + (long)Bz * Nn * Cc;             // [2,256,1024]

    float *gm, *gjoint, *gqkv;
    __half *gwth, *gjh, *gah, *ghid;
    cudaGetSymbolAddress((void**)&gm,     g_m);
    cudaGetSymbolAddress((void**)&gjoint, g_joint);
    cudaGetSymbolAddress((void**)&gqkv,   g_qkv);
    cudaGetSymbolAddress((void**)&gwth,   g_wTh);
    cudaGetSymbolAddress((void**)&gjh,    g_jh);
    cudaGetSymbolAddress((void**)&gah,    g_ah);
    cudaGetSymbolAddress((void**)&ghid,   g_hid16);

    cudaFuncSetAttribute(flash_tc_kernel, cudaFuncAttributeMaxDynamicSharedMemorySize, FA_SMEM);
    cudaFuncSetAttribute(gemm_h<0,0>, cudaFuncAttributeMaxDynamicSharedMemorySize, GEMMH_SMEM);
    cudaFuncSetAttribute(gemm_h<1,1>, cudaFuncAttributeMaxDynamicSharedMemorySize, GEMMH_SMEM);
    cudaFuncSetAttribute(gemm_h<2,1>, cudaFuncAttributeMaxDynamicSharedMemorySize, GEMMH_SMEM);

    const long SC = (long)Ss * Cc;
    const long NC = (long)Nn * Cc;
    const long TC = (long)Tt * Cc;

    // 0. weight transposes + fp16 cvt into g_wTh ([N][K] K-major)
    dim3 tb(32, 8);
    transpose_cvt_kernel<<<dim3(3 * Cc / 32, Cc / 32), tb>>>(w_qkv,  gwth + WT_QKV,  Cc, 3 * Cc);
    transpose_cvt_kernel<<<dim3(Cc / 32, Cc / 32),     tb>>>(w_proj, gwth + WT_PROJ, Cc, Cc);
    transpose_cvt_kernel<<<dim3(Hh / 32, Cc / 32),     tb>>>(w_s1,   gwth + WT_S1,   Cc, Hh);
    transpose_cvt_kernel<<<dim3(Cc / 32, Hh / 32),     tb>>>(w_s2,   gwth + WT_S2,   Hh, Cc);
    transpose_cvt_kernel<<<dim3(Hh / 32, Cc / 32),     tb>>>(w_d1,   gwth + WT_D1,   Cc, Hh);
    transpose_cvt_kernel<<<dim3(Cc / 32, Hh / 32),     tb>>>(w_d2,   gwth + WT_D2,   Hh, Cc);

    // 1. modulation vectors
    adaln_kernel<<<dim3(24, Bz), 256>>>(mod, w_adaln, b_adaln, gm);

    // 2. LN + msa modulate -> joint fp16 [B,S,C]
    ln_mod_h_kernel<<<Bz * Nn, 256>>>(x,    gjh, gm, Nn, 0, Cc, SC, 0);
    ln_mod_h_kernel<<<Bz * Tt, 256>>>(cond, gjh, gm, Tt, 0, Cc, SC, Nn);

    // 3. qkv = joint @ w_qkv + b  (4608 x 3072 x 1024), fp32 out
    gemm_h<0,0><<<dim3(3072 / 128, (Bz * Ss) / 128), 256, GEMMH_SMEM>>>(
        gjh, gwth + WT_QKV, b_qkv, gqkv, Bz * Ss, 3 * Cc, Cc);

    // 4. attention (tf32 flash, BR=128) -> fp16 attn
    flash_tc_kernel<<<dim3(Ss / 128, Bz * HEADS), 256, FA_SMEM>>>(gqkv, gah);

    // 5. proj (4608 x 1024 x 1024) -> fp32 gjoint
    gemm_h<0,0><<<dim3(Cc / 128, (Bz * Ss) / 128), 256, GEMMH_SMEM>>>(
        gah, gwth + WT_PROJ, b_proj, gjoint, Bz * Ss, Cc, Cc);

    // 6. attn residual with g_msa (offset 2C)
    resid_gate_kernel<<<Bz * Nn, 256>>>(x,    gjoint, outx, gm, 2 * Cc, Nn, SC, 0);
    resid_gate_kernel<<<Bz * Tt, 256>>>(cond, gjoint, outc, gm, 2 * Cc, Tt, SC, Nn);

    // 7. LN + mlp modulate -> fp16 x2/c2
    __half* gx2 = gjh;                        // [B*N, C]
    __half* gc2 = gjh + (long)Bz * Nn * Cc;   // [B*T, C]
    ln_mod_h_kernel<<<Bz * Nn, 256>>>(outx, gx2, gm, Nn, 3 * Cc, 4 * Cc, NC, 0);
    ln_mod_h_kernel<<<Bz * Tt, 256>>>(outc, gc2, gm, Tt, 3 * Cc, 4 * Cc, TC, 0);

    // 8. x MLP: gelu(x2@w_s1+b) @ w_s2 + b
    gemm_h<1,1><<<dim3(Hh / 128, (Bz * Nn) / 128), 256, GEMMH_SMEM>>>(
        gx2, gwth + WT_S1, b_s1, ghid, Bz * Nn, Hh, Cc);
    gemm_h<0,0><<<dim3(Cc / 128, (Bz * Nn) / 128), 256, GEMMH_SMEM>>>(
        ghid, gwth + WT_S2, b_s2, gqkv, Bz * Nn, Cc, Hh);
    resid_gate_kernel<<<Bz * Nn, 256>>>(outx, gqkv, outx, gm, 5 * Cc, Nn, NC, 0);

    // 9. cond MLP: silu(c2@w_d1+b) @ w_d2 + b
    gemm_h<2,1><<<dim3(Hh / 128, (Bz * Tt) / 128), 256, GEMMH_SMEM>>>(
        gc2, gwth + WT_D1, b_d1, ghid, Bz * Tt, Hh, Cc);
    gemm_h<0,0><<<dim3(Cc / 128, (Bz * Tt) / 128), 256, GEMMH_SMEM>>>(
        ghid, gwth + WT_D2, b_d2, gqkv, Bz * Tt, Cc, Hh);
    resid_gate_kernel<<<Bz * Tt, 256>>>(outc, gqkv, outc, gm, 5 * Cc, Tt, TC, 0);
}

// round 12
// speedup vs baseline: 5.1325x; 1.1589x over previous
#include <cuda_runtime.h>
#include <cuda_fp16.h>
#include <cstdint>

// ---------------- problem constants ----------------
#define Bz   2
#define Nn   2048
#define Tt   256
#define Cc   1024
#define Hh   4096
#define Ss   2304          // N + T
#define HEADS 16
#define Dd   64

// ---------------- scratch (no allocation allowed) ----------------
__device__ float  g_m[Bz * 6 * Cc];                  // adaLN modulation vectors
__device__ float  g_joint[(long)Bz * Ss * Cc];       // proj out (fp32)
__device__ float  g_qkv[(long)Bz * Ss * 3 * Cc];     // mlp out (fp32)
__device__ __half g_qkvh[(long)Bz * Ss * 3 * Cc];    // qkv (fp16)
__device__ __half g_wTh[20971520];                   // transposed fp16 weights [N][K]
__device__ __half g_jh[(long)Bz * Ss * Cc];          // fp16: joint / x2,c2
__device__ __half g_ah[(long)Bz * Ss * Cc];          // fp16: attention out
__device__ __half g_hid16[(long)Bz * Nn * Hh];       // fp16: MLP hidden

// offsets into g_wTh (halves)
#define WT_QKV  0L
#define WT_PROJ 3145728L
#define WT_S1   4194304L
#define WT_S2   8388608L
#define WT_D1   12582912L
#define WT_D2   16777216L

// ---------------- activations ----------------
template<int ACT>
__device__ __forceinline__ float act_fn(float x) {
    if (ACT == 1) { // gelu tanh approx
        float x3 = x * x * x;
        return 0.5f * x * (1.f + tanhf(0.7978845608028654f * (x + 0.044715f * x3)));
    }
    if (ACT == 2) { // silu
        return x / (1.f + __expf(-x));
    }
    return x;
}

__device__ __forceinline__ void mma_f16(float* d,
                                        const uint32_t* a, const uint32_t* b) {
    asm volatile(
        "mma.sync.aligned.m16n8k16.row.col.f32.f16.f16.f32 "
        "{%0,%1,%2,%3}, {%4,%5,%6,%7}, {%8,%9}, {%0,%1,%2,%3};\n"
        : "+f"(d[0]), "+f"(d[1]), "+f"(d[2]), "+f"(d[3])
        : "r"(a[0]), "r"(a[1]), "r"(a[2]), "r"(a[3]), "r"(b[0]), "r"(b[1]));
}

__device__ __forceinline__ void cp_async16(uint32_t smem_dst, const void* gsrc) {
    asm volatile("cp.async.ca.shared.global [%0], [%1], 16;\n"
                 :: "r"(smem_dst), "l"(gsrc));
}

// ---------------- weight transpose + cvt: out[N][K] = (half)in[K][N] ----------------
__global__ void transpose_cvt_kernel(const float* __restrict__ in, __half* __restrict__ out,
                                     int K, int N) {
    __shared__ float t[32][33];
    int n0 = blockIdx.x * 32, k0 = blockIdx.y * 32;
    int tx = threadIdx.x, ty = threadIdx.y;  // (32, 8)
#pragma unroll
    for (int i = 0; i < 32; i += 8)
        t[ty + i][tx] = in[(long)(k0 + ty + i) * N + n0 + tx];
    __syncthreads();
#pragma unroll
    for (int i = 0; i < 32; i += 8)
        out[(long)(n0 + ty + i) * K + k0 + tx] = __float2half(t[tx][ty + i]);
}

// ---------------- adaLN: m = silu(mod) @ w_adaln + b ----------------
__global__ void adaln_kernel(const float* __restrict__ mod,
                             const float* __restrict__ w,
                             const float* __restrict__ bias,
                             float* __restrict__ mout) {
    int b = blockIdx.y;
    int j = blockIdx.x * 256 + threadIdx.x;   // < 6144
    __shared__ float sm[Cc];
    for (int i = threadIdx.x; i < Cc; i += 256) {
        float v = mod[b * Cc + i];
        sm[i] = v / (1.f + __expf(-v));
    }
    __syncthreads();
    float acc = bias[j];
    for (int k = 0; k < Cc; k++) acc += sm[k] * w[(long)k * (6 * Cc) + j];
    mout[b * 6 * Cc + j] = acc;
}

// ---------------- LN + modulate -> fp16 out ----------------
__global__ void ln_mod_h_kernel(const float* __restrict__ in, __half* __restrict__ out,
                                const float* __restrict__ m, int rowsPerBatch,
                                int shOff, int scOff,
                                long outBatchStride, int outRowOff) {
    int row = blockIdx.x;
    int b = row / rowsPerBatch;
    int r = row - b * rowsPerBatch;
    const float* xi = in + (long)row * Cc;
    float v[4]; float s = 0.f, s2 = 0.f;
#pragma unroll
    for (int i = 0; i < 4; i++) {
        v[i] = xi[threadIdx.x + 256 * i];
        s += v[i]; s2 += v[i] * v[i];
    }
    __shared__ float rs[256], rs2[256];
    rs[threadIdx.x] = s; rs2[threadIdx.x] = s2;
    __syncthreads();
    for (int off = 128; off > 0; off >>= 1) {
        if (threadIdx.x < off) {
            rs[threadIdx.x]  += rs[threadIdx.x + off];
            rs2[threadIdx.x] += rs2[threadIdx.x + off];
        }
        __syncthreads();
    }
    float mu   = rs[0] * (1.f / (float)Cc);
    float var  = rs2[0] * (1.f / (float)Cc) - mu * mu;
    float rstd = rsqrtf(var + 1e-6f);
    const float* mb = m + b * 6 * Cc;
    __half* po = out + (long)b * outBatchStride + (long)(outRowOff + r) * Cc;
#pragma unroll
    for (int i = 0; i < 4; i++) {
        int c = threadIdx.x + 256 * i;
        po[c] = __float2half((v[i] - mu) * rstd * (1.f + mb[scOff + c]) + mb[shOff + c]);
    }
}

// ---------------- residual gate (fp32) ----------------
__global__ void resid_gate_kernel(const float* __restrict__ base,
                                  const float* __restrict__ add,
                                  float* __restrict__ out,
                                  const float* __restrict__ m, int gOff,
                                  int rowsPerBatch, long addBatchStride, int addRowOff) {
    int row = blockIdx.x;
    int b = row / rowsPerBatch;
    int r = row - b * rowsPerBatch;
    const float* pb = base + (long)row * Cc;
    const float* pa = add + (long)b * addBatchStride + (long)(addRowOff + r) * Cc;
    float* po = out + (long)row * Cc;
    const float* g = m + b * 6 * Cc + gOff;
#pragma unroll
    for (int i = 0; i < 4; i++) {
        int c = threadIdx.x + 256 * i;
        po[c] = pb[c] + pa[c] * g[c];
    }
}

// ---------------- FP16 tensor-core GEMM (validated R10) ----------------
#define GH_ST 20
#define GH_STG (128 * GH_ST)
#define GEMMH_SMEM (6 * GH_STG * 4)

template<int ACT, int HOUT>
__global__ __launch_bounds__(256, 2)
void gemm_h(const __half* __restrict__ A, const __half* __restrict__ BT,
            const float* __restrict__ bias, void* __restrict__ Cv,
            int M, int N, int K) {
    extern __shared__ uint32_t smg[];
    uint32_t* As = smg;                 // [3][128][20]
    uint32_t* Bs = smg + 3 * GH_STG;    // [3][128][20]

    int tid  = threadIdx.x;
    int warp = tid >> 5, lane = tid & 31;
    int g    = lane >> 2, tig = lane & 3;
    int warpM = (warp >> 2) * 64;
    int warpN = (warp & 3) * 32;

    const __half* Ab = A  + (long)blockIdx.y * 128 * K;
    const __half* Bb = BT + (long)blockIdx.x * 128 * K;

    float acc[4][4][4];
#pragma unroll
    for (int i = 0; i < 4; i++)
#pragma unroll
        for (int j = 0; j < 4; j++)
#pragma unroll
            for (int q = 0; q < 4; q++) acc[i][j][q] = 0.f;

    int nstages = K >> 5;

#define GH_FILL(s) do {                                                        \
        int buf_ = (s) % 3;                                                    \
        int k0_  = (s) << 5;                                                   \
        uint32_t* Ad = As + buf_ * GH_STG;                                     \
        uint32_t* Bd = Bs + buf_ * GH_STG;                                     \
        _Pragma("unroll")                                                      \
        for (int i_ = 0; i_ < 2; i_++) {                                       \
            int c_ = tid + i_ * 256;           /* 0..511 */                    \
            int r_ = c_ >> 2, kc_ = c_ & 3;                                    \
            uint32_t da_ = (uint32_t)__cvta_generic_to_shared(Ad + r_ * GH_ST + kc_ * 4); \
            cp_async16(da_, Ab + (long)r_ * K + k0_ + kc_ * 8);                \
            uint32_t db_ = (uint32_t)__cvta_generic_to_shared(Bd + r_ * GH_ST + kc_ * 4); \
            cp_async16(db_, Bb + (long)r_ * K + k0_ + kc_ * 8);                \
        }                                                                      \
        asm volatile("cp.async.commit_group;\n");                              \
    } while (0)

    GH_FILL(0);
    GH_FILL(1);

    for (int s = 0; s < nstages; s++) {
        if (s + 1 < nstages) asm volatile("cp.async.wait_group 1;\n");
        else                 asm volatile("cp.async.wait_group 0;\n");
        __syncthreads();
        if (s + 2 < nstages) GH_FILL(s + 2);

        uint32_t* Ac = As + (s % 3) * GH_STG;
        uint32_t* Bc = Bs + (s % 3) * GH_STG;
#pragma unroll
        for (int kk = 0; kk < 2; kk++) {
            uint32_t af[4][4], bf[4][2];
#pragma unroll
            for (int mi = 0; mi < 4; mi++) {
                int m = warpM + mi * 16 + g;
                af[mi][0] = Ac[m * GH_ST + kk * 8 + tig];
                af[mi][1] = Ac[(m + 8) * GH_ST + kk * 8 + tig];
                af[mi][2] = Ac[m * GH_ST + kk * 8 + 4 + tig];
                af[mi][3] = Ac[(m + 8) * GH_ST + kk * 8 + 4 + tig];
            }
#pragma unroll
            for (int ni = 0; ni < 4; ni++) {
                int n = warpN + ni * 8 + g;
                bf[ni][0] = Bc[n * GH_ST + kk * 8 + tig];
                bf[ni][1] = Bc[n * GH_ST + kk * 8 + 4 + tig];
            }
#pragma unroll
            for (int mi = 0; mi < 4; mi++)
#pragma unroll
                for (int ni = 0; ni < 4; ni++)
                    mma_f16(acc[mi][ni], af[mi], bf[ni]);
        }
    }
#undef GH_FILL

    int rowBase = blockIdx.y * 128 + warpM;
    int colBase = blockIdx.x * 128 + warpN;
#pragma unroll
    for (int mi = 0; mi < 4; mi++) {
#pragma unroll
        for (int ni = 0; ni < 4; ni++) {
            int r0 = rowBase + mi * 16 + g;
            int c0 = colBase + ni * 8 + tig * 2;
            float b0 = bias[c0], b1 = bias[c0 + 1];
            float v00 = act_fn<ACT>(acc[mi][ni][0] + b0);
            float v01 = act_fn<ACT>(acc[mi][ni][1] + b1);
            float v10 = act_fn<ACT>(acc[mi][ni][2] + b0);
            float v11 = act_fn<ACT>(acc[mi][ni][3] + b1);
            if (HOUT) {
                __half* C = (__half*)Cv;
                *(__half2*)(C + (long)r0 * N + c0)       = __floats2half2_rn(v00, v01);
                *(__half2*)(C + (long)(r0 + 8) * N + c0) = __floats2half2_rn(v10, v11);
            } else {
                float* C = (float*)Cv;
                float2 w0 = { v00, v01 }, w1 = { v10, v11 };
                *(float2*)(C + (long)r0 * N + c0)       = w0;
                *(float2*)(C + (long)(r0 + 8) * N + c0) = w1;
            }
        }
    }
}

// ---------------- FP16 tensor-core flash attention, BR=128, BC=64 ----------------
// 8 warps: 4 (M, 32 rows) x 2 (N, 32 cols).
// Qs[r][d] fp16 (stride 36 words), Ks[j][d] fp16 / Vs[d][c] fp16 (stride 36),
// St[c][r] fp32 scores^T (stride 136), Ph[r][c] fp16 probs (stride 36).
#define FH_ST 36
#define FS_ST 136
#define FA_SMEM (int)((128 * FH_ST + 64 * FH_ST + 64 * FS_ST + 128 * FH_ST + 3 * 128) * 4)
__global__ __launch_bounds__(256, 2)
void flash_h_kernel(const __half* __restrict__ qkvh, __half* __restrict__ outp) {
    extern __shared__ uint32_t smu[];
    uint32_t* Qs = smu;                         // [128][FH_ST]
    uint32_t* Ks = Qs + 128 * FH_ST;            // [64][FH_ST]  K tile, then V^T tile
    float*    St = (float*)(Ks + 64 * FH_ST);   // [64][FS_ST]  scores^T
    uint32_t* Ph = (uint32_t*)St + 64 * FS_ST;  // [128][FH_ST] probs
    float* mrow = (float*)(Ph + 128 * FH_ST);   // [128]
    float* lrow = mrow + 128;
    float* crow = lrow + 128;

    int bh = blockIdx.y;
    int b = bh >> 4, h = bh & 15;
    int q0 = blockIdx.x * 128;
    int tid = threadIdx.x;
    int lane = tid & 31, warp = tid >> 5;
    int g = lane >> 2, tig = lane & 3;
    int warpM = (warp >> 1) * 32;   // 0,32,64,96
    int warpN = (warp & 1) * 32;    // 0,32

    // ---- load Q [r][d] fp16, prescale by 0.125 (exact) ----
    // 128 rows x 64 halves = 1024 uint4 chunks (8 halves each)
    const __half2 qsc = __float2half2_rn(0.125f);
    for (int idx = tid; idx < 1024; idx += 256) {
        int r = idx & 127, s4 = idx >> 7;   // s4 0..7
        uint4 v = *(const uint4*)(qkvh + (long)(b * Ss + q0 + r) * (3 * Cc) + h * Dd + s4 * 8);
        __half2* hv = (__half2*)&v;
        hv[0] = __hmul2(hv[0], qsc);
        hv[1] = __hmul2(hv[1], qsc);
        hv[2] = __hmul2(hv[2], qsc);
        hv[3] = __hmul2(hv[3], qsc);
        *(uint4*)&Qs[r * FH_ST + s4 * 4] = v;
    }
    if (tid < 128) { mrow[tid] = -1e30f; lrow[tid] = 0.f; }
    __syncthreads();

    float Oc[2][4][4] = {};   // [mi][ni][frag]

    for (int j0 = 0; j0 < Ss; j0 += 64) {
        // ---- K tile [j][d] fp16: 64 rows x 64 halves = 512 uint4 chunks ----
        for (int idx = tid; idx < 512; idx += 256) {
            int r = idx & 63, s4 = idx >> 6;   // s4 0..7
            uint4 v = *(const uint4*)(qkvh + (long)(b * Ss + j0 + r) * (3 * Cc) + Cc + h * Dd + s4 * 8);
            *(uint4*)&Ks[r * FH_ST + s4 * 4] = v;
        }
        __syncthreads();

        // ---- S = Q K^T (fp16 mma, k=64 -> 4 k16 steps) ----
        float Sc[2][4][4];
#pragma unroll
        for (int mi = 0; mi < 2; mi++)
#pragma unroll
            for (int ni = 0; ni < 4; ni++)
#pragma unroll
                for (int q = 0; q < 4; q++) Sc[mi][ni][q] = 0.f;
#pragma unroll
        for (int ks = 0; ks < 4; ks++) {
            uint32_t af[2][4], bf[4][2];
#pragma unroll
            for (int mi = 0; mi < 2; mi++) {
                int m = warpM + mi * 16 + g;
                af[mi][0] = Qs[m * FH_ST + ks * 8 + tig];
                af[mi][1] = Qs[(m + 8) * FH_ST + ks * 8 + tig];
                af[mi][2] = Qs[m * FH_ST + ks * 8 + 4 + tig];
                af[mi][3] = Qs[(m + 8) * FH_ST + ks * 8 + 4 + tig];
            }
#pragma unroll
            for (int ni = 0; ni < 4; ni++) {
                int n = warpN + ni * 8 + g;
                bf[ni][0] = Ks[n * FH_ST + ks * 8 + tig];
                bf[ni][1] = Ks[n * FH_ST + ks * 8 + 4 + tig];
            }
#pragma unroll
            for (int mi = 0; mi < 2; mi++)
#pragma unroll
                for (int ni = 0; ni < 4; ni++)
                    mma_f16(Sc[mi][ni], af[mi], bf[ni]);
        }
        // store S^T into St (fp32)
#pragma unroll
        for (int mi = 0; mi < 2; mi++) {
            int m0 = warpM + mi * 16 + g;
#pragma unroll
            for (int ni = 0; ni < 4; ni++) {
                int n0 = warpN + ni * 8 + tig * 2;
                St[n0 * FS_ST + m0]           = Sc[mi][ni][0];
                St[(n0 + 1) * FS_ST + m0]     = Sc[mi][ni][1];
                St[n0 * FS_ST + m0 + 8]       = Sc[mi][ni][2];
                St[(n0 + 1) * FS_ST + m0 + 8] = Sc[mi][ni][3];
            }
        }
        __syncthreads();

        // ---- online softmax (2 threads/row); write packed fp16 probs to Ph[r][c] ----
        {
            int r = tid >> 1, q = tid & 1;
            float pv[32];
            float tm = -1e30f;
#pragma unroll
            for (int i = 0; i < 32; i++) {
                pv[i] = St[(q * 32 + i) * FS_ST + r];
                tm = fmaxf(tm, pv[i]);
            }
            tm = fmaxf(tm, __shfl_xor_sync(0xffffffff, tm, 1));
            float mold = mrow[r];
            tm = fmaxf(tm, mold);
            float ls = 0.f;
#pragma unroll
            for (int i = 0; i < 32; i++) {
                pv[i] = __expf(pv[i] - tm);
                ls += pv[i];
            }
#pragma unroll
            for (int jj = 0; jj < 16; jj++) {
                __half2 hp = __floats2half2_rn(pv[2 * jj], pv[2 * jj + 1]);
                Ph[r * FH_ST + q * 16 + jj] = *(uint32_t*)&hp;
            }
            ls += __shfl_xor_sync(0xffffffff, ls, 1);
            if (q == 0) {
                float corr = __expf(mold - tm);
                crow[r] = corr;
                mrow[r] = tm;
                lrow[r] = lrow[r] * corr + ls;
            }
        }

        // ---- V tile transposed to Vs[d][c] packed along c (aliases Ks) ----
        {
            int c2 = tid & 31, i = tid >> 5;     // c2: col pair, i: 8-d group
            const __half* vb = qkvh + 2 * Cc + h * Dd + i * 8;
            uint4 lo = *(const uint4*)(vb + (long)(b * Ss + j0 + 2 * c2) * (3 * Cc));
            uint4 hi = *(const uint4*)(vb + (long)(b * Ss + j0 + 2 * c2 + 1) * (3 * Cc));
            const uint32_t* lw = (const uint32_t*)&lo;
            const uint32_t* hw = (const uint32_t*)&hi;
#pragma unroll
            for (int j = 0; j < 8; j++) {
                uint32_t w = __byte_perm(lw[j >> 1], hw[j >> 1], (j & 1) ? 0x7632 : 0x5410);
                Ks[(i * 8 + j) * FH_ST + c2] = w;
            }
        }
        __syncthreads();

        // ---- rescale O ----
#pragma unroll
        for (int mi = 0; mi < 2; mi++) {
            int m0 = warpM + mi * 16 + g;
            float cl = crow[m0], ch = crow[m0 + 8];
#pragma unroll
            for (int ni = 0; ni < 4; ni++) {
                Oc[mi][ni][0] *= cl; Oc[mi][ni][1] *= cl;
                Oc[mi][ni][2] *= ch; Oc[mi][ni][3] *= ch;
            }
        }

        // ---- O += P @ V (fp16 mma, k=c=64 -> 4 k16 steps) ----
#pragma unroll
        for (int ks = 0; ks < 4; ks++) {
            uint32_t af[2][4], bf[4][2];
#pragma unroll
            for (int mi = 0; mi < 2; mi++) {
                int m = warpM + mi * 16 + g;
                af[mi][0] = Ph[m * FH_ST + ks * 8 + tig];
                af[mi][1] = Ph[(m + 8) * FH_ST + ks * 8 + tig];
                af[mi][2] = Ph[m * FH_ST + ks * 8 + 4 + tig];
                af[mi][3] = Ph[(m + 8) * FH_ST + ks * 8 + 4 + tig];
            }
#pragma unroll
            for (int ni = 0; ni < 4; ni++) {
                int n = warpN + ni * 8 + g;
                bf[ni][0] = Ks[n * FH_ST + ks * 8 + tig];
                bf[ni][1] = Ks[n * FH_ST + ks * 8 + 4 + tig];
            }
#pragma unroll
            for (int mi = 0; mi < 2; mi++)
#pragma unroll
                for (int ni = 0; ni < 4; ni++)
                    mma_f16(Oc[mi][ni], af[mi], bf[ni]);
        }
        __syncthreads();
    }

    // ---- epilogue: normalize, write fp16 ----
#pragma unroll
    for (int mi = 0; mi < 2; mi++) {
        int m0 = warpM + mi * 16 + g;
        float inv0 = 1.f / lrow[m0];
        float inv1 = 1.f / lrow[m0 + 8];
#pragma unroll
        for (int ni = 0; ni < 4; ni++) {
            int n0 = warpN + ni * 8 + tig * 2;
            *(__half2*)(outp + (long)(b * Ss + q0 + m0) * Cc + h * Dd + n0) =
                __floats2half2_rn(Oc[mi][ni][0] * inv0, Oc[mi][ni][1] * inv0);
            *(__half2*)(outp + (long)(b * Ss + q0 + m0 + 8) * Cc + h * Dd + n0) =
                __floats2half2_rn(Oc[mi][ni][2] * inv1, Oc[mi][ni][3] * inv1);
        }
    }
}

// ---------------- launch ----------------
extern "C" void kernel_launch(void* const* d_in, const int* in_sizes, int n_in,
                              void* d_out, int out_size) {
    const float* x       = (const float*)d_in[0];
    const float* mod     = (const float*)d_in[1];
    const float* cond    = (const float*)d_in[2];
    const float* w_adaln = (const float*)d_in[3];
    const float* b_adaln = (const float*)d_in[4];
    const float* w_qkv   = (const float*)d_in[5];
    const float* b_qkv   = (const float*)d_in[6];
    const float* w_proj  = (const float*)d_in[7];
    const float* b_proj  = (const float*)d_in[8];
    const float* w_s1    = (const float*)d_in[9];
    const float* b_s1    = (const float*)d_in[10];
    const float* w_s2    = (const float*)d_in[11];
    const float* b_s2    = (const float*)d_in[12];
    const float* w_d1    = (const float*)d_in[13];
    const float* b_d1    = (const float*)d_in[14];
    const float* w_d2    = (const float*)d_in[15];
    const float* b_d2    = (const float*)d_in[16];

    float* outx = (float*)d_out;                         // [2,2048,1024]
    float* outc = outx + (long)Bz * Nn * Cc;             // [2,256,1024]

    float *gm, *gjoint, *gqkv;
    __half *gqkvh, *gwth, *gjh, *gah, *ghid;
    cudaGetSymbolAddress((void**)&gm,     g_m);
    cudaGetSymbolAddress((void**)&gjoint, g_joint);
    cudaGetSymbolAddress((void**)&gqkv,   g_qkv);
    cudaGetSymbolAddress((void**)&gqkvh,  g_qkvh);
    cudaGetSymbolAddress((void**)&gwth,   g_wTh);
    cudaGetSymbolAddress((void**)&gjh,    g_jh);
    cudaGetSymbolAddress((void**)&gah,    g_ah);
    cudaGetSymbolAddress((void**)&ghid,   g_hid16);

    cudaFuncSetAttribute(flash_h_kernel, cudaFuncAttributeMaxDynamicSharedMemorySize, FA_SMEM);
    cudaFuncSetAttribute(gemm_h<0,0>, cudaFuncAttributeMaxDynamicSharedMemorySize, GEMMH_SMEM);
    cudaFuncSetAttribute(gemm_h<0,1>, cudaFuncAttributeMaxDynamicSharedMemorySize, GEMMH_SMEM);
    cudaFuncSetAttribute(gemm_h<1,1>, cudaFuncAttributeMaxDynamicSharedMemorySize, GEMMH_SMEM);
    cudaFuncSetAttribute(gemm_h<2,1>, cudaFuncAttributeMaxDynamicSharedMemorySize, GEMMH_SMEM);

    const long SC = (long)Ss * Cc;
    const long NC = (long)Nn * Cc;
    const long TC = (long)Tt * Cc;

    // 0. weight transposes + fp16 cvt into g_wTh ([N][K] K-major)
    dim3 tb(32, 8);
    transpose_cvt_kernel<<<dim3(3 * Cc / 32, Cc / 32), tb>>>(w_qkv,  gwth + WT_QKV,  Cc, 3 * Cc);
    transpose_cvt_kernel<<<dim3(Cc / 32, Cc / 32),     tb>>>(w_proj, gwth + WT_PROJ, Cc, Cc);
    transpose_cvt_kernel<<<dim3(Hh / 32, Cc / 32),     tb>>>(w_s1,   gwth + WT_S1,   Cc, Hh);
    transpose_cvt_kernel<<<dim3(Cc / 32, Hh / 32),     tb>>>(w_s2,   gwth + WT_S2,   Hh, Cc);
    transpose_cvt_kernel<<<dim3(Hh / 32, Cc / 32),     tb>>>(w_d1,   gwth + WT_D1,   Cc, Hh);
    transpose_cvt_kernel<<<dim3(Cc / 32, Hh / 32),     tb>>>(w_d2,   gwth + WT_D2,   Hh, Cc);

    // 1. modulation vectors
    adaln_kernel<<<dim3(24, Bz), 256>>>(mod, w_adaln, b_adaln, gm);

    // 2. LN + msa modulate -> joint fp16 [B,S,C]
    ln_mod_h_kernel<<<Bz * Nn, 256>>>(x,    gjh, gm, Nn, 0, Cc, SC, 0);
    ln_mod_h_kernel<<<Bz * Tt, 256>>>(cond, gjh, gm, Tt, 0, Cc, SC, Nn);

    // 3. qkv = joint @ w_qkv + b  (4608 x 3072 x 1024), fp16 out
    gemm_h<0,1><<<dim3(3072 / 128, (Bz * Ss) / 128), 256, GEMMH_SMEM>>>(
        gjh, gwth + WT_QKV, b_qkv, gqkvh, Bz * Ss, 3 * Cc, Cc);

    // 4. attention (fp16 flash, BR=128) -> fp16 attn
    flash_h_kernel<<<dim3(Ss / 128, Bz * HEADS), 256, FA_SMEM>>>(gqkvh, gah);

    // 5. proj (4608 x 1024 x 1024) -> fp32 gjoint
    gemm_h<0,0><<<dim3(Cc / 128, (Bz * Ss) / 128), 256, GEMMH_SMEM>>>(
        gah, gwth + WT_PROJ, b_proj, gjoint, Bz * Ss, Cc, Cc);

    // 6. attn residual with g_msa (offset 2C)
    resid_gate_kernel<<<Bz * Nn, 256>>>(x,    gjoint, outx, gm, 2 * Cc, Nn, SC, 0);
    resid_gate_kernel<<<Bz * Tt, 256>>>(cond, gjoint, outc, gm, 2 * Cc, Tt, SC, Nn);

    // 7. LN + mlp modulate -> fp16 x2/c2
    __half* gx2 = gjh;                        // [B*N, C]
    __half* gc2 = gjh + (long)Bz * Nn * Cc;   // [B*T, C]
    ln_mod_h_kernel<<<Bz * Nn, 256>>>(outx, gx2, gm, Nn, 3 * Cc, 4 * Cc, NC, 0);
    ln_mod_h_kernel<<<Bz * Tt, 256>>>(outc, gc2, gm, Tt, 3 * Cc, 4 * Cc, TC, 0);

    // 8. x MLP: gelu(x2@w_s1+b) @ w_s2 + b
    gemm_h<1,1><<<dim3(Hh / 128, (Bz * Nn) / 128), 256, GEMMH_SMEM>>>(
        gx2, gwth + WT_S1, b_s1, ghid, Bz * Nn, Hh, Cc);
    gemm_h<0,0><<<dim3(Cc / 128, (Bz * Nn) / 128), 256, GEMMH_SMEM>>>(
        ghid, gwth + WT_S2, b_s2, gqkv, Bz * Nn, Cc, Hh);
    resid_gate_kernel<<<Bz * Nn, 256>>>(outx, gqkv, outx, gm, 5 * Cc, Nn, NC, 0);

    // 9. cond MLP: silu(c2@w_d1+b) @ w_d2 + b
    gemm_h<2,1><<<dim3(Hh / 128, (Bz * Tt) / 128), 256, GEMMH_SMEM>>>(
        gc2, gwth + WT_D1, b_d1, ghid, Bz * Tt, Hh, Cc);
    gemm_h<0,0><<<dim3(Cc / 128, (Bz * Tt) / 128), 256, GEMMH_SMEM>>>(
        ghid, gwth + WT_D2, b_d2, gqkv, Bz * Tt, Cc, Hh);
    resid_gate_kernel<<<Bz * Tt, 256>>>(outc, gqkv, outc, gm, 5 * Cc, Tt, TC, 0);
}

// round 13
// speedup vs baseline: 5.6518x; 1.1012x over previous
#include <cuda_runtime.h>
#include <cuda_fp16.h>
#include <cstdint>

// ---------------- problem constants ----------------
#define Bz   2
#define Nn   2048
#define Tt   256
#define Cc   1024
#define Hh   4096
#define Ss   2304          // N + T
#define HEADS 16
#define Dd   64

// ---------------- scratch (no allocation allowed) ----------------
__device__ float  g_m[Bz * 6 * Cc];                  // adaLN modulation vectors
__device__ __half g_qkvh[(long)Bz * Ss * 3 * Cc];    // qkv (fp16)
__device__ __half g_wTh[20971520];                   // transposed fp16 weights [N][K]
__device__ __half g_jh[(long)Bz * Ss * Cc];          // fp16: joint / x2,c2
__device__ __half g_ah[(long)Bz * Ss * Cc];          // fp16: attention out
__device__ __half g_hid16[(long)Bz * Ss * Hh];       // fp16: MLP hidden (x + cond rows)

// offsets into g_wTh (halves)
#define WT_QKV  0L
#define WT_PROJ 3145728L
#define WT_S1   4194304L
#define WT_S2   8388608L
#define WT_D1   12582912L
#define WT_D2   16777216L

// ---------------- activations ----------------
template<int ACT>
__device__ __forceinline__ float act_fn(float x) {
    if (ACT == 1) { // gelu tanh approx
        float x3 = x * x * x;
        return 0.5f * x * (1.f + tanhf(0.7978845608028654f * (x + 0.044715f * x3)));
    }
    if (ACT == 2) { // silu
        return x / (1.f + __expf(-x));
    }
    return x;
}

__device__ __forceinline__ void mma_f16(float* d,
                                        const uint32_t* a, const uint32_t* b) {
    asm volatile(
        "mma.sync.aligned.m16n8k16.row.col.f32.f16.f16.f32 "
        "{%0,%1,%2,%3}, {%4,%5,%6,%7}, {%8,%9}, {%0,%1,%2,%3};\n"
        : "+f"(d[0]), "+f"(d[1]), "+f"(d[2]), "+f"(d[3])
        : "r"(a[0]), "r"(a[1]), "r"(a[2]), "r"(a[3]), "r"(b[0]), "r"(b[1]));
}

__device__ __forceinline__ void cp_async16(uint32_t smem_dst, const void* gsrc) {
    asm volatile("cp.async.ca.shared.global [%0], [%1], 16;\n"
                 :: "r"(smem_dst), "l"(gsrc));
}

// ---------------- weight transpose + cvt: out[N][K] = (half)in[K][N] ----------------
__global__ void transpose_cvt_kernel(const float* __restrict__ in, __half* __restrict__ out,
                                     int K, int N) {
    __shared__ float t[32][33];
    int n0 = blockIdx.x * 32, k0 = blockIdx.y * 32;
    int tx = threadIdx.x, ty = threadIdx.y;  // (32, 8)
#pragma unroll
    for (int i = 0; i < 32; i += 8)
        t[ty + i][tx] = in[(long)(k0 + ty + i) * N + n0 + tx];
    __syncthreads();
#pragma unroll
    for (int i = 0; i < 32; i += 8)
        out[(long)(n0 + ty + i) * K + k0 + tx] = __float2half(t[tx][ty + i]);
}

// ---------------- adaLN: m = silu(mod) @ w_adaln + b ----------------
__global__ void adaln_kernel(const float* __restrict__ mod,
                             const float* __restrict__ w,
                             const float* __restrict__ bias,
                             float* __restrict__ mout) {
    int b = blockIdx.y;
    int j = blockIdx.x * 256 + threadIdx.x;   // < 6144
    __shared__ float sm[Cc];
    for (int i = threadIdx.x; i < Cc; i += 256) {
        float v = mod[b * Cc + i];
        sm[i] = v / (1.f + __expf(-v));
    }
    __syncthreads();
    float acc = bias[j];
    for (int k = 0; k < Cc; k++) acc += sm[k] * w[(long)k * (6 * Cc) + j];
    mout[b * 6 * Cc + j] = acc;
}

// ---------------- LN + modulate -> fp16 out ----------------
__global__ void ln_mod_h_kernel(const float* __restrict__ in, __half* __restrict__ out,
                                const float* __restrict__ m, int rowsPerBatch,
                                int shOff, int scOff,
                                long outBatchStride, int outRowOff) {
    int row = blockIdx.x;
    int b = row / rowsPerBatch;
    int r = row - b * rowsPerBatch;
    const float* xi = in + (long)row * Cc;
    float v[4]; float s = 0.f, s2 = 0.f;
#pragma unroll
    for (int i = 0; i < 4; i++) {
        v[i] = xi[threadIdx.x + 256 * i];
        s += v[i]; s2 += v[i] * v[i];
    }
    __shared__ float rs[256], rs2[256];
    rs[threadIdx.x] = s; rs2[threadIdx.x] = s2;
    __syncthreads();
    for (int off = 128; off > 0; off >>= 1) {
        if (threadIdx.x < off) {
            rs[threadIdx.x]  += rs[threadIdx.x + off];
            rs2[threadIdx.x] += rs2[threadIdx.x + off];
        }
        __syncthreads();
    }
    float mu   = rs[0] * (1.f / (float)Cc);
    float var  = rs2[0] * (1.f / (float)Cc) - mu * mu;
    float rstd = rsqrtf(var + 1e-6f);
    const float* mb = m + b * 6 * Cc;
    __half* po = out + (long)b * outBatchStride + (long)(outRowOff + r) * Cc;
#pragma unroll
    for (int i = 0; i < 4; i++) {
        int c = threadIdx.x + 256 * i;
        po[c] = __float2half((v[i] - mu) * rstd * (1.f + mb[scOff + c]) + mb[shOff + c]);
    }
}

// ---------------- FP16 tensor-core GEMM, fused epilogues ----------------
// MODE 1: C[fp16] = acc + bias1                                 (qkv)
// MODE 2: C[fp16] = region1 ? gelu(acc+bias1) : silu(acc+bias2) (s1 | d1 merged)
// MODE 3: fp32 out{x,c} = base{x,c} + (acc+bias1)*g_msa          (proj, region by row)
// MODE 4: fp32 out{x,c} = out{x,c} + (acc+bias{1,2})*g_mlp       (s2 | d2 merged)
// Mainloop is the R10-validated gemm_h pipeline; only B-select and epilogue differ.
#define GH_ST 20
#define GH_STG (128 * GH_ST)
#define GEMMH_SMEM (6 * GH_STG * 4)

template<int MODE>
__global__ __launch_bounds__(256, 2)
void gemm_h2(const __half* __restrict__ A,
             const __half* __restrict__ BT1, const __half* __restrict__ BT2,
             const float* __restrict__ bias1, const float* __restrict__ bias2,
             void* __restrict__ out1, void* __restrict__ out2,
             const float* __restrict__ base1, const float* __restrict__ base2,
             const float* __restrict__ gmv, int gOff, int splitBlk,
             int M, int N, int K) {
    extern __shared__ uint32_t smg[];
    uint32_t* As = smg;                 // [3][128][20]
    uint32_t* Bs = smg + 3 * GH_STG;    // [3][128][20]

    int tid  = threadIdx.x;
    int warp = tid >> 5, lane = tid & 31;
    int lg   = lane >> 2, tig = lane & 3;
    int warpM = (warp >> 2) * 64;
    int warpN = (warp & 3) * 32;

    bool reg1 = (int)blockIdx.y < splitBlk;
    const __half* BTsel = reg1 ? BT1 : BT2;
    const float*  bsel  = reg1 ? bias1 : bias2;

    const __half* Ab = A + (long)blockIdx.y * 128 * K;
    const __half* Bb = BTsel + (long)blockIdx.x * 128 * K;

    float acc[4][4][4];
#pragma unroll
    for (int i = 0; i < 4; i++)
#pragma unroll
        for (int j = 0; j < 4; j++)
#pragma unroll
            for (int q = 0; q < 4; q++) acc[i][j][q] = 0.f;

    int nstages = K >> 5;

#define GH_FILL(s) do {                                                        \
        int buf_ = (s) % 3;                                                    \
        int k0_  = (s) << 5;                                                   \
        uint32_t* Ad = As + buf_ * GH_STG;                                     \
        uint32_t* Bd = Bs + buf_ * GH_STG;                                     \
        _Pragma("unroll")                                                      \
        for (int i_ = 0; i_ < 2; i_++) {                                       \
            int c_ = tid + i_ * 256;           /* 0..511 */                    \
            int r_ = c_ >> 2, kc_ = c_ & 3;                                    \
            uint32_t da_ = (uint32_t)__cvta_generic_to_shared(Ad + r_ * GH_ST + kc_ * 4); \
            cp_async16(da_, Ab + (long)r_ * K + k0_ + kc_ * 8);                \
            uint32_t db_ = (uint32_t)__cvta_generic_to_shared(Bd + r_ * GH_ST + kc_ * 4); \
            cp_async16(db_, Bb + (long)r_ * K + k0_ + kc_ * 8);                \
        }                                                                      \
        asm volatile("cp.async.commit_group;\n");                              \
    } while (0)

    GH_FILL(0);
    GH_FILL(1);

    for (int s = 0; s < nstages; s++) {
        if (s + 1 < nstages) asm volatile("cp.async.wait_group 1;\n");
        else                 asm volatile("cp.async.wait_group 0;\n");
        __syncthreads();
        if (s + 2 < nstages) GH_FILL(s + 2);

        uint32_t* Ac = As + (s % 3) * GH_STG;
        uint32_t* Bc = Bs + (s % 3) * GH_STG;
#pragma unroll
        for (int kk = 0; kk < 2; kk++) {
            uint32_t af[4][4], bf[4][2];
#pragma unroll
            for (int mi = 0; mi < 4; mi++) {
                int m = warpM + mi * 16 + lg;
                af[mi][0] = Ac[m * GH_ST + kk * 8 + tig];
                af[mi][1] = Ac[(m + 8) * GH_ST + kk * 8 + tig];
                af[mi][2] = Ac[m * GH_ST + kk * 8 + 4 + tig];
                af[mi][3] = Ac[(m + 8) * GH_ST + kk * 8 + 4 + tig];
            }
#pragma unroll
            for (int ni = 0; ni < 4; ni++) {
                int n = warpN + ni * 8 + lg;
                bf[ni][0] = Bc[n * GH_ST + kk * 8 + tig];
                bf[ni][1] = Bc[n * GH_ST + kk * 8 + 4 + tig];
            }
#pragma unroll
            for (int mi = 0; mi < 4; mi++)
#pragma unroll
                for (int ni = 0; ni < 4; ni++)
                    mma_f16(acc[mi][ni], af[mi], bf[ni]);
        }
    }
#undef GH_FILL

    // ------------- fused epilogues -------------
    int gRow0 = blockIdx.y * 128;      // global row of tile top
    int colBase = blockIdx.x * 128 + warpN;

    // per-block uniform output mapping for MODE 3/4
    float* outp = nullptr;
    const float* basep = nullptr;
    const float* gvp = nullptr;
    if (MODE == 3) {
        int b = gRow0 / Ss;
        int rr0 = gRow0 - b * Ss;
        if (rr0 < Nn) {
            outp  = (float*)out1 + ((long)b * Nn + rr0) * Cc;
            basep = base1 + ((long)b * Nn + rr0) * Cc;
        } else {
            outp  = (float*)out2 + ((long)b * Tt + rr0 - Nn) * Cc;
            basep = base2 + ((long)b * Tt + rr0 - Nn) * Cc;
        }
        gvp = gmv + b * 6 * Cc + gOff;
    }
    if (MODE == 4) {
        if (reg1) {
            int b = gRow0 >> 11;                      // / Nn
            outp  = (float*)out1 + (long)gRow0 * Cc;
            basep = base1 + (long)gRow0 * Cc;
            gvp = gmv + b * 6 * Cc + gOff;
        } else {
            int rc0 = gRow0 - Bz * Nn;
            int b = rc0 >> 8;                         // / Tt
            outp  = (float*)out2 + (long)rc0 * Cc;
            basep = base2 + (long)rc0 * Cc;
            gvp = gmv + b * 6 * Cc + gOff;
        }
    }

#pragma unroll
    for (int mi = 0; mi < 4; mi++) {
#pragma unroll
        for (int ni = 0; ni < 4; ni++) {
            int rloc = warpM + mi * 16 + lg;          // row within 128-tile
            int c0 = colBase + ni * 8 + tig * 2;
            float b0 = bsel[c0], b1 = bsel[c0 + 1];
            float v00 = acc[mi][ni][0] + b0;
            float v01 = acc[mi][ni][1] + b1;
            float v10 = acc[mi][ni][2] + b0;
            float v11 = acc[mi][ni][3] + b1;
            if (MODE == 1) {
                __half* C = (__half*)out1;
                long r0 = gRow0 + rloc;
                *(__half2*)(C + r0 * N + c0)       = __floats2half2_rn(v00, v01);
                *(__half2*)(C + (r0 + 8) * N + c0) = __floats2half2_rn(v10, v11);
            } else if (MODE == 2) {
                if (reg1) {
                    v00 = act_fn<1>(v00); v01 = act_fn<1>(v01);
                    v10 = act_fn<1>(v10); v11 = act_fn<1>(v11);
                } else {
                    v00 = act_fn<2>(v00); v01 = act_fn<2>(v01);
                    v10 = act_fn<2>(v10); v11 = act_fn<2>(v11);
                }
                __half* C = (__half*)out1;
                long r0 = gRow0 + rloc;
                *(__half2*)(C + r0 * N + c0)       = __floats2half2_rn(v00, v01);
                *(__half2*)(C + (r0 + 8) * N + c0) = __floats2half2_rn(v10, v11);
            } else { // MODE 3 / 4: residual gate, fp32
                float g0 = gvp[c0], g1 = gvp[c0 + 1];
                float* p0 = outp + (long)rloc * Cc + c0;
                float* p1 = outp + (long)(rloc + 8) * Cc + c0;
                const float* q0 = basep + (long)rloc * Cc + c0;
                const float* q1 = basep + (long)(rloc + 8) * Cc + c0;
                p0[0] = q0[0] + v00 * g0;
                p0[1] = q0[1] + v01 * g1;
                p1[0] = q1[0] + v10 * g0;
                p1[1] = q1[1] + v11 * g1;
            }
        }
    }
}

// ---------------- FP16 tensor-core flash attention, BR=128, BC=64 (validated R12) ----------------
#define FH_ST 36
#define FS_ST 136
#define FA_SMEM (int)((128 * FH_ST + 64 * FH_ST + 64 * FS_ST + 128 * FH_ST + 3 * 128) * 4)
__global__ __launch_bounds__(256, 2)
void flash_h_kernel(const __half* __restrict__ qkvh, __half* __restrict__ outp) {
    extern __shared__ uint32_t smu[];
    uint32_t* Qs = smu;                         // [128][FH_ST]
    uint32_t* Ks = Qs + 128 * FH_ST;            // [64][FH_ST]  K tile, then V^T tile
    float*    St = (float*)(Ks + 64 * FH_ST);   // [64][FS_ST]  scores^T
    uint32_t* Ph = (uint32_t*)St + 64 * FS_ST;  // [128][FH_ST] probs
    float* mrow = (float*)(Ph + 128 * FH_ST);   // [128]
    float* lrow = mrow + 128;
    float* crow = lrow + 128;

    int bh = blockIdx.y;
    int b = bh >> 4, h = bh & 15;
    int q0 = blockIdx.x * 128;
    int tid = threadIdx.x;
    int lane = tid & 31, warp = tid >> 5;
    int g = lane >> 2, tig = lane & 3;
    int warpM = (warp >> 1) * 32;   // 0,32,64,96
    int warpN = (warp & 1) * 32;    // 0,32

    const __half2 qsc = __float2half2_rn(0.125f);
    for (int idx = tid; idx < 1024; idx += 256) {
        int r = idx & 127, s4 = idx >> 7;   // s4 0..7
        uint4 v = *(const uint4*)(qkvh + (long)(b * Ss + q0 + r) * (3 * Cc) + h * Dd + s4 * 8);
        __half2* hv = (__half2*)&v;
        hv[0] = __hmul2(hv[0], qsc);
        hv[1] = __hmul2(hv[1], qsc);
        hv[2] = __hmul2(hv[2], qsc);
        hv[3] = __hmul2(hv[3], qsc);
        *(uint4*)&Qs[r * FH_ST + s4 * 4] = v;
    }
    if (tid < 128) { mrow[tid] = -1e30f; lrow[tid] = 0.f; }
    __syncthreads();

    float Oc[2][4][4] = {};   // [mi][ni][frag]

    for (int j0 = 0; j0 < Ss; j0 += 64) {
        for (int idx = tid; idx < 512; idx += 256) {
            int r = idx & 63, s4 = idx >> 6;   // s4 0..7
            uint4 v = *(const uint4*)(qkvh + (long)(b * Ss + j0 + r) * (3 * Cc) + Cc + h * Dd + s4 * 8);
            *(uint4*)&Ks[r * FH_ST + s4 * 4] = v;
        }
        __syncthreads();

        float Sc[2][4][4];
#pragma unroll
        for (int mi = 0; mi < 2; mi++)
#pragma unroll
            for (int ni = 0; ni < 4; ni++)
#pragma unroll
                for (int q = 0; q < 4; q++) Sc[mi][ni][q] = 0.f;
#pragma unroll
        for (int ks = 0; ks < 4; ks++) {
            uint32_t af[2][4], bf[4][2];
#pragma unroll
            for (int mi = 0; mi < 2; mi++) {
                int m = warpM + mi * 16 + g;
                af[mi][0] = Qs[m * FH_ST + ks * 8 + tig];
                af[mi][1] = Qs[(m + 8) * FH_ST + ks * 8 + tig];
                af[mi][2] = Qs[m * FH_ST + ks * 8 + 4 + tig];
                af[mi][3] = Qs[(m + 8) * FH_ST + ks * 8 + 4 + tig];
            }
#pragma unroll
            for (int ni = 0; ni < 4; ni++) {
                int n = warpN + ni * 8 + g;
                bf[ni][0] = Ks[n * FH_ST + ks * 8 + tig];
                bf[ni][1] = Ks[n * FH_ST + ks * 8 + 4 + tig];
            }
#pragma unroll
            for (int mi = 0; mi < 2; mi++)
#pragma unroll
                for (int ni = 0; ni < 4; ni++)
                    mma_f16(Sc[mi][ni], af[mi], bf[ni]);
        }
#pragma unroll
        for (int mi = 0; mi < 2; mi++) {
            int m0 = warpM + mi * 16 + g;
#pragma unroll
            for (int ni = 0; ni < 4; ni++) {
                int n0 = warpN + ni * 8 + tig * 2;
                St[n0 * FS_ST + m0]           = Sc[mi][ni][0];
                St[(n0 + 1) * FS_ST + m0]     = Sc[mi][ni][1];
                St[n0 * FS_ST + m0 + 8]       = Sc[mi][ni][2];
                St[(n0 + 1) * FS_ST + m0 + 8] = Sc[mi][ni][3];
            }
        }
        __syncthreads();

        {
            int r = tid >> 1, q = tid & 1;
            float pv[32];
            float tm = -1e30f;
#pragma unroll
            for (int i = 0; i < 32; i++) {
                pv[i] = St[(q * 32 + i) * FS_ST + r];
                tm = fmaxf(tm, pv[i]);
            }
            tm = fmaxf(tm, __shfl_xor_sync(0xffffffff, tm, 1));
            float mold = mrow[r];
            tm = fmaxf(tm, mold);
            float ls = 0.f;
#pragma unroll
            for (int i = 0; i < 32; i++) {
                pv[i] = __expf(pv[i] - tm);
                ls += pv[i];
            }
#pragma unroll
            for (int jj = 0; jj < 16; jj++) {
                __half2 hp = __floats2half2_rn(pv[2 * jj], pv[2 * jj + 1]);
                Ph[r * FH_ST + q * 16 + jj] = *(uint32_t*)&hp;
            }
            ls += __shfl_xor_sync(0xffffffff, ls, 1);
            if (q == 0) {
                float corr = __expf(mold - tm);
                crow[r] = corr;
                mrow[r] = tm;
                lrow[r] = lrow[r] * corr + ls;
            }
        }

        {
            int c2 = tid & 31, i = tid >> 5;     // c2: col pair, i: 8-d group
            const __half* vb = qkvh + 2 * Cc + h * Dd + i * 8;
            uint4 lo = *(const uint4*)(vb + (long)(b * Ss + j0 + 2 * c2) * (3 * Cc));
            uint4 hi = *(const uint4*)(vb + (long)(b * Ss + j0 + 2 * c2 + 1) * (3 * Cc));
            const uint32_t* lw = (const uint32_t*)&lo;
            const uint32_t* hw = (const uint32_t*)&hi;
#pragma unroll
            for (int j = 0; j < 8; j++) {
                uint32_t w = __byte_perm(lw[j >> 1], hw[j >> 1], (j & 1) ? 0x7632 : 0x5410);
                Ks[(i * 8 + j) * FH_ST + c2] = w;
            }
        }
        __syncthreads();

#pragma unroll
        for (int mi = 0; mi < 2; mi++) {
            int m0 = warpM + mi * 16 + g;
            float cl = crow[m0], ch = crow[m0 + 8];
#pragma unroll
            for (int ni = 0; ni < 4; ni++) {
                Oc[mi][ni][0] *= cl; Oc[mi][ni][1] *= cl;
                Oc[mi][ni][2] *= ch; Oc[mi][ni][3] *= ch;
            }
        }

#pragma unroll
        for (int ks = 0; ks < 4; ks++) {
            uint32_t af[2][4], bf[4][2];
#pragma unroll
            for (int mi = 0; mi < 2; mi++) {
                int m = warpM + mi * 16 + g;
                af[mi][0] = Ph[m * FH_ST + ks * 8 + tig];
                af[mi][1] = Ph[(m + 8) * FH_ST + ks * 8 + tig];
                af[mi][2] = Ph[m * FH_ST + ks * 8 + 4 + tig];
                af[mi][3] = Ph[(m + 8) * FH_ST + ks * 8 + 4 + tig];
            }
#pragma unroll
            for (int ni = 0; ni < 4; ni++) {
                int n = warpN + ni * 8 + g;
                bf[ni][0] = Ks[n * FH_ST + ks * 8 + tig];
                bf[ni][1] = Ks[n * FH_ST + ks * 8 + 4 + tig];
            }
#pragma unroll
            for (int mi = 0; mi < 2; mi++)
#pragma unroll
                for (int ni = 0; ni < 4; ni++)
                    mma_f16(Oc[mi][ni], af[mi], bf[ni]);
        }
        __syncthreads();
    }

#pragma unroll
    for (int mi = 0; mi < 2; mi++) {
        int m0 = warpM + mi * 16 + g;
        float inv0 = 1.f / lrow[m0];
        float inv1 = 1.f / lrow[m0 + 8];
#pragma unroll
        for (int ni = 0; ni < 4; ni++) {
            int n0 = warpN + ni * 8 + tig * 2;
            *(__half2*)(outp + (long)(b * Ss + q0 + m0) * Cc + h * Dd + n0) =
                __floats2half2_rn(Oc[mi][ni][0] * inv0, Oc[mi][ni][1] * inv0);
            *(__half2*)(outp + (long)(b * Ss + q0 + m0 + 8) * Cc + h * Dd + n0) =
                __floats2half2_rn(Oc[mi][ni][2] * inv1, Oc[mi][ni][3] * inv1);
        }
    }
}

// ---------------- launch ----------------
extern "C" void kernel_launch(void* const* d_in, const int* in_sizes, int n_in,
                              void* d_out, int out_size) {
    const float* x       = (const float*)d_in[0];
    const float* mod     = (const float*)d_in[1];
    const float* cond    = (const float*)d_in[2];
    const float* w_adaln = (const float*)d_in[3];
    const float* b_adaln = (const float*)d_in[4];
    const float* w_qkv   = (const float*)d_in[5];
    const float* b_qkv   = (const float*)d_in[6];
    const float* w_proj  = (const float*)d_in[7];
    const float* b_proj  = (const float*)d_in[8];
    const float* w_s1    = (const float*)d_in[9];
    const float* b_s1    = (const float*)d_in[10];
    const float* w_s2    = (const float*)d_in[11];
    const float* b_s2    = (const float*)d_in[12];
    const float* w_d1    = (const float*)d_in[13];
    const float* b_d1    = (const float*)d_in[14];
    const float* w_d2    = (const float*)d_in[15];
    const float* b_d2    = (const float*)d_in[16];

    float* outx = (float*)d_out;                         // [2,2048,1024]
    float* outc = outx + (long)Bz * Nn * Cc;             // [2,256,1024]

    float *gm;
    __half *gqkvh, *gwth, *gjh, *gah, *ghid;
    cudaGetSymbolAddress((void**)&gm,    g_m);
    cudaGetSymbolAddress((void**)&gqkvh, g_qkvh);
    cudaGetSymbolAddress((void**)&gwth,  g_wTh);
    cudaGetSymbolAddress((void**)&gjh,   g_jh);
    cudaGetSymbolAddress((void**)&gah,   g_ah);
    cudaGetSymbolAddress((void**)&ghid,  g_hid16);

    cudaFuncSetAttribute(flash_h_kernel, cudaFuncAttributeMaxDynamicSharedMemorySize, FA_SMEM);
    cudaFuncSetAttribute(gemm_h2<1>, cudaFuncAttributeMaxDynamicSharedMemorySize, GEMMH_SMEM);
    cudaFuncSetAttribute(gemm_h2<2>, cudaFuncAttributeMaxDynamicSharedMemorySize, GEMMH_SMEM);
    cudaFuncSetAttribute(gemm_h2<3>, cudaFuncAttributeMaxDynamicSharedMemorySize, GEMMH_SMEM);
    cudaFuncSetAttribute(gemm_h2<4>, cudaFuncAttributeMaxDynamicSharedMemorySize, GEMMH_SMEM);

    const long SC = (long)Ss * Cc;
    const long NC = (long)Nn * Cc;
    const long TC = (long)Tt * Cc;

    // 0. weight transposes + fp16 cvt
    dim3 tb(32, 8);
    transpose_cvt_kernel<<<dim3(3 * Cc / 32, Cc / 32), tb>>>(w_qkv,  gwth + WT_QKV,  Cc, 3 * Cc);
    transpose_cvt_kernel<<<dim3(Cc / 32, Cc / 32),     tb>>>(w_proj, gwth + WT_PROJ, Cc, Cc);
    transpose_cvt_kernel<<<dim3(Hh / 32, Cc / 32),     tb>>>(w_s1,   gwth + WT_S1,   Cc, Hh);
    transpose_cvt_kernel<<<dim3(Cc / 32, Hh / 32),     tb>>>(w_s2,   gwth + WT_S2,   Hh, Cc);
    transpose_cvt_kernel<<<dim3(Hh / 32, Cc / 32),     tb>>>(w_d1,   gwth + WT_D1,   Cc, Hh);
    transpose_cvt_kernel<<<dim3(Cc / 32, Hh / 32),     tb>>>(w_d2,   gwth + WT_D2,   Hh, Cc);

    // 1. modulation vectors
    adaln_kernel<<<dim3(24, Bz), 256>>>(mod, w_adaln, b_adaln, gm);

    // 2. LN + msa modulate -> joint fp16 [B,S,C]
    ln_mod_h_kernel<<<Bz * Nn, 256>>>(x,    gjh, gm, Nn, 0, Cc, SC, 0);
    ln_mod_h_kernel<<<Bz * Tt, 256>>>(cond, gjh, gm, Tt, 0, Cc, SC, Nn);

    // 3. qkv (fp16 out)
    gemm_h2<1><<<dim3(24, 36), 256, GEMMH_SMEM>>>(
        gjh, gwth + WT_QKV, gwth + WT_QKV, b_qkv, b_qkv,
        gqkvh, nullptr, nullptr, nullptr, nullptr, 0, 36,
        Bz * Ss, 3 * Cc, Cc);

    // 4. attention
    flash_h_kernel<<<dim3(Ss / 128, Bz * HEADS), 256, FA_SMEM>>>(gqkvh, gah);

    // 5. proj + fused attn-residual (writes outx / outc directly)
    gemm_h2<3><<<dim3(8, 36), 256, GEMMH_SMEM>>>(
        gah, gwth + WT_PROJ, gwth + WT_PROJ, b_proj, b_proj,
        outx, outc, x, cond, gm, 2 * Cc, 36,
        Bz * Ss, Cc, Cc);

    // 6. LN + mlp modulate -> fp16 x2/c2 (contiguous in gjh)
    __half* gx2 = gjh;
    __half* gc2 = gjh + (long)Bz * Nn * Cc;
    ln_mod_h_kernel<<<Bz * Nn, 256>>>(outx, gx2, gm, Nn, 3 * Cc, 4 * Cc, NC, 0);
    ln_mod_h_kernel<<<Bz * Tt, 256>>>(outc, gc2, gm, Tt, 3 * Cc, 4 * Cc, TC, 0);

    // 7. merged s1|d1: gelu(x2@w_s1) rows<4096, silu(c2@w_d1) rows>=4096 -> ghid fp16
    gemm_h2<2><<<dim3(32, 36), 256, GEMMH_SMEM>>>(
        gjh, gwth + WT_S1, gwth + WT_D1, b_s1, b_d1,
        ghid, nullptr, nullptr, nullptr, nullptr, 0, 32,
        Bz * Ss, Hh, Cc);

    // 8. merged s2|d2 + fused mlp-residual -> outx/outc
    gemm_h2<4><<<dim3(8, 36), 256, GEMMH_SMEM>>>(
        ghid, gwth + WT_S2, gwth + WT_D2, b_s2, b_d2,
        outx, outc, outx, outc, gm, 5 * Cc, 32,
        Bz * Ss, Cc, Hh);
}

// round 14
// speedup vs baseline: 6.0084x; 1.0631x over previous
#include <cuda_runtime.h>
#include <cuda_fp16.h>
#include <cstdint>

// ---------------- problem constants ----------------
#define Bz   2
#define Nn   2048
#define Tt   256
#define Cc   1024
#define Hh   4096
#define Ss   2304          // N + T
#define HEADS 16
#define Dd   64

// ---------------- scratch (no allocation allowed) ----------------
__device__ float  g_m[Bz * 6 * Cc];                  // adaLN modulation vectors
__device__ __half g_qkvh[(long)Bz * Ss * 3 * Cc];    // qkv (fp16)
__device__ __half g_wTh[20971520];                   // transposed fp16 weights [N][K]
__device__ __half g_jh[(long)Bz * Ss * Cc];          // fp16: joint / x2,c2
__device__ __half g_ah[(long)Bz * Ss * Cc];          // fp16: attention out
__device__ __half g_hid16[(long)Bz * Ss * Hh];       // fp16: MLP hidden (x + cond rows)

// offsets into g_wTh (halves)
#define WT_QKV  0L
#define WT_PROJ 3145728L
#define WT_S1   4194304L
#define WT_S2   8388608L
#define WT_D1   12582912L
#define WT_D2   16777216L

// ---------------- activations ----------------
template<int ACT>
__device__ __forceinline__ float act_fn(float x) {
    if (ACT == 1) { // gelu tanh approx
        float x3 = x * x * x;
        return 0.5f * x * (1.f + tanhf(0.7978845608028654f * (x + 0.044715f * x3)));
    }
    if (ACT == 2) { // silu
        return x / (1.f + __expf(-x));
    }
    return x;
}

__device__ __forceinline__ void mma_f16(float* d,
                                        const uint32_t* a, const uint32_t* b) {
    asm volatile(
        "mma.sync.aligned.m16n8k16.row.col.f32.f16.f16.f32 "
        "{%0,%1,%2,%3}, {%4,%5,%6,%7}, {%8,%9}, {%0,%1,%2,%3};\n"
        : "+f"(d[0]), "+f"(d[1]), "+f"(d[2]), "+f"(d[3])
        : "r"(a[0]), "r"(a[1]), "r"(a[2]), "r"(a[3]), "r"(b[0]), "r"(b[1]));
}

__device__ __forceinline__ void cp_async16(uint32_t smem_dst, const void* gsrc) {
    asm volatile("cp.async.ca.shared.global [%0], [%1], 16;\n"
                 :: "r"(smem_dst), "l"(gsrc));
}

// ---------------- weight transpose + cvt: out[N][K] = (half)in[K][N] ----------------
// 64x64 tiles: float2 reads (256B/warp), half2 writes (128B/warp contiguous).
__global__ void transpose_cvt_kernel(const float* __restrict__ in, __half* __restrict__ out,
                                     int K, int N) {
    __shared__ float t[64][65];
    int n0 = blockIdx.x * 64, k0 = blockIdx.y * 64;
    int tid = threadIdx.x;   // 256
#pragma unroll
    for (int i = 0; i < 8; i++) {
        int idx = tid + i * 256;
        int kr = idx >> 5;            // 0..63 (uniform per warp)
        int nc = (idx & 31) * 2;      // 0..62
        float2 v = *(const float2*)(in + (long)(k0 + kr) * N + n0 + nc);
        t[nc][kr]     = v.x;          // store transposed
        t[nc + 1][kr] = v.y;
    }
    __syncthreads();
#pragma unroll
    for (int i = 0; i < 8; i++) {
        int idx = tid + i * 256;
        int nr = idx >> 5;            // 0..63 (uniform per warp)
        int kc = (idx & 31) * 2;
        __half2 h = __floats2half2_rn(t[nr][kc], t[nr][kc + 1]);
        *(__half2*)(out + (long)(n0 + nr) * K + k0 + kc) = h;
    }
}

// ---------------- adaLN: m = silu(mod) @ w_adaln + b ----------------
__global__ void adaln_kernel(const float* __restrict__ mod,
                             const float* __restrict__ w,
                             const float* __restrict__ bias,
                             float* __restrict__ mout) {
    int b = blockIdx.y;
    int j = blockIdx.x * 256 + threadIdx.x;   // < 6144
    __shared__ float sm[Cc];
    for (int i = threadIdx.x; i < Cc; i += 256) {
        float v = mod[b * Cc + i];
        sm[i] = v / (1.f + __expf(-v));
    }
    __syncthreads();
    float acc = bias[j];
    for (int k = 0; k < Cc; k++) acc += sm[k] * w[(long)k * (6 * Cc) + j];
    mout[b * 6 * Cc + j] = acc;
}

// ---------------- LN + modulate -> fp16 out ----------------
__global__ void ln_mod_h_kernel(const float* __restrict__ in, __half* __restrict__ out,
                                const float* __restrict__ m, int rowsPerBatch,
                                int shOff, int scOff,
                                long outBatchStride, int outRowOff) {
    int row = blockIdx.x;
    int b = row / rowsPerBatch;
    int r = row - b * rowsPerBatch;
    const float* xi = in + (long)row * Cc;
    float v[4]; float s = 0.f, s2 = 0.f;
#pragma unroll
    for (int i = 0; i < 4; i++) {
        v[i] = xi[threadIdx.x + 256 * i];
        s += v[i]; s2 += v[i] * v[i];
    }
    __shared__ float rs[256], rs2[256];
    rs[threadIdx.x] = s; rs2[threadIdx.x] = s2;
    __syncthreads();
    for (int off = 128; off > 0; off >>= 1) {
        if (threadIdx.x < off) {
            rs[threadIdx.x]  += rs[threadIdx.x + off];
            rs2[threadIdx.x] += rs2[threadIdx.x + off];
        }
        __syncthreads();
    }
    float mu   = rs[0] * (1.f / (float)Cc);
    float var  = rs2[0] * (1.f / (float)Cc) - mu * mu;
    float rstd = rsqrtf(var + 1e-6f);
    const float* mb = m + b * 6 * Cc;
    __half* po = out + (long)b * outBatchStride + (long)(outRowOff + r) * Cc;
#pragma unroll
    for (int i = 0; i < 4; i++) {
        int c = threadIdx.x + 256 * i;
        po[c] = __float2half((v[i] - mu) * rstd * (1.f + mb[scOff + c]) + mb[shOff + c]);
    }
}

// ---------------- FP16 tensor-core GEMM, fused epilogues (validated R13) ----------------
// MODE 1: C[fp16] = acc + bias1                                 (qkv)
// MODE 2: C[fp16] = region1 ? gelu(acc+bias1) : silu(acc+bias2) (s1 | d1 merged)
// MODE 3: fp32 out{x,c} = base{x,c} + (acc+bias1)*g_msa          (proj)
// MODE 4: fp32 out{x,c} = out{x,c} + (acc+bias{1,2})*g_mlp       (s2 | d2 merged)
#define GH_ST 20
#define GH_STG (128 * GH_ST)
#define GEMMH_SMEM (6 * GH_STG * 4)

template<int MODE>
__global__ __launch_bounds__(256, 2)
void gemm_h2(const __half* __restrict__ A,
             const __half* __restrict__ BT1, const __half* __restrict__ BT2,
             const float* __restrict__ bias1, const float* __restrict__ bias2,
             void* __restrict__ out1, void* __restrict__ out2,
             const float* __restrict__ base1, const float* __restrict__ base2,
             const float* __restrict__ gmv, int gOff, int splitBlk,
             int M, int N, int K) {
    extern __shared__ uint32_t smg[];
    uint32_t* As = smg;                 // [3][128][20]
    uint32_t* Bs = smg + 3 * GH_STG;    // [3][128][20]

    int tid  = threadIdx.x;
    int warp = tid >> 5, lane = tid & 31;
    int lg   = lane >> 2, tig = lane & 3;
    int warpM = (warp >> 2) * 64;
    int warpN = (warp & 3) * 32;

    bool reg1 = (int)blockIdx.y < splitBlk;
    const __half* BTsel = reg1 ? BT1 : BT2;
    const float*  bsel  = reg1 ? bias1 : bias2;

    const __half* Ab = A + (long)blockIdx.y * 128 * K;
    const __half* Bb = BTsel + (long)blockIdx.x * 128 * K;

    float acc[4][4][4];
#pragma unroll
    for (int i = 0; i < 4; i++)
#pragma unroll
        for (int j = 0; j < 4; j++)
#pragma unroll
            for (int q = 0; q < 4; q++) acc[i][j][q] = 0.f;

    int nstages = K >> 5;

#define GH_FILL(s) do {                                                        \
        int buf_ = (s) % 3;                                                    \
        int k0_  = (s) << 5;                                                   \
        uint32_t* Ad = As + buf_ * GH_STG;                                     \
        uint32_t* Bd = Bs + buf_ * GH_STG;                                     \
        _Pragma("unroll")                                                      \
        for (int i_ = 0; i_ < 2; i_++) {                                       \
            int c_ = tid + i_ * 256;           /* 0..511 */                    \
            int r_ = c_ >> 2, kc_ = c_ & 3;                                    \
            uint32_t da_ = (uint32_t)__cvta_generic_to_shared(Ad + r_ * GH_ST + kc_ * 4); \
            cp_async16(da_, Ab + (long)r_ * K + k0_ + kc_ * 8);                \
            uint32_t db_ = (uint32_t)__cvta_generic_to_shared(Bd + r_ * GH_ST + kc_ * 4); \
            cp_async16(db_, Bb + (long)r_ * K + k0_ + kc_ * 8);                \
        }                                                                      \
        asm volatile("cp.async.commit_group;\n");                              \
    } while (0)

    GH_FILL(0);
    GH_FILL(1);

    for (int s = 0; s < nstages; s++) {
        if (s + 1 < nstages) asm volatile("cp.async.wait_group 1;\n");
        else                 asm volatile("cp.async.wait_group 0;\n");
        __syncthreads();
        if (s + 2 < nstages) GH_FILL(s + 2);

        uint32_t* Ac = As + (s % 3) * GH_STG;
        uint32_t* Bc = Bs + (s % 3) * GH_STG;
#pragma unroll
        for (int kk = 0; kk < 2; kk++) {
            uint32_t af[4][4], bf[4][2];
#pragma unroll
            for (int mi = 0; mi < 4; mi++) {
                int m = warpM + mi * 16 + lg;
                af[mi][0] = Ac[m * GH_ST + kk * 8 + tig];
                af[mi][1] = Ac[(m + 8) * GH_ST + kk * 8 + tig];
                af[mi][2] = Ac[m * GH_ST + kk * 8 + 4 + tig];
                af[mi][3] = Ac[(m + 8) * GH_ST + kk * 8 + 4 + tig];
            }
#pragma unroll
            for (int ni = 0; ni < 4; ni++) {
                int n = warpN + ni * 8 + lg;
                bf[ni][0] = Bc[n * GH_ST + kk * 8 + tig];
                bf[ni][1] = Bc[n * GH_ST + kk * 8 + 4 + tig];
            }
#pragma unroll
            for (int mi = 0; mi < 4; mi++)
#pragma unroll
                for (int ni = 0; ni < 4; ni++)
                    mma_f16(acc[mi][ni], af[mi], bf[ni]);
        }
    }
#undef GH_FILL

    int gRow0 = blockIdx.y * 128;
    int colBase = blockIdx.x * 128 + warpN;

    float* outp = nullptr;
    const float* basep = nullptr;
    const float* gvp = nullptr;
    if (MODE == 3) {
        int b = gRow0 / Ss;
        int rr0 = gRow0 - b * Ss;
        if (rr0 < Nn) {
            outp  = (float*)out1 + ((long)b * Nn + rr0) * Cc;
            basep = base1 + ((long)b * Nn + rr0) * Cc;
        } else {
            outp  = (float*)out2 + ((long)b * Tt + rr0 - Nn) * Cc;
            basep = base2 + ((long)b * Tt + rr0 - Nn) * Cc;
        }
        gvp = gmv + b * 6 * Cc + gOff;
    }
    if (MODE == 4) {
        if (reg1) {
            int b = gRow0 >> 11;
            outp  = (float*)out1 + (long)gRow0 * Cc;
            basep = base1 + (long)gRow0 * Cc;
            gvp = gmv + b * 6 * Cc + gOff;
        } else {
            int rc0 = gRow0 - Bz * Nn;
            int b = rc0 >> 8;
            outp  = (float*)out2 + (long)rc0 * Cc;
            basep = base2 + (long)rc0 * Cc;
            gvp = gmv + b * 6 * Cc + gOff;
        }
    }

#pragma unroll
    for (int mi = 0; mi < 4; mi++) {
#pragma unroll
        for (int ni = 0; ni < 4; ni++) {
            int rloc = warpM + mi * 16 + lg;
            int c0 = colBase + ni * 8 + tig * 2;
            float b0 = bsel[c0], b1 = bsel[c0 + 1];
            float v00 = acc[mi][ni][0] + b0;
            float v01 = acc[mi][ni][1] + b1;
            float v10 = acc[mi][ni][2] + b0;
            float v11 = acc[mi][ni][3] + b1;
            if (MODE == 1) {
                __half* C = (__half*)out1;
                long r0 = gRow0 + rloc;
                *(__half2*)(C + r0 * N + c0)       = __floats2half2_rn(v00, v01);
                *(__half2*)(C + (r0 + 8) * N + c0) = __floats2half2_rn(v10, v11);
            } else if (MODE == 2) {
                if (reg1) {
                    v00 = act_fn<1>(v00); v01 = act_fn<1>(v01);
                    v10 = act_fn<1>(v10); v11 = act_fn<1>(v11);
                } else {
                    v00 = act_fn<2>(v00); v01 = act_fn<2>(v01);
                    v10 = act_fn<2>(v10); v11 = act_fn<2>(v11);
                }
                __half* C = (__half*)out1;
                long r0 = gRow0 + rloc;
                *(__half2*)(C + r0 * N + c0)       = __floats2half2_rn(v00, v01);
                *(__half2*)(C + (r0 + 8) * N + c0) = __floats2half2_rn(v10, v11);
            } else {
                float g0 = gvp[c0], g1 = gvp[c0 + 1];
                float* p0 = outp + (long)rloc * Cc + c0;
                float* p1 = outp + (long)(rloc + 8) * Cc + c0;
                const float* q0 = basep + (long)rloc * Cc + c0;
                const float* q1 = basep + (long)(rloc + 8) * Cc + c0;
                p0[0] = q0[0] + v00 * g0;
                p0[1] = q0[1] + v01 * g1;
                p1[0] = q1[0] + v10 * g0;
                p1[1] = q1[1] + v11 * g1;
            }
        }
    }
}

// ---------------- FP16 flash attention, BR=128, BC=64, shuffle softmax ----------------
// 8 warps: 4 (M, 32 rows) x 2 (N, 32 cols). No St buffer: row reductions via
// quad-shuffles + 1KB cross-warp exchange; probs packed half2 straight into Ph.
#define FH_ST 36
#define FA_SMEM (int)(((128 + 64 + 128) * FH_ST + 4 * 128 + 2 * 256) * 4)
__global__ __launch_bounds__(256, 2)
void flash_h_kernel(const __half* __restrict__ qkvh, __half* __restrict__ outp) {
    extern __shared__ uint32_t smu[];
    uint32_t* Qs = smu;                          // [128][FH_ST]
    uint32_t* Ks = Qs + 128 * FH_ST;             // [64][FH_ST]  K tile, then V^T tile
    uint32_t* Ph = Ks + 64 * FH_ST;              // [128][FH_ST] probs (packed half2)
    float* mrow  = (float*)(Ph + 128 * FH_ST);   // [128]
    float* lrow  = mrow + 128;
    float* crow  = lrow + 128;
    float* tmrow = crow + 128;
    float* pm    = tmrow + 128;                  // [2][128] partial max
    float* ps    = pm + 256;                     // [2][128] partial sum

    int bh = blockIdx.y;
    int b = bh >> 4, h = bh & 15;
    int q0 = blockIdx.x * 128;
    int tid = threadIdx.x;
    int lane = tid & 31, warp = tid >> 5;
    int g = lane >> 2, tig = lane & 3;
    int warpM = (warp >> 1) * 32;   // 0,32,64,96
    int wn = warp & 1;
    int warpN = wn * 32;            // 0,32

    const __half2 qsc = __float2half2_rn(0.125f);
    for (int idx = tid; idx < 1024; idx += 256) {
        int r = idx & 127, s4 = idx >> 7;   // s4 0..7
        uint4 v = *(const uint4*)(qkvh + (long)(b * Ss + q0 + r) * (3 * Cc) + h * Dd + s4 * 8);
        __half2* hv = (__half2*)&v;
        hv[0] = __hmul2(hv[0], qsc);
        hv[1] = __hmul2(hv[1], qsc);
        hv[2] = __hmul2(hv[2], qsc);
        hv[3] = __hmul2(hv[3], qsc);
        *(uint4*)&Qs[r * FH_ST + s4 * 4] = v;
    }
    if (tid < 128) { mrow[tid] = -1e30f; lrow[tid] = 0.f; }
    __syncthreads();

    float Oc[2][4][4] = {};   // [mi][ni][frag]

    for (int j0 = 0; j0 < Ss; j0 += 64) {
        // ---- K tile [j][d] fp16 ----
        for (int idx = tid; idx < 512; idx += 256) {
            int r = idx & 63, s4 = idx >> 6;   // s4 0..7
            uint4 v = *(const uint4*)(qkvh + (long)(b * Ss + j0 + r) * (3 * Cc) + Cc + h * Dd + s4 * 8);
            *(uint4*)&Ks[r * FH_ST + s4 * 4] = v;
        }
        __syncthreads();                                    // bar A

        // ---- S = Q K^T (fp16 mma) ----
        float Sc[2][4][4];
#pragma unroll
        for (int mi = 0; mi < 2; mi++)
#pragma unroll
            for (int ni = 0; ni < 4; ni++)
#pragma unroll
                for (int q = 0; q < 4; q++) Sc[mi][ni][q] = 0.f;
#pragma unroll
        for (int ks = 0; ks < 4; ks++) {
            uint32_t af[2][4], bf[4][2];
#pragma unroll
            for (int mi = 0; mi < 2; mi++) {
                int m = warpM + mi * 16 + g;
                af[mi][0] = Qs[m * FH_ST + ks * 8 + tig];
                af[mi][1] = Qs[(m + 8) * FH_ST + ks * 8 + tig];
                af[mi][2] = Qs[m * FH_ST + ks * 8 + 4 + tig];
                af[mi][3] = Qs[(m + 8) * FH_ST + ks * 8 + 4 + tig];
            }
#pragma unroll
            for (int ni = 0; ni < 4; ni++) {
                int n = warpN + ni * 8 + g;
                bf[ni][0] = Ks[n * FH_ST + ks * 8 + tig];
                bf[ni][1] = Ks[n * FH_ST + ks * 8 + 4 + tig];
            }
#pragma unroll
            for (int mi = 0; mi < 2; mi++)
#pragma unroll
                for (int ni = 0; ni < 4; ni++)
                    mma_f16(Sc[mi][ni], af[mi], bf[ni]);
        }

        // ---- partial row max via quad shuffles, cross-warp exchange ----
#pragma unroll
        for (int mi = 0; mi < 2; mi++) {
#pragma unroll
            for (int hf = 0; hf < 2; hf++) {
                float v = -1e30f;
#pragma unroll
                for (int ni = 0; ni < 4; ni++)
                    v = fmaxf(v, fmaxf(Sc[mi][ni][hf * 2], Sc[mi][ni][hf * 2 + 1]));
                v = fmaxf(v, __shfl_xor_sync(0xffffffff, v, 1));
                v = fmaxf(v, __shfl_xor_sync(0xffffffff, v, 2));
                if (tig == 0)
                    pm[wn * 128 + warpM + mi * 16 + g + hf * 8] = v;
            }
        }
        __syncthreads();                                    // bar B
        if (wn == 0 && tig == 0) {
#pragma unroll
            for (int mi = 0; mi < 2; mi++)
#pragma unroll
                for (int hf = 0; hf < 2; hf++) {
                    int r = warpM + mi * 16 + g + hf * 8;
                    float tm = fmaxf(fmaxf(pm[r], pm[128 + r]), mrow[r]);
                    tmrow[r] = tm;
                    crow[r] = __expf(mrow[r] - tm);
                    mrow[r] = tm;
                }
        }
        __syncthreads();                                    // bar C

        // ---- exp + pack probs into Ph + partial sums ----
#pragma unroll
        for (int mi = 0; mi < 2; mi++) {
#pragma unroll
            for (int hf = 0; hf < 2; hf++) {
                int r = warpM + mi * 16 + g + hf * 8;
                float tm = tmrow[r];
                float s = 0.f;
#pragma unroll
                for (int ni = 0; ni < 4; ni++) {
                    float p0 = __expf(Sc[mi][ni][hf * 2] - tm);
                    float p1 = __expf(Sc[mi][ni][hf * 2 + 1] - tm);
                    s += p0 + p1;
                    __half2 hp = __floats2half2_rn(p0, p1);
                    Ph[r * FH_ST + wn * 16 + ni * 4 + tig] = *(uint32_t*)&hp;
                }
                s += __shfl_xor_sync(0xffffffff, s, 1);
                s += __shfl_xor_sync(0xffffffff, s, 2);
                if (tig == 0)
                    ps[wn * 128 + r] = s;
            }
        }

        // ---- V tile transposed to Vs[d][c] (aliases Ks; QK reads done pre-bar B) ----
        {
            int c2 = tid & 31, i = tid >> 5;
            const __half* vb = qkvh + 2 * Cc + h * Dd + i * 8;
            uint4 lo = *(const uint4*)(vb + (long)(b * Ss + j0 + 2 * c2) * (3 * Cc));
            uint4 hi = *(const uint4*)(vb + (long)(b * Ss + j0 + 2 * c2 + 1) * (3 * Cc));
            const uint32_t* lw = (const uint32_t*)&lo;
            const uint32_t* hw = (const uint32_t*)&hi;
#pragma unroll
            for (int j = 0; j < 8; j++) {
                uint32_t w = __byte_perm(lw[j >> 1], hw[j >> 1], (j & 1) ? 0x7632 : 0x5410);
                Ks[(i * 8 + j) * FH_ST + c2] = w;
            }
        }
        __syncthreads();                                    // bar D

        if (wn == 0 && tig == 0) {
#pragma unroll
            for (int mi = 0; mi < 2; mi++)
#pragma unroll
                for (int hf = 0; hf < 2; hf++) {
                    int r = warpM + mi * 16 + g + hf * 8;
                    lrow[r] = lrow[r] * crow[r] + ps[r] + ps[128 + r];
                }
        }

        // ---- rescale O ----
#pragma unroll
        for (int mi = 0; mi < 2; mi++) {
            int m0 = warpM + mi * 16 + g;
            float cl = crow[m0], ch = crow[m0 + 8];
#pragma unroll
            for (int ni = 0; ni < 4; ni++) {
                Oc[mi][ni][0] *= cl; Oc[mi][ni][1] *= cl;
                Oc[mi][ni][2] *= ch; Oc[mi][ni][3] *= ch;
            }
        }

        // ---- O += P @ V (fp16 mma) ----
#pragma unroll
        for (int ks = 0; ks < 4; ks++) {
            uint32_t af[2][4], bf[4][2];
#pragma unroll
            for (int mi = 0; mi < 2; mi++) {
                int m = warpM + mi * 16 + g;
                af[mi][0] = Ph[m * FH_ST + ks * 8 + tig];
                af[mi][1] = Ph[(m + 8) * FH_ST + ks * 8 + tig];
                af[mi][2] = Ph[m * FH_ST + ks * 8 + 4 + tig];
                af[mi][3] = Ph[(m + 8) * FH_ST + ks * 8 + 4 + tig];
            }
#pragma unroll
            for (int ni = 0; ni < 4; ni++) {
                int n = warpN + ni * 8 + g;
                bf[ni][0] = Ks[n * FH_ST + ks * 8 + tig];
                bf[ni][1] = Ks[n * FH_ST + ks * 8 + 4 + tig];
            }
#pragma unroll
            for (int mi = 0; mi < 2; mi++)
#pragma unroll
                for (int ni = 0; ni < 4; ni++)
                    mma_f16(Oc[mi][ni], af[mi], bf[ni]);
        }
        __syncthreads();                                    // bar E
    }

    // ---- epilogue: normalize, write fp16 ----
#pragma unroll
    for (int mi = 0; mi < 2; mi++) {
        int m0 = warpM + mi * 16 + g;
        float inv0 = 1.f / lrow[m0];
        float inv1 = 1.f / lrow[m0 + 8];
#pragma unroll
        for (int ni = 0; ni < 4; ni++) {
            int n0 = warpN + ni * 8 + tig * 2;
            *(__half2*)(outp + (long)(b * Ss + q0 + m0) * Cc + h * Dd + n0) =
                __floats2half2_rn(Oc[mi][ni][0] * inv0, Oc[mi][ni][1] * inv0);
            *(__half2*)(outp + (long)(b * Ss + q0 + m0 + 8) * Cc + h * Dd + n0) =
                __floats2half2_rn(Oc[mi][ni][2] * inv1, Oc[mi][ni][3] * inv1);
        }
    }
}

// ---------------- launch ----------------
extern "C" void kernel_launch(void* const* d_in, const int* in_sizes, int n_in,
                              void* d_out, int out_size) {
    const float* x       = (const float*)d_in[0];
    const float* mod     = (const float*)d_in[1];
    const float* cond    = (const float*)d_in[2];
    const float* w_adaln = (const float*)d_in[3];
    const float* b_adaln = (const float*)d_in[4];
    const float* w_qkv   = (const float*)d_in[5];
    const float* b_qkv   = (const float*)d_in[6];
    const float* w_proj  = (const float*)d_in[7];
    const float* b_proj  = (const float*)d_in[8];
    const float* w_s1    = (const float*)d_in[9];
    const float* b_s1    = (const float*)d_in[10];
    const float* w_s2    = (const float*)d_in[11];
    const float* b_s2    = (const float*)d_in[12];
    const float* w_d1    = (const float*)d_in[13];
    const float* b_d1    = (const float*)d_in[14];
    const float* w_d2    = (const float*)d_in[15];
    const float* b_d2    = (const float*)d_in[16];

    float* outx = (float*)d_out;                         // [2,2048,1024]
    float* outc = outx + (long)Bz * Nn * Cc;             // [2,256,1024]

    float *gm;
    __half *gqkvh, *gwth, *gjh, *gah, *ghid;
    cudaGetSymbolAddress((void**)&gm,    g_m);
    cudaGetSymbolAddress((void**)&gqkvh, g_qkvh);
    cudaGetSymbolAddress((void**)&gwth,  g_wTh);
    cudaGetSymbolAddress((void**)&gjh,   g_jh);
    cudaGetSymbolAddress((void**)&gah,   g_ah);
    cudaGetSymbolAddress((void**)&ghid,  g_hid16);

    cudaFuncSetAttribute(flash_h_kernel, cudaFuncAttributeMaxDynamicSharedMemorySize, FA_SMEM);
    cudaFuncSetAttribute(gemm_h2<1>, cudaFuncAttributeMaxDynamicSharedMemorySize, GEMMH_SMEM);
    cudaFuncSetAttribute(gemm_h2<2>, cudaFuncAttributeMaxDynamicSharedMemorySize, GEMMH_SMEM);
    cudaFuncSetAttribute(gemm_h2<3>, cudaFuncAttributeMaxDynamicSharedMemorySize, GEMMH_SMEM);
    cudaFuncSetAttribute(gemm_h2<4>, cudaFuncAttributeMaxDynamicSharedMemorySize, GEMMH_SMEM);

    const long SC = (long)Ss * Cc;
    const long NC = (long)Nn * Cc;
    const long TC = (long)Tt * Cc;

    // 0. weight transposes + fp16 cvt (64x64 coalesced tiles)
    transpose_cvt_kernel<<<dim3(3 * Cc / 64, Cc / 64), 256>>>(w_qkv,  gwth + WT_QKV,  Cc, 3 * Cc);
    transpose_cvt_kernel<<<dim3(Cc / 64, Cc / 64),     256>>>(w_proj, gwth + WT_PROJ, Cc, Cc);
    transpose_cvt_kernel<<<dim3(Hh / 64, Cc / 64),     256>>>(w_s1,   gwth + WT_S1,   Cc, Hh);
    transpose_cvt_kernel<<<dim3(Cc / 64, Hh / 64),     256>>>(w_s2,   gwth + WT_S2,   Hh, Cc);
    transpose_cvt_kernel<<<dim3(Hh / 64, Cc / 64),     256>>>(w_d1,   gwth + WT_D1,   Cc, Hh);
    transpose_cvt_kernel<<<dim3(Cc / 64, Hh / 64),     256>>>(w_d2,   gwth + WT_D2,   Hh, Cc);

    // 1. modulation vectors
    adaln_kernel<<<dim3(24, Bz), 256>>>(mod, w_adaln, b_adaln, gm);

    // 2. LN + msa modulate -> joint fp16 [B,S,C]
    ln_mod_h_kernel<<<Bz * Nn, 256>>>(x,    gjh, gm, Nn, 0, Cc, SC, 0);
    ln_mod_h_kernel<<<Bz * Tt, 256>>>(cond, gjh, gm, Tt, 0, Cc, SC, Nn);

    // 3. qkv (fp16 out)
    gemm_h2<1><<<dim3(24, 36), 256, GEMMH_SMEM>>>(
        gjh, gwth + WT_QKV, gwth + WT_QKV, b_qkv, b_qkv,
        gqkvh, nullptr, nullptr, nullptr, nullptr, 0, 36,
        Bz * Ss, 3 * Cc, Cc);

    // 4. attention
    flash_h_kernel<<<dim3(Ss / 128, Bz * HEADS), 256, FA_SMEM>>>(gqkvh, gah);

    // 5. proj + fused attn-residual
    gemm_h2<3><<<dim3(8, 36), 256, GEMMH_SMEM>>>(
        gah, gwth + WT_PROJ, gwth + WT_PROJ, b_proj, b_proj,
        outx, outc, x, cond, gm, 2 * Cc, 36,
        Bz * Ss, Cc, Cc);

    // 6. LN + mlp modulate -> fp16 x2/c2 (contiguous in gjh)
    __half* gx2 = gjh;
    __half* gc2 = gjh + (long)Bz * Nn * Cc;
    ln_mod_h_kernel<<<Bz * Nn, 256>>>(outx, gx2, gm, Nn, 3 * Cc, 4 * Cc, NC, 0);
    ln_mod_h_kernel<<<Bz * Tt, 256>>>(outc, gc2, gm, Tt, 3 * Cc, 4 * Cc, TC, 0);

    // 7. merged s1|d1 -> ghid fp16
    gemm_h2<2><<<dim3(32, 36), 256, GEMMH_SMEM>>>(
        gjh, gwth + WT_S1, gwth + WT_D1, b_s1, b_d1,
        ghid, nullptr, nullptr, nullptr, nullptr, 0, 32,
        Bz * Ss, Hh, Cc);

    // 8. merged s2|d2 + fused mlp-residual -> outx/outc
    gemm_h2<4><<<dim3(8, 36), 256, GEMMH_SMEM>>>(
        ghid, gwth + WT_S2, gwth + WT_D2, b_s2, b_d2,
        outx, outc, outx, outc, gm, 5 * Cc, 32,
        Bz * Ss, Cc, Hh);
}